// round 10
// baseline (speedup 1.0000x reference)
#include <cuda_runtime.h>
#include <cuda_bf16.h>
#include <cstdint>
#include <cstddef>

#define N_USER 200000
#define N_NEWS 100000
#define N_SOURCE 5000
#define N_FOLLOWER 200000
#define HDIM 128
#define E_POSTS 500000
#define E_PUB 100000
#define E_FOL 1000000

#define TOT_NODES (N_USER + N_NEWS + N_SOURCE + N_FOLLOWER)

#define OFF_U ((size_t)0)
#define OFF_N ((size_t)N_USER * HDIM)
#define OFF_S ((size_t)(N_USER + N_NEWS) * HDIM)
#define OFF_F ((size_t)(N_USER + N_NEWS + N_SOURCE) * HDIM)

#define DS_POSTS_U 0
#define DS_POSTS_N 200000
#define DS_PUB_S   300000
#define DS_PUB_N   305000
#define DS_FOL_F   405000
#define DS_FOL_U   605000
#define DEG_TOTAL  805000

#define RP0 0
#define RP1 100001
#define RP2 300002
#define RP3 400003
#define RP4 405004
#define RP5 605005
#define RP_TOTAL 805006

#define EL0 0
#define EL1 500000
#define EL2 1000000
#define EL3 1100000
#define EL4 1200000
#define EL5 2200000
#define EL_TOTAL 3200000

__device__ float g_bufA[(size_t)TOT_NODES * HDIM];
__device__ float g_bufB[(size_t)TOT_NODES * HDIM];
__device__ float g_agg[(size_t)N_USER * 256];
__device__ float g_deg[DEG_TOTAL];
__device__ int   g_cnt[DEG_TOTAL];
__device__ int   g_cur[DEG_TOTAL];
__device__ int   g_rp[RP_TOTAL];
__device__ int   g_el[EL_TOTAL];

// ---------------------------------------------------------------------------
__global__ void zero4_kernel(float4* __restrict__ p, size_t n4) {
    size_t i = (size_t)blockIdx.x * blockDim.x + threadIdx.x;
    size_t stride = (size_t)gridDim.x * blockDim.x;
    float4 z = make_float4(0.f, 0.f, 0.f, 0.f);
    for (; i < n4; i += stride) p[i] = z;
}

__global__ void counti_kernel(const int* __restrict__ idx, int n, int* __restrict__ cnt) {
    int i = blockIdx.x * blockDim.x + threadIdx.x;
    int stride = gridDim.x * blockDim.x;
    for (; i < n; i += stride) atomicAdd(&cnt[idx[i]], 1);
}

__global__ void rsqrt_cnt_kernel(const int* __restrict__ cnt, float* __restrict__ deg, int n) {
    int i = blockIdx.x * blockDim.x + threadIdx.x;
    int stride = gridDim.x * blockDim.x;
    for (; i < n; i += stride) {
        int c = cnt[i];
        deg[i] = rsqrtf((float)(c < 1 ? 1 : c));
    }
}

__global__ __launch_bounds__(1024) void scan6_kernel(const int* __restrict__ cnt,
                                                     int* __restrict__ rp) {
    const int segs[6] = {DS_POSTS_N, DS_POSTS_U, DS_PUB_N, DS_PUB_S, DS_FOL_U, DS_FOL_F};
    const int ns[6]   = {N_NEWS, N_USER, N_NEWS, N_SOURCE, N_USER, N_FOLLOWER};
    const int rpo[6]  = {RP0, RP1, RP2, RP3, RP4, RP5};
    int r = blockIdx.x;
    const int* c = cnt + segs[r];
    int* out = rp + rpo[r];
    int n = ns[r];
    int tid = threadIdx.x;
    int lane = tid & 31;
    int wid = tid >> 5;
    __shared__ int wsum[32];
    __shared__ int carry;
    if (tid == 0) { carry = 0; out[0] = 0; }
    __syncthreads();
    for (int base = 0; base < n; base += 1024) {
        int v = (base + tid < n) ? c[base + tid] : 0;
        int x = v;
#pragma unroll
        for (int o = 1; o < 32; o <<= 1) {
            int y = __shfl_up_sync(0xffffffffu, x, o);
            if (lane >= o) x += y;
        }
        if (lane == 31) wsum[wid] = x;
        __syncthreads();
        if (wid == 0) {
            int s = wsum[lane];
#pragma unroll
            for (int o = 1; o < 32; o <<= 1) {
                int y = __shfl_up_sync(0xffffffffu, s, o);
                if (lane >= o) s += y;
            }
            wsum[lane] = s;
        }
        __syncthreads();
        int pre = (wid > 0) ? wsum[wid - 1] : 0;
        int incl = carry + pre + x;
        if (base + tid < n) out[base + tid + 1] = incl;
        __syncthreads();
        if (tid == 1023) carry = incl;
        __syncthreads();
    }
}

__global__ void fill_kernel(const int* __restrict__ src, const int* __restrict__ dst, int E,
                            const int* __restrict__ rp, int* __restrict__ cur,
                            int* __restrict__ el) {
    int i = blockIdx.x * blockDim.x + threadIdx.x;
    int stride = gridDim.x * blockDim.x;
    for (; i < E; i += stride) {
        int d = dst[i];
        int p = atomicAdd(&cur[d], 1);
        el[rp[d] + p] = src[i];
    }
}

__global__ void gather_kernel(const float* __restrict__ h, const int* __restrict__ rp,
                              const int* __restrict__ el, const float* __restrict__ rs_src,
                              const float* __restrict__ rs_dst, float* __restrict__ agg,
                              int colofs, int n_dst) {
    int warp = (blockIdx.x * blockDim.x + threadIdx.x) >> 5;
    int lane = threadIdx.x & 31;
    int nwarps = (gridDim.x * blockDim.x) >> 5;
    for (int row = warp; row < n_dst; row += nwarps) {
        int beg = rp[row], end = rp[row + 1];
        float4 acc = make_float4(0.f, 0.f, 0.f, 0.f);
        for (int e = beg; e < end; e++) {
            int s = el[e];
            float sc = rs_src[s];
            float4 v = *reinterpret_cast<const float4*>(h + (size_t)s * HDIM + lane * 4);
            acc.x += sc * v.x; acc.y += sc * v.y; acc.z += sc * v.z; acc.w += sc * v.w;
        }
        float ri = rs_dst[row];
        acc.x *= ri; acc.y *= ri; acc.z *= ri; acc.w *= ri;
        *reinterpret_cast<float4*>(agg + (size_t)row * 256 + colofs + lane * 4) = acc;
    }
}

// ---------------------------------------------------------------------------
// bf16x3 HMMA GEMM, K-chunk 64, ~70KB smem -> 3 CTAs/SM.
// C[M,128] = epi( A[M,K](lda) @ [W0;W1][K,128] + b0 + b1 )
// ---------------------------------------------------------------------------
#define ASTR 72    // bf16 row stride for A smem (64 data + 8 pad -> 144B)
#define BSTR 136   // bf16 row stride for B smem (128 data + 8 pad -> 272B)
#define SM_BYTES (2 * 128 * ASTR * 2 + 2 * 64 * BSTR * 2)  // 36864+34816 = 71680 B

__device__ __forceinline__ void mma16816(float* c, const uint32_t* a, const uint32_t* b) {
    asm volatile(
        "mma.sync.aligned.m16n8k16.row.col.f32.bf16.bf16.f32 "
        "{%0,%1,%2,%3}, {%4,%5,%6,%7}, {%8,%9}, {%0,%1,%2,%3};\n"
        : "+f"(c[0]), "+f"(c[1]), "+f"(c[2]), "+f"(c[3])
        : "r"(a[0]), "r"(a[1]), "r"(a[2]), "r"(a[3]), "r"(b[0]), "r"(b[1]));
}
__device__ __forceinline__ void ldsm_x4(uint32_t* r, const void* p) {
    uint32_t addr = (uint32_t)__cvta_generic_to_shared(p);
    asm volatile("ldmatrix.sync.aligned.m8n8.x4.shared.b16 {%0,%1,%2,%3}, [%4];"
                 : "=r"(r[0]), "=r"(r[1]), "=r"(r[2]), "=r"(r[3]) : "r"(addr));
}
__device__ __forceinline__ void ldsm_x4_t(uint32_t* r, const void* p) {
    uint32_t addr = (uint32_t)__cvta_generic_to_shared(p);
    asm volatile("ldmatrix.sync.aligned.m8n8.x4.trans.shared.b16 {%0,%1,%2,%3}, [%4];"
                 : "=r"(r[0]), "=r"(r[1]), "=r"(r[2]), "=r"(r[3]) : "r"(addr));
}
__device__ __forceinline__ uint32_t pack_hi2(float a, float b, uint32_t* lo) {
    __nv_bfloat16 h0 = __float2bfloat16_rn(a);
    __nv_bfloat16 h1 = __float2bfloat16_rn(b);
    __nv_bfloat16 l0 = __float2bfloat16_rn(a - __bfloat162float(h0));
    __nv_bfloat16 l1 = __float2bfloat16_rn(b - __bfloat162float(h1));
    *lo = (uint32_t)__bfloat16_as_ushort(l0) | ((uint32_t)__bfloat16_as_ushort(l1) << 16);
    return (uint32_t)__bfloat16_as_ushort(h0) | ((uint32_t)__bfloat16_as_ushort(h1) << 16);
}

__global__ __launch_bounds__(256) void tgemm_kernel(
    const float* __restrict__ A, int lda,
    const float* __restrict__ W0, const float* __restrict__ W1, int K0, int K,
    const float* __restrict__ b0, const float* __restrict__ b1,
    float* __restrict__ C, int M, float scale, int do_act) {
    extern __shared__ __align__(16) char smraw[];
    __nv_bfloat16* AH = reinterpret_cast<__nv_bfloat16*>(smraw);
    __nv_bfloat16* AL = AH + 128 * ASTR;
    __nv_bfloat16* BH = AL + 128 * ASTR;
    __nv_bfloat16* BL = BH + 64 * BSTR;

    int tid = threadIdx.x;
    int lane = tid & 31;
    int warp = tid >> 5;
    int wm = warp & 1;
    int wn = warp >> 1;
    int block_row = blockIdx.x * 128;

    float c[4][4][4];
#pragma unroll
    for (int mt = 0; mt < 4; mt++)
#pragma unroll
        for (int nt = 0; nt < 4; nt++)
#pragma unroll
            for (int j = 0; j < 4; j++) c[mt][nt][j] = 0.f;

    for (int kbase = 0; kbase < K; kbase += 64) {
        int kcount = K - kbase; if (kcount > 64) kcount = 64;
        // ---- stage A chunk: 128 rows x 64 k ----
        for (int idx = tid; idx < 128 * 8; idx += 256) {
            int row = idx >> 3;
            int kl = (idx & 7) * 8;
            float v[8];
#pragma unroll
            for (int j = 0; j < 8; j++) v[j] = 0.f;
            int grow = block_row + row;
            int gk = kbase + kl;
            if (grow < M && gk < K) {
                const float* ap = A + (size_t)grow * lda + gk;
                if (gk + 7 < K) {
                    float4 v0 = *reinterpret_cast<const float4*>(ap);
                    float4 v1 = *reinterpret_cast<const float4*>(ap + 4);
                    v[0] = v0.x; v[1] = v0.y; v[2] = v0.z; v[3] = v0.w;
                    v[4] = v1.x; v[5] = v1.y; v[6] = v1.z; v[7] = v1.w;
                } else {
#pragma unroll
                    for (int j = 0; j < 8; j++)
                        if (gk + j < K) v[j] = ap[j];
                }
            }
            uint32_t hp[4], lp[4];
#pragma unroll
            for (int j = 0; j < 4; j++) hp[j] = pack_hi2(v[2 * j], v[2 * j + 1], &lp[j]);
            uint32_t off = (uint32_t)(row * ASTR + kl);
            *reinterpret_cast<uint4*>(&AH[off]) = make_uint4(hp[0], hp[1], hp[2], hp[3]);
            *reinterpret_cast<uint4*>(&AL[off]) = make_uint4(lp[0], lp[1], lp[2], lp[3]);
        }
        // ---- stage W chunk: 64 k-rows x 128 n ----
        for (int idx = tid; idx < 64 * 16; idx += 256) {
            int kr = idx >> 4;
            int nl = (idx & 15) * 8;
            float v[8];
#pragma unroll
            for (int j = 0; j < 8; j++) v[j] = 0.f;
            int gk = kbase + kr;
            if (gk < K) {
                const float* wp = (gk < K0) ? W0 + (size_t)gk * HDIM + nl
                                            : W1 + (size_t)(gk - K0) * HDIM + nl;
                float4 v0 = *reinterpret_cast<const float4*>(wp);
                float4 v1 = *reinterpret_cast<const float4*>(wp + 4);
                v[0] = v0.x; v[1] = v0.y; v[2] = v0.z; v[3] = v0.w;
                v[4] = v1.x; v[5] = v1.y; v[6] = v1.z; v[7] = v1.w;
            }
            uint32_t hp[4], lp[4];
#pragma unroll
            for (int j = 0; j < 4; j++) hp[j] = pack_hi2(v[2 * j], v[2 * j + 1], &lp[j]);
            uint32_t off = (uint32_t)(kr * BSTR + nl);
            *reinterpret_cast<uint4*>(&BH[off]) = make_uint4(hp[0], hp[1], hp[2], hp[3]);
            *reinterpret_cast<uint4*>(&BL[off]) = make_uint4(lp[0], lp[1], lp[2], lp[3]);
        }
        __syncthreads();

        int nsteps = (kcount + 15) / 16;
        for (int s = 0; s < nsteps; s++) {
            uint32_t bh[4][2], bl[4][2];
#pragma unroll
            for (int half = 0; half < 2; half++) {
                uint32_t off = (uint32_t)((s * 16 + (lane & 15)) * BSTR + wn * 32 +
                                          half * 16 + (lane >> 4) * 8);
                uint32_t r[4];
                ldsm_x4_t(r, &BH[off]);
                bh[half * 2][0] = r[0]; bh[half * 2][1] = r[1];
                bh[half * 2 + 1][0] = r[2]; bh[half * 2 + 1][1] = r[3];
                ldsm_x4_t(r, &BL[off]);
                bl[half * 2][0] = r[0]; bl[half * 2][1] = r[1];
                bl[half * 2 + 1][0] = r[2]; bl[half * 2 + 1][1] = r[3];
            }
#pragma unroll
            for (int mt = 0; mt < 4; mt++) {
                uint32_t off = (uint32_t)((wm * 64 + mt * 16 + (lane & 15)) * ASTR +
                                          s * 16 + (lane >> 4) * 8);
                uint32_t ah[4], al[4];
                ldsm_x4(ah, &AH[off]);
                ldsm_x4(al, &AL[off]);
#pragma unroll
                for (int nt = 0; nt < 4; nt++) {
                    mma16816(c[mt][nt], ah, bh[nt]);
                    mma16816(c[mt][nt], ah, bl[nt]);
                    mma16816(c[mt][nt], al, bh[nt]);
                }
            }
        }
        __syncthreads();
    }

    // ---- epilogue ----
#pragma unroll
    for (int mt = 0; mt < 4; mt++) {
#pragma unroll
        for (int nt = 0; nt < 4; nt++) {
            int col = wn * 32 + nt * 8 + (lane & 3) * 2;
            float bb0 = (b0 ? b0[col] : 0.f) + (b1 ? b1[col] : 0.f);
            float bb1 = (b0 ? b0[col + 1] : 0.f) + (b1 ? b1[col + 1] : 0.f);
#pragma unroll
            for (int h = 0; h < 2; h++) {
                int row = block_row + wm * 64 + mt * 16 + (lane >> 2) + h * 8;
                if (row >= M) continue;
                float r0 = (c[mt][nt][2 * h] + bb0) * scale;
                float r1 = (c[mt][nt][2 * h + 1] + bb1) * scale;
                if (do_act) {
                    r0 = r0 > 0.f ? r0 : 0.01f * r0;
                    r1 = r1 > 0.f ? r1 : 0.01f * r1;
                }
                *reinterpret_cast<float2*>(C + (size_t)row * HDIM + col) = make_float2(r0, r1);
            }
        }
    }
}

// final head: out[r,0:2] = h1[r,:] @ Wl[128,2] + bl
__global__ void head_kernel(const float* __restrict__ h1, const float* __restrict__ Wl,
                            const float* __restrict__ bl, float* __restrict__ out, int Nrows) {
    int warp = (blockIdx.x * blockDim.x + threadIdx.x) >> 5;
    int lane = threadIdx.x & 31;
    int nwarps = (gridDim.x * blockDim.x) >> 5;
    int k = lane * 4;
    float w00 = Wl[(k + 0) * 2], w01 = Wl[(k + 0) * 2 + 1];
    float w10 = Wl[(k + 1) * 2], w11 = Wl[(k + 1) * 2 + 1];
    float w20 = Wl[(k + 2) * 2], w21 = Wl[(k + 2) * 2 + 1];
    float w30 = Wl[(k + 3) * 2], w31 = Wl[(k + 3) * 2 + 1];
    for (int r = warp; r < Nrows; r += nwarps) {
        float4 v = *reinterpret_cast<const float4*>(h1 + (size_t)r * HDIM + k);
        float p0 = v.x * w00 + v.y * w10 + v.z * w20 + v.w * w30;
        float p1 = v.x * w01 + v.y * w11 + v.z * w21 + v.w * w31;
#pragma unroll
        for (int off = 16; off; off >>= 1) {
            p0 += __shfl_xor_sync(0xffffffffu, p0, off);
            p1 += __shfl_xor_sync(0xffffffffu, p1, off);
        }
        if (lane == 0) {
            out[(size_t)r * 2 + 0] = p0 + bl[0];
            out[(size_t)r * 2 + 1] = p1 + bl[1];
        }
    }
}

// ---------------------------------------------------------------------------
extern "C" void kernel_launch(void* const* d_in, const int* in_sizes, int n_in,
                              void* d_out, int out_size) {
    const float* x_user = (const float*)d_in[0];
    const float* x_news = (const float*)d_in[1];
    const float* x_source = (const float*)d_in[2];
    const float* x_follower = (const float*)d_in[3];
    const float* Wi1_user = (const float*)d_in[4];
    const float* bi1_user = (const float*)d_in[5];
    const float* Wi1_news = (const float*)d_in[6];
    const float* bi1_news = (const float*)d_in[7];
    const float* Wi1_source = (const float*)d_in[8];
    const float* bi1_source = (const float*)d_in[9];
    const float* Wi1_follower = (const float*)d_in[10];
    const float* bi1_follower = (const float*)d_in[11];
    const float* Wi2 = (const float*)d_in[12];
    const float* bi2 = (const float*)d_in[13];
    const float* conv1_W = (const float*)d_in[14];
    const float* conv1_b = (const float*)d_in[15];
    const float* conv2_W = (const float*)d_in[16];
    const float* conv2_b = (const float*)d_in[17];
    const float* Wl_user = (const float*)d_in[18];
    const float* bl_user = (const float*)d_in[19];
    const float* Wl_news = (const float*)d_in[20];
    const float* bl_news = (const float*)d_in[21];
    const float* Wl_source = (const float*)d_in[22];
    const float* bl_source = (const float*)d_in[23];
    const float* Wl_follower = (const float*)d_in[24];
    const float* bl_follower = (const float*)d_in[25];
    const int* posts_u = (const int*)d_in[26];
    const int* posts_n = (const int*)d_in[27];
    const int* pub_s = (const int*)d_in[28];
    const int* pub_n = (const int*)d_in[29];
    const int* fol_f = (const int*)d_in[30];
    const int* fol_u = (const int*)d_in[31];
    float* out = (float*)d_out;

    float *bufA, *bufB, *agg, *deg;
    int *cnt, *cur, *rp, *el;
    cudaGetSymbolAddress((void**)&bufA, g_bufA);
    cudaGetSymbolAddress((void**)&bufB, g_bufB);
    cudaGetSymbolAddress((void**)&agg, g_agg);
    cudaGetSymbolAddress((void**)&deg, g_deg);
    cudaGetSymbolAddress((void**)&cnt, g_cnt);
    cudaGetSymbolAddress((void**)&cur, g_cur);
    cudaGetSymbolAddress((void**)&rp, g_rp);
    cudaGetSymbolAddress((void**)&el, g_el);

    cudaFuncSetAttribute(tgemm_kernel, cudaFuncAttributeMaxDynamicSharedMemorySize, SM_BYTES);

    auto gemm1 = [](const float* A, int lda, const float* W, int K, const float* b,
                    float* C, int M, float scale, int act) {
        tgemm_kernel<<<(M + 127) / 128, 256, SM_BYTES>>>(A, lda, W, nullptr, K, K, b, nullptr,
                                                         C, M, scale, act);
    };
    auto gemm2 = [](const float* A, const float* Wa, const float* Wb, const float* ba,
                    const float* bb, float* C, int M, float scale) {
        tgemm_kernel<<<(M + 127) / 128, 256, SM_BYTES>>>(A, 256, Wa, Wb, 128, 256, ba, bb,
                                                         C, M, scale, 1);
    };

    const size_t HH = (size_t)HDIM * HDIM;

    // ---- dense layer 1 (launch idx 0-3): x -> bufA ----
    gemm1(x_user, 128, Wi1_user, 128, bi1_user, bufA + OFF_U, N_USER, 1.f, 1);
    gemm1(x_source, 128, Wi1_source, 128, bi1_source, bufA + OFF_S, N_SOURCE, 1.f, 1);
    gemm1(x_follower, 128, Wi1_follower, 128, bi1_follower, bufA + OFF_F, N_FOLLOWER, 1.f, 1);
    gemm1(x_news, 300, Wi1_news, 300, bi1_news, bufA + OFF_N, N_NEWS, 1.f, 1);

    // ---- dense layer 2 (idx 4-7; idx 5 = follower M=200k for ncu capture) ----
    gemm1(bufA + OFF_U, 128, Wi2 + 0 * HH, 128, bi2 + 0 * HDIM, bufB + OFF_U, N_USER, 1.f, 1);
    gemm1(bufA + OFF_F, 128, Wi2 + 3 * HH, 128, bi2 + 3 * HDIM, bufB + OFF_F, N_FOLLOWER, 1.f, 1);
    gemm1(bufA + OFF_N, 128, Wi2 + 1 * HH, 128, bi2 + 1 * HDIM, bufB + OFF_N, N_NEWS, 1.f, 1);
    gemm1(bufA + OFF_S, 128, Wi2 + 2 * HH, 128, bi2 + 2 * HDIM, bufB + OFF_S, N_SOURCE, 1.f, 1);

    // ---- CSR build ----
    zero4_kernel<<<2048, 256>>>((float4*)cnt, DEG_TOTAL / 4);
    zero4_kernel<<<2048, 256>>>((float4*)cur, DEG_TOTAL / 4);
    counti_kernel<<<2048, 256>>>(posts_u, E_POSTS, cnt + DS_POSTS_U);
    counti_kernel<<<2048, 256>>>(posts_n, E_POSTS, cnt + DS_POSTS_N);
    counti_kernel<<<512, 256>>>(pub_s, E_PUB, cnt + DS_PUB_S);
    counti_kernel<<<512, 256>>>(pub_n, E_PUB, cnt + DS_PUB_N);
    counti_kernel<<<4096, 256>>>(fol_f, E_FOL, cnt + DS_FOL_F);
    counti_kernel<<<4096, 256>>>(fol_u, E_FOL, cnt + DS_FOL_U);
    rsqrt_cnt_kernel<<<2048, 256>>>(cnt, deg, DEG_TOTAL);
    scan6_kernel<<<6, 1024>>>(cnt, rp);
    fill_kernel<<<2048, 256>>>(posts_u, posts_n, E_POSTS, rp + RP0, cur + DS_POSTS_N, el + EL0);
    fill_kernel<<<2048, 256>>>(posts_n, posts_u, E_POSTS, rp + RP1, cur + DS_POSTS_U, el + EL1);
    fill_kernel<<<512, 256>>>(pub_s, pub_n, E_PUB, rp + RP2, cur + DS_PUB_N, el + EL2);
    fill_kernel<<<512, 256>>>(pub_n, pub_s, E_PUB, rp + RP3, cur + DS_PUB_S, el + EL3);
    fill_kernel<<<4096, 256>>>(fol_f, fol_u, E_FOL, rp + RP4, cur + DS_FOL_U, el + EL4);
    fill_kernel<<<4096, 256>>>(fol_u, fol_f, E_FOL, rp + RP5, cur + DS_FOL_F, el + EL5);

    auto gath = [&](const float* hbase, size_t hoff, int rpo, int elo, int rs_src, int rs_dst,
                    int colofs, int n_dst) {
        gather_kernel<<<(n_dst + 7) / 8, 256>>>(hbase + hoff, rp + rpo, el + elo,
                                                deg + rs_src, deg + rs_dst, agg, colofs, n_dst);
    };

    // ---- conv layers ----
    const size_t H1_BASE = (size_t)TOT_NODES * 2;
    float* h1_u = out + H1_BASE + OFF_U;
    float* h1_n = out + H1_BASE + OFF_N;
    float* h1_s = out + H1_BASE + OFF_S;
    float* h1_f = out + H1_BASE + OFF_F;

    for (int layer = 0; layer < 2; layer++) {
        const float* hsrc = (layer == 0) ? bufB : bufA;
        const float* Wc = (layer == 0) ? conv1_W : conv2_W;
        const float* bc = (layer == 0) ? conv1_b : conv2_b;
        float* o_u = (layer == 0) ? bufA + OFF_U : h1_u;
        float* o_n = (layer == 0) ? bufA + OFF_N : h1_n;
        float* o_s = (layer == 0) ? bufA + OFF_S : h1_s;
        float* o_f = (layer == 0) ? bufA + OFF_F : h1_f;

        gath(hsrc, OFF_N, RP1, EL1, DS_POSTS_N, DS_POSTS_U, 0, N_USER);
        gath(hsrc, OFF_F, RP4, EL4, DS_FOL_F, DS_FOL_U, 128, N_USER);
        gemm2(agg, Wc + (0 * 6 + 1) * HH, Wc + (0 * 6 + 4) * HH,
              bc + (0 * 6 + 1) * HDIM, bc + (0 * 6 + 4) * HDIM, o_u, N_USER, 0.5f);
        gath(hsrc, OFF_U, RP0, EL0, DS_POSTS_U, DS_POSTS_N, 0, N_NEWS);
        gath(hsrc, OFF_S, RP2, EL2, DS_PUB_S, DS_PUB_N, 128, N_NEWS);
        gemm2(agg, Wc + (1 * 6 + 0) * HH, Wc + (1 * 6 + 2) * HH,
              bc + (1 * 6 + 0) * HDIM, bc + (1 * 6 + 2) * HDIM, o_n, N_NEWS, 0.5f);
        gath(hsrc, OFF_N, RP3, EL3, DS_PUB_N, DS_PUB_S, 0, N_SOURCE);
        tgemm_kernel<<<(N_SOURCE + 127) / 128, 256, SM_BYTES>>>(
            agg, 256, Wc + (2 * 6 + 3) * HH, nullptr, 128, 128,
            bc + (2 * 6 + 3) * HDIM, nullptr, o_s, N_SOURCE, 1.f, 1);
        gath(hsrc, OFF_U, RP5, EL5, DS_FOL_U, DS_FOL_F, 0, N_FOLLOWER);
        tgemm_kernel<<<(N_FOLLOWER + 127) / 128, 256, SM_BYTES>>>(
            agg, 256, Wc + (3 * 6 + 5) * HH, nullptr, 128, 128,
            bc + (3 * 6 + 5) * HDIM, nullptr, o_f, N_FOLLOWER, 1.f, 1);
    }

    // ---- head ----
    float* out_u = out + 0;
    float* out_n = out + (size_t)N_USER * 2;
    float* out_s = out + (size_t)(N_USER + N_NEWS) * 2;
    float* out_f = out + (size_t)(N_USER + N_NEWS + N_SOURCE) * 2;
    head_kernel<<<(N_USER * 32 + 255) / 256, 256>>>(h1_u, Wl_user, bl_user, out_u, N_USER);
    head_kernel<<<(N_NEWS * 32 + 255) / 256, 256>>>(h1_n, Wl_news, bl_news, out_n, N_NEWS);
    head_kernel<<<(N_SOURCE * 32 + 255) / 256, 256>>>(h1_s, Wl_source, bl_source, out_s, N_SOURCE);
    head_kernel<<<(N_FOLLOWER * 32 + 255) / 256, 256>>>(h1_f, Wl_follower, bl_follower, out_f, N_FOLLOWER);
}

// round 11
// speedup vs baseline: 1.3740x; 1.3740x over previous
#include <cuda_runtime.h>
#include <cuda_bf16.h>
#include <cstdint>
#include <cstddef>

#define N_USER 200000
#define N_NEWS 100000
#define N_SOURCE 5000
#define N_FOLLOWER 200000
#define HDIM 128
#define E_POSTS 500000
#define E_PUB 100000
#define E_FOL 1000000

#define TOT_NODES (N_USER + N_NEWS + N_SOURCE + N_FOLLOWER)

#define OFF_U ((size_t)0)
#define OFF_N ((size_t)N_USER * HDIM)
#define OFF_S ((size_t)(N_USER + N_NEWS) * HDIM)
#define OFF_F ((size_t)(N_USER + N_NEWS + N_SOURCE) * HDIM)

#define DS_POSTS_U 0
#define DS_POSTS_N 200000
#define DS_PUB_S   300000
#define DS_PUB_N   305000
#define DS_FOL_F   405000
#define DS_FOL_U   605000
#define DEG_TOTAL  805000

#define RP0 0
#define RP1 100001
#define RP2 300002
#define RP3 400003
#define RP4 405004
#define RP5 605005
#define RP_TOTAL 805006

#define EL0 0
#define EL1 500000
#define EL2 1000000
#define EL3 1100000
#define EL4 1200000
#define EL5 2200000
#define EL_TOTAL 3200000

__device__ float g_bufA[(size_t)TOT_NODES * HDIM];
__device__ float g_bufB[(size_t)TOT_NODES * HDIM];
__device__ float g_agg[(size_t)N_USER * 256];
__device__ float g_deg[DEG_TOTAL];
__device__ int   g_cnt[DEG_TOTAL];
__device__ int   g_cur[DEG_TOTAL];
__device__ int   g_rp[RP_TOTAL];
__device__ int   g_el[EL_TOTAL];

// ---------------------------------------------------------------------------
__global__ void zero4_kernel(float4* __restrict__ p, size_t n4) {
    size_t i = (size_t)blockIdx.x * blockDim.x + threadIdx.x;
    size_t stride = (size_t)gridDim.x * blockDim.x;
    float4 z = make_float4(0.f, 0.f, 0.f, 0.f);
    for (; i < n4; i += stride) p[i] = z;
}

__global__ void counti_kernel(const int* __restrict__ idx, int n, int* __restrict__ cnt) {
    int i = blockIdx.x * blockDim.x + threadIdx.x;
    int stride = gridDim.x * blockDim.x;
    for (; i < n; i += stride) atomicAdd(&cnt[idx[i]], 1);
}

__global__ void rsqrt_cnt_kernel(const int* __restrict__ cnt, float* __restrict__ deg, int n) {
    int i = blockIdx.x * blockDim.x + threadIdx.x;
    int stride = gridDim.x * blockDim.x;
    for (; i < n; i += stride) {
        int c = cnt[i];
        deg[i] = rsqrtf((float)(c < 1 ? 1 : c));
    }
}

__global__ __launch_bounds__(1024) void scan6_kernel(const int* __restrict__ cnt,
                                                     int* __restrict__ rp) {
    const int segs[6] = {DS_POSTS_N, DS_POSTS_U, DS_PUB_N, DS_PUB_S, DS_FOL_U, DS_FOL_F};
    const int ns[6]   = {N_NEWS, N_USER, N_NEWS, N_SOURCE, N_USER, N_FOLLOWER};
    const int rpo[6]  = {RP0, RP1, RP2, RP3, RP4, RP5};
    int r = blockIdx.x;
    const int* c = cnt + segs[r];
    int* out = rp + rpo[r];
    int n = ns[r];
    int tid = threadIdx.x;
    int lane = tid & 31;
    int wid = tid >> 5;
    __shared__ int wsum[32];
    __shared__ int carry;
    if (tid == 0) { carry = 0; out[0] = 0; }
    __syncthreads();
    for (int base = 0; base < n; base += 1024) {
        int v = (base + tid < n) ? c[base + tid] : 0;
        int x = v;
#pragma unroll
        for (int o = 1; o < 32; o <<= 1) {
            int y = __shfl_up_sync(0xffffffffu, x, o);
            if (lane >= o) x += y;
        }
        if (lane == 31) wsum[wid] = x;
        __syncthreads();
        if (wid == 0) {
            int s = wsum[lane];
#pragma unroll
            for (int o = 1; o < 32; o <<= 1) {
                int y = __shfl_up_sync(0xffffffffu, s, o);
                if (lane >= o) s += y;
            }
            wsum[lane] = s;
        }
        __syncthreads();
        int pre = (wid > 0) ? wsum[wid - 1] : 0;
        int incl = carry + pre + x;
        if (base + tid < n) out[base + tid + 1] = incl;
        __syncthreads();
        if (tid == 1023) carry = incl;
        __syncthreads();
    }
}

__global__ void fill_kernel(const int* __restrict__ src, const int* __restrict__ dst, int E,
                            const int* __restrict__ rp, int* __restrict__ cur,
                            int* __restrict__ el) {
    int i = blockIdx.x * blockDim.x + threadIdx.x;
    int stride = gridDim.x * blockDim.x;
    for (; i < E; i += stride) {
        int d = dst[i];
        int p = atomicAdd(&cur[d], 1);
        el[rp[d] + p] = src[i];
    }
}

__global__ void gather_kernel(const float* __restrict__ h, const int* __restrict__ rp,
                              const int* __restrict__ el, const float* __restrict__ rs_src,
                              const float* __restrict__ rs_dst, float* __restrict__ agg,
                              int colofs, int n_dst) {
    int warp = (blockIdx.x * blockDim.x + threadIdx.x) >> 5;
    int lane = threadIdx.x & 31;
    int nwarps = (gridDim.x * blockDim.x) >> 5;
    for (int row = warp; row < n_dst; row += nwarps) {
        int beg = rp[row], end = rp[row + 1];
        float4 acc = make_float4(0.f, 0.f, 0.f, 0.f);
        for (int e = beg; e < end; e++) {
            int s = el[e];
            float sc = rs_src[s];
            float4 v = *reinterpret_cast<const float4*>(h + (size_t)s * HDIM + lane * 4);
            acc.x += sc * v.x; acc.y += sc * v.y; acc.z += sc * v.z; acc.w += sc * v.w;
        }
        float ri = rs_dst[row];
        acc.x *= ri; acc.y *= ri; acc.z *= ri; acc.w *= ri;
        *reinterpret_cast<float4*>(agg + (size_t)row * 256 + colofs + lane * 4) = acc;
    }
}

// ---------------------------------------------------------------------------
// bf16x3 HMMA GEMM, K-chunk 64, 70KB smem, 128-reg cap -> 2 CTAs/SM.
// C[M,128] = epi( A[M,K](lda) @ [W0;W1][K,128] + b0 + b1 )
// ---------------------------------------------------------------------------
#define ASTR 72    // bf16 row stride for A smem (64 data + 8 pad -> 144B)
#define BSTR 136   // bf16 row stride for B smem (128 data + 8 pad -> 272B)
#define SM_BYTES (2 * 128 * ASTR * 2 + 2 * 64 * BSTR * 2)  // 36864+34816 = 71680 B

__device__ __forceinline__ void mma16816(float* c, const uint32_t* a, const uint32_t* b) {
    asm volatile(
        "mma.sync.aligned.m16n8k16.row.col.f32.bf16.bf16.f32 "
        "{%0,%1,%2,%3}, {%4,%5,%6,%7}, {%8,%9}, {%0,%1,%2,%3};\n"
        : "+f"(c[0]), "+f"(c[1]), "+f"(c[2]), "+f"(c[3])
        : "r"(a[0]), "r"(a[1]), "r"(a[2]), "r"(a[3]), "r"(b[0]), "r"(b[1]));
}
__device__ __forceinline__ void ldsm_x4(uint32_t* r, const void* p) {
    uint32_t addr = (uint32_t)__cvta_generic_to_shared(p);
    asm volatile("ldmatrix.sync.aligned.m8n8.x4.shared.b16 {%0,%1,%2,%3}, [%4];"
                 : "=r"(r[0]), "=r"(r[1]), "=r"(r[2]), "=r"(r[3]) : "r"(addr));
}
__device__ __forceinline__ void ldsm_x4_t(uint32_t* r, const void* p) {
    uint32_t addr = (uint32_t)__cvta_generic_to_shared(p);
    asm volatile("ldmatrix.sync.aligned.m8n8.x4.trans.shared.b16 {%0,%1,%2,%3}, [%4];"
                 : "=r"(r[0]), "=r"(r[1]), "=r"(r[2]), "=r"(r[3]) : "r"(addr));
}
__device__ __forceinline__ uint32_t pack_hi2(float a, float b, uint32_t* lo) {
    __nv_bfloat16 h0 = __float2bfloat16_rn(a);
    __nv_bfloat16 h1 = __float2bfloat16_rn(b);
    __nv_bfloat16 l0 = __float2bfloat16_rn(a - __bfloat162float(h0));
    __nv_bfloat16 l1 = __float2bfloat16_rn(b - __bfloat162float(h1));
    *lo = (uint32_t)__bfloat16_as_ushort(l0) | ((uint32_t)__bfloat16_as_ushort(l1) << 16);
    return (uint32_t)__bfloat16_as_ushort(h0) | ((uint32_t)__bfloat16_as_ushort(h1) << 16);
}

__global__ __launch_bounds__(256, 2) void tgemm_kernel(
    const float* __restrict__ A, int lda,
    const float* __restrict__ W0, const float* __restrict__ W1, int K0, int K,
    const float* __restrict__ b0, const float* __restrict__ b1,
    float* __restrict__ C, int M, float scale, int do_act) {
    extern __shared__ __align__(16) char smraw[];
    __nv_bfloat16* AH = reinterpret_cast<__nv_bfloat16*>(smraw);
    __nv_bfloat16* AL = AH + 128 * ASTR;
    __nv_bfloat16* BH = AL + 128 * ASTR;
    __nv_bfloat16* BL = BH + 64 * BSTR;

    int tid = threadIdx.x;
    int lane = tid & 31;
    int warp = tid >> 5;
    int wm = warp & 1;
    int wn = warp >> 1;
    int block_row = blockIdx.x * 128;

    float c[4][4][4];
#pragma unroll
    for (int mt = 0; mt < 4; mt++)
#pragma unroll
        for (int nt = 0; nt < 4; nt++)
#pragma unroll
            for (int j = 0; j < 4; j++) c[mt][nt][j] = 0.f;

    for (int kbase = 0; kbase < K; kbase += 64) {
        int kcount = K - kbase; if (kcount > 64) kcount = 64;
        // ---- stage A chunk: 128 rows x 64 k ----
        for (int idx = tid; idx < 128 * 8; idx += 256) {
            int row = idx >> 3;
            int kl = (idx & 7) * 8;
            float v[8];
#pragma unroll
            for (int j = 0; j < 8; j++) v[j] = 0.f;
            int grow = block_row + row;
            int gk = kbase + kl;
            if (grow < M && gk < K) {
                const float* ap = A + (size_t)grow * lda + gk;
                if (gk + 7 < K) {
                    float4 v0 = *reinterpret_cast<const float4*>(ap);
                    float4 v1 = *reinterpret_cast<const float4*>(ap + 4);
                    v[0] = v0.x; v[1] = v0.y; v[2] = v0.z; v[3] = v0.w;
                    v[4] = v1.x; v[5] = v1.y; v[6] = v1.z; v[7] = v1.w;
                } else {
#pragma unroll
                    for (int j = 0; j < 8; j++)
                        if (gk + j < K) v[j] = ap[j];
                }
            }
            uint32_t hp[4], lp[4];
#pragma unroll
            for (int j = 0; j < 4; j++) hp[j] = pack_hi2(v[2 * j], v[2 * j + 1], &lp[j]);
            uint32_t off = (uint32_t)(row * ASTR + kl);
            *reinterpret_cast<uint4*>(&AH[off]) = make_uint4(hp[0], hp[1], hp[2], hp[3]);
            *reinterpret_cast<uint4*>(&AL[off]) = make_uint4(lp[0], lp[1], lp[2], lp[3]);
        }
        // ---- stage W chunk: 64 k-rows x 128 n ----
        for (int idx = tid; idx < 64 * 16; idx += 256) {
            int kr = idx >> 4;
            int nl = (idx & 15) * 8;
            float v[8];
#pragma unroll
            for (int j = 0; j < 8; j++) v[j] = 0.f;
            int gk = kbase + kr;
            if (gk < K) {
                const float* wp = (gk < K0) ? W0 + (size_t)gk * HDIM + nl
                                            : W1 + (size_t)(gk - K0) * HDIM + nl;
                float4 v0 = *reinterpret_cast<const float4*>(wp);
                float4 v1 = *reinterpret_cast<const float4*>(wp + 4);
                v[0] = v0.x; v[1] = v0.y; v[2] = v0.z; v[3] = v0.w;
                v[4] = v1.x; v[5] = v1.y; v[6] = v1.z; v[7] = v1.w;
            }
            uint32_t hp[4], lp[4];
#pragma unroll
            for (int j = 0; j < 4; j++) hp[j] = pack_hi2(v[2 * j], v[2 * j + 1], &lp[j]);
            uint32_t off = (uint32_t)(kr * BSTR + nl);
            *reinterpret_cast<uint4*>(&BH[off]) = make_uint4(hp[0], hp[1], hp[2], hp[3]);
            *reinterpret_cast<uint4*>(&BL[off]) = make_uint4(lp[0], lp[1], lp[2], lp[3]);
        }
        __syncthreads();

        int nsteps = (kcount + 15) / 16;
        for (int s = 0; s < nsteps; s++) {
            uint32_t bh[4][2], bl[4][2];
#pragma unroll
            for (int half = 0; half < 2; half++) {
                uint32_t off = (uint32_t)((s * 16 + (lane & 15)) * BSTR + wn * 32 +
                                          half * 16 + (lane >> 4) * 8);
                uint32_t r[4];
                ldsm_x4_t(r, &BH[off]);
                bh[half * 2][0] = r[0]; bh[half * 2][1] = r[1];
                bh[half * 2 + 1][0] = r[2]; bh[half * 2 + 1][1] = r[3];
                ldsm_x4_t(r, &BL[off]);
                bl[half * 2][0] = r[0]; bl[half * 2][1] = r[1];
                bl[half * 2 + 1][0] = r[2]; bl[half * 2 + 1][1] = r[3];
            }
#pragma unroll
            for (int mt = 0; mt < 4; mt++) {
                uint32_t off = (uint32_t)((wm * 64 + mt * 16 + (lane & 15)) * ASTR +
                                          s * 16 + (lane >> 4) * 8);
                uint32_t ah[4], al[4];
                ldsm_x4(ah, &AH[off]);
                ldsm_x4(al, &AL[off]);
#pragma unroll
                for (int nt = 0; nt < 4; nt++) {
                    mma16816(c[mt][nt], ah, bh[nt]);
                    mma16816(c[mt][nt], ah, bl[nt]);
                    mma16816(c[mt][nt], al, bh[nt]);
                }
            }
        }
        __syncthreads();
    }

    // ---- epilogue ----
#pragma unroll
    for (int mt = 0; mt < 4; mt++) {
#pragma unroll
        for (int nt = 0; nt < 4; nt++) {
            int col = wn * 32 + nt * 8 + (lane & 3) * 2;
            float bb0 = (b0 ? b0[col] : 0.f) + (b1 ? b1[col] : 0.f);
            float bb1 = (b0 ? b0[col + 1] : 0.f) + (b1 ? b1[col + 1] : 0.f);
#pragma unroll
            for (int h = 0; h < 2; h++) {
                int row = block_row + wm * 64 + mt * 16 + (lane >> 2) + h * 8;
                if (row >= M) continue;
                float r0 = (c[mt][nt][2 * h] + bb0) * scale;
                float r1 = (c[mt][nt][2 * h + 1] + bb1) * scale;
                if (do_act) {
                    r0 = r0 > 0.f ? r0 : 0.01f * r0;
                    r1 = r1 > 0.f ? r1 : 0.01f * r1;
                }
                *reinterpret_cast<float2*>(C + (size_t)row * HDIM + col) = make_float2(r0, r1);
            }
        }
    }
}

// final head: out[r,0:2] = h1[r,:] @ Wl[128,2] + bl
__global__ void head_kernel(const float* __restrict__ h1, const float* __restrict__ Wl,
                            const float* __restrict__ bl, float* __restrict__ out, int Nrows) {
    int warp = (blockIdx.x * blockDim.x + threadIdx.x) >> 5;
    int lane = threadIdx.x & 31;
    int nwarps = (gridDim.x * blockDim.x) >> 5;
    int k = lane * 4;
    float w00 = Wl[(k + 0) * 2], w01 = Wl[(k + 0) * 2 + 1];
    float w10 = Wl[(k + 1) * 2], w11 = Wl[(k + 1) * 2 + 1];
    float w20 = Wl[(k + 2) * 2], w21 = Wl[(k + 2) * 2 + 1];
    float w30 = Wl[(k + 3) * 2], w31 = Wl[(k + 3) * 2 + 1];
    for (int r = warp; r < Nrows; r += nwarps) {
        float4 v = *reinterpret_cast<const float4*>(h1 + (size_t)r * HDIM + k);
        float p0 = v.x * w00 + v.y * w10 + v.z * w20 + v.w * w30;
        float p1 = v.x * w01 + v.y * w11 + v.z * w21 + v.w * w31;
#pragma unroll
        for (int off = 16; off; off >>= 1) {
            p0 += __shfl_xor_sync(0xffffffffu, p0, off);
            p1 += __shfl_xor_sync(0xffffffffu, p1, off);
        }
        if (lane == 0) {
            out[(size_t)r * 2 + 0] = p0 + bl[0];
            out[(size_t)r * 2 + 1] = p1 + bl[1];
        }
    }
}

// ---------------------------------------------------------------------------
extern "C" void kernel_launch(void* const* d_in, const int* in_sizes, int n_in,
                              void* d_out, int out_size) {
    const float* x_user = (const float*)d_in[0];
    const float* x_news = (const float*)d_in[1];
    const float* x_source = (const float*)d_in[2];
    const float* x_follower = (const float*)d_in[3];
    const float* Wi1_user = (const float*)d_in[4];
    const float* bi1_user = (const float*)d_in[5];
    const float* Wi1_news = (const float*)d_in[6];
    const float* bi1_news = (const float*)d_in[7];
    const float* Wi1_source = (const float*)d_in[8];
    const float* bi1_source = (const float*)d_in[9];
    const float* Wi1_follower = (const float*)d_in[10];
    const float* bi1_follower = (const float*)d_in[11];
    const float* Wi2 = (const float*)d_in[12];
    const float* bi2 = (const float*)d_in[13];
    const float* conv1_W = (const float*)d_in[14];
    const float* conv1_b = (const float*)d_in[15];
    const float* conv2_W = (const float*)d_in[16];
    const float* conv2_b = (const float*)d_in[17];
    const float* Wl_user = (const float*)d_in[18];
    const float* bl_user = (const float*)d_in[19];
    const float* Wl_news = (const float*)d_in[20];
    const float* bl_news = (const float*)d_in[21];
    const float* Wl_source = (const float*)d_in[22];
    const float* bl_source = (const float*)d_in[23];
    const float* Wl_follower = (const float*)d_in[24];
    const float* bl_follower = (const float*)d_in[25];
    const int* posts_u = (const int*)d_in[26];
    const int* posts_n = (const int*)d_in[27];
    const int* pub_s = (const int*)d_in[28];
    const int* pub_n = (const int*)d_in[29];
    const int* fol_f = (const int*)d_in[30];
    const int* fol_u = (const int*)d_in[31];
    float* out = (float*)d_out;

    float *bufA, *bufB, *agg, *deg;
    int *cnt, *cur, *rp, *el;
    cudaGetSymbolAddress((void**)&bufA, g_bufA);
    cudaGetSymbolAddress((void**)&bufB, g_bufB);
    cudaGetSymbolAddress((void**)&agg, g_agg);
    cudaGetSymbolAddress((void**)&deg, g_deg);
    cudaGetSymbolAddress((void**)&cnt, g_cnt);
    cudaGetSymbolAddress((void**)&cur, g_cur);
    cudaGetSymbolAddress((void**)&rp, g_rp);
    cudaGetSymbolAddress((void**)&el, g_el);

    cudaFuncSetAttribute(tgemm_kernel, cudaFuncAttributeMaxDynamicSharedMemorySize, SM_BYTES);

    auto gemm1 = [](const float* A, int lda, const float* W, int K, const float* b,
                    float* C, int M, float scale, int act) {
        tgemm_kernel<<<(M + 127) / 128, 256, SM_BYTES>>>(A, lda, W, nullptr, K, K, b, nullptr,
                                                         C, M, scale, act);
    };
    auto gemm2 = [](const float* A, const float* Wa, const float* Wb, const float* ba,
                    const float* bb, float* C, int M, float scale) {
        tgemm_kernel<<<(M + 127) / 128, 256, SM_BYTES>>>(A, 256, Wa, Wb, 128, 256, ba, bb,
                                                         C, M, scale, 1);
    };

    const size_t HH = (size_t)HDIM * HDIM;

    // ---- dense layer 1 (launch idx 0-3): x -> bufA ----
    gemm1(x_user, 128, Wi1_user, 128, bi1_user, bufA + OFF_U, N_USER, 1.f, 1);
    gemm1(x_source, 128, Wi1_source, 128, bi1_source, bufA + OFF_S, N_SOURCE, 1.f, 1);
    gemm1(x_follower, 128, Wi1_follower, 128, bi1_follower, bufA + OFF_F, N_FOLLOWER, 1.f, 1);
    gemm1(x_news, 300, Wi1_news, 300, bi1_news, bufA + OFF_N, N_NEWS, 1.f, 1);

    // ---- dense layer 2 (idx 4-7; idx 5 = follower M=200k for ncu capture) ----
    gemm1(bufA + OFF_U, 128, Wi2 + 0 * HH, 128, bi2 + 0 * HDIM, bufB + OFF_U, N_USER, 1.f, 1);
    gemm1(bufA + OFF_F, 128, Wi2 + 3 * HH, 128, bi2 + 3 * HDIM, bufB + OFF_F, N_FOLLOWER, 1.f, 1);
    gemm1(bufA + OFF_N, 128, Wi2 + 1 * HH, 128, bi2 + 1 * HDIM, bufB + OFF_N, N_NEWS, 1.f, 1);
    gemm1(bufA + OFF_S, 128, Wi2 + 2 * HH, 128, bi2 + 2 * HDIM, bufB + OFF_S, N_SOURCE, 1.f, 1);

    // ---- CSR build ----
    zero4_kernel<<<2048, 256>>>((float4*)cnt, DEG_TOTAL / 4);
    zero4_kernel<<<2048, 256>>>((float4*)cur, DEG_TOTAL / 4);
    counti_kernel<<<2048, 256>>>(posts_u, E_POSTS, cnt + DS_POSTS_U);
    counti_kernel<<<2048, 256>>>(posts_n, E_POSTS, cnt + DS_POSTS_N);
    counti_kernel<<<512, 256>>>(pub_s, E_PUB, cnt + DS_PUB_S);
    counti_kernel<<<512, 256>>>(pub_n, E_PUB, cnt + DS_PUB_N);
    counti_kernel<<<4096, 256>>>(fol_f, E_FOL, cnt + DS_FOL_F);
    counti_kernel<<<4096, 256>>>(fol_u, E_FOL, cnt + DS_FOL_U);
    rsqrt_cnt_kernel<<<2048, 256>>>(cnt, deg, DEG_TOTAL);
    scan6_kernel<<<6, 1024>>>(cnt, rp);
    fill_kernel<<<2048, 256>>>(posts_u, posts_n, E_POSTS, rp + RP0, cur + DS_POSTS_N, el + EL0);
    fill_kernel<<<2048, 256>>>(posts_n, posts_u, E_POSTS, rp + RP1, cur + DS_POSTS_U, el + EL1);
    fill_kernel<<<512, 256>>>(pub_s, pub_n, E_PUB, rp + RP2, cur + DS_PUB_N, el + EL2);
    fill_kernel<<<512, 256>>>(pub_n, pub_s, E_PUB, rp + RP3, cur + DS_PUB_S, el + EL3);
    fill_kernel<<<4096, 256>>>(fol_f, fol_u, E_FOL, rp + RP4, cur + DS_FOL_U, el + EL4);
    fill_kernel<<<4096, 256>>>(fol_u, fol_f, E_FOL, rp + RP5, cur + DS_FOL_F, el + EL5);

    auto gath = [&](const float* hbase, size_t hoff, int rpo, int elo, int rs_src, int rs_dst,
                    int colofs, int n_dst) {
        gather_kernel<<<(n_dst + 7) / 8, 256>>>(hbase + hoff, rp + rpo, el + elo,
                                                deg + rs_src, deg + rs_dst, agg, colofs, n_dst);
    };

    // ---- conv layers ----
    const size_t H1_BASE = (size_t)TOT_NODES * 2;
    float* h1_u = out + H1_BASE + OFF_U;
    float* h1_n = out + H1_BASE + OFF_N;
    float* h1_s = out + H1_BASE + OFF_S;
    float* h1_f = out + H1_BASE + OFF_F;

    for (int layer = 0; layer < 2; layer++) {
        const float* hsrc = (layer == 0) ? bufB : bufA;
        const float* Wc = (layer == 0) ? conv1_W : conv2_W;
        const float* bc = (layer == 0) ? conv1_b : conv2_b;
        float* o_u = (layer == 0) ? bufA + OFF_U : h1_u;
        float* o_n = (layer == 0) ? bufA + OFF_N : h1_n;
        float* o_s = (layer == 0) ? bufA + OFF_S : h1_s;
        float* o_f = (layer == 0) ? bufA + OFF_F : h1_f;

        gath(hsrc, OFF_N, RP1, EL1, DS_POSTS_N, DS_POSTS_U, 0, N_USER);
        gath(hsrc, OFF_F, RP4, EL4, DS_FOL_F, DS_FOL_U, 128, N_USER);
        gemm2(agg, Wc + (0 * 6 + 1) * HH, Wc + (0 * 6 + 4) * HH,
              bc + (0 * 6 + 1) * HDIM, bc + (0 * 6 + 4) * HDIM, o_u, N_USER, 0.5f);
        gath(hsrc, OFF_U, RP0, EL0, DS_POSTS_U, DS_POSTS_N, 0, N_NEWS);
        gath(hsrc, OFF_S, RP2, EL2, DS_PUB_S, DS_PUB_N, 128, N_NEWS);
        gemm2(agg, Wc + (1 * 6 + 0) * HH, Wc + (1 * 6 + 2) * HH,
              bc + (1 * 6 + 0) * HDIM, bc + (1 * 6 + 2) * HDIM, o_n, N_NEWS, 0.5f);
        gath(hsrc, OFF_N, RP3, EL3, DS_PUB_N, DS_PUB_S, 0, N_SOURCE);
        tgemm_kernel<<<(N_SOURCE + 127) / 128, 256, SM_BYTES>>>(
            agg, 256, Wc + (2 * 6 + 3) * HH, nullptr, 128, 128,
            bc + (2 * 6 + 3) * HDIM, nullptr, o_s, N_SOURCE, 1.f, 1);
        gath(hsrc, OFF_U, RP5, EL5, DS_FOL_U, DS_FOL_F, 0, N_FOLLOWER);
        tgemm_kernel<<<(N_FOLLOWER + 127) / 128, 256, SM_BYTES>>>(
            agg, 256, Wc + (3 * 6 + 5) * HH, nullptr, 128, 128,
            bc + (3 * 6 + 5) * HDIM, nullptr, o_f, N_FOLLOWER, 1.f, 1);
    }

    // ---- head ----
    float* out_u = out + 0;
    float* out_n = out + (size_t)N_USER * 2;
    float* out_s = out + (size_t)(N_USER + N_NEWS) * 2;
    float* out_f = out + (size_t)(N_USER + N_NEWS + N_SOURCE) * 2;
    head_kernel<<<(N_USER * 32 + 255) / 256, 256>>>(h1_u, Wl_user, bl_user, out_u, N_USER);
    head_kernel<<<(N_NEWS * 32 + 255) / 256, 256>>>(h1_n, Wl_news, bl_news, out_n, N_NEWS);
    head_kernel<<<(N_SOURCE * 32 + 255) / 256, 256>>>(h1_s, Wl_source, bl_source, out_s, N_SOURCE);
    head_kernel<<<(N_FOLLOWER * 32 + 255) / 256, 256>>>(h1_f, Wl_follower, bl_follower, out_f, N_FOLLOWER);
}

// round 12
// speedup vs baseline: 1.5023x; 1.0934x over previous
#include <cuda_runtime.h>
#include <cuda_bf16.h>
#include <cstdint>
#include <cstddef>

#define N_USER 200000
#define N_NEWS 100000
#define N_SOURCE 5000
#define N_FOLLOWER 200000
#define HDIM 128
#define E_POSTS 500000
#define E_PUB 100000
#define E_FOL 1000000

#define TOT_NODES (N_USER + N_NEWS + N_SOURCE + N_FOLLOWER)

#define OFF_U ((size_t)0)
#define OFF_N ((size_t)N_USER * HDIM)
#define OFF_S ((size_t)(N_USER + N_NEWS) * HDIM)
#define OFF_F ((size_t)(N_USER + N_NEWS + N_SOURCE) * HDIM)

#define DS_POSTS_U 0
#define DS_POSTS_N 200000
#define DS_PUB_S   300000
#define DS_PUB_N   305000
#define DS_FOL_F   405000
#define DS_FOL_U   605000
#define DEG_TOTAL  805000

#define RP0 0
#define RP1 100001
#define RP2 300002
#define RP3 400003
#define RP4 405004
#define RP5 605005
#define RP_TOTAL 805006

#define EL0 0
#define EL1 500000
#define EL2 1000000
#define EL3 1100000
#define EL4 1200000
#define EL5 2200000
#define EL_TOTAL 3200000

// weight-plane segment offsets (elements)
#define WU1 0
#define WN1 16384
#define WS1 54784
#define WF1 71168
#define WI2 87552
#define WC1 153088
#define WC2 546304
#define WTOT 939520

// split feature planes (bf16 hi/lo) + scratch
__device__ __nv_bfloat16 g_pAh[(size_t)TOT_NODES * HDIM];
__device__ __nv_bfloat16 g_pAl[(size_t)TOT_NODES * HDIM];
__device__ __nv_bfloat16 g_pBh[(size_t)TOT_NODES * HDIM];
__device__ __nv_bfloat16 g_pBl[(size_t)TOT_NODES * HDIM];
__device__ __nv_bfloat16 g_aggh[(size_t)N_USER * 256];
__device__ __nv_bfloat16 g_aggl[(size_t)N_USER * 256];
__device__ __nv_bfloat16 g_wh[WTOT];
__device__ __nv_bfloat16 g_wl[WTOT];
__device__ float g_deg[DEG_TOTAL];
__device__ int   g_cnt[DEG_TOTAL];
__device__ int   g_cur[DEG_TOTAL];
__device__ int   g_rp[RP_TOTAL];
__device__ int   g_el[EL_TOTAL];

// ---------------------------------------------------------------------------
__device__ __forceinline__ uint32_t pack_hi2(float a, float b, uint32_t* lo) {
    __nv_bfloat16 h0 = __float2bfloat16_rn(a);
    __nv_bfloat16 h1 = __float2bfloat16_rn(b);
    __nv_bfloat16 l0 = __float2bfloat16_rn(a - __bfloat162float(h0));
    __nv_bfloat16 l1 = __float2bfloat16_rn(b - __bfloat162float(h1));
    *lo = (uint32_t)__bfloat16_as_ushort(l0) | ((uint32_t)__bfloat16_as_ushort(l1) << 16);
    return (uint32_t)__bfloat16_as_ushort(h0) | ((uint32_t)__bfloat16_as_ushort(h1) << 16);
}
__device__ __forceinline__ float bflo(uint32_t u) { return __uint_as_float(u << 16); }
__device__ __forceinline__ float bfhi(uint32_t u) { return __uint_as_float(u & 0xffff0000u); }

// ---------------------------------------------------------------------------
__global__ void zero4_kernel(float4* __restrict__ p, size_t n4) {
    size_t i = (size_t)blockIdx.x * blockDim.x + threadIdx.x;
    size_t stride = (size_t)gridDim.x * blockDim.x;
    float4 z = make_float4(0.f, 0.f, 0.f, 0.f);
    for (; i < n4; i += stride) p[i] = z;
}

// split all weight tensors into bf16 hi/lo planes; segment per blockIdx.y
__global__ void wsplit_kernel(const float* __restrict__ wu, const float* __restrict__ wn,
                              const float* __restrict__ ws, const float* __restrict__ wf,
                              const float* __restrict__ wi2, const float* __restrict__ c1,
                              const float* __restrict__ c2,
                              __nv_bfloat16* __restrict__ wh, __nv_bfloat16* __restrict__ wl) {
    const float* src; int n; int off;
    switch (blockIdx.y) {
        case 0: src = wu;  n = 16384;  off = WU1; break;
        case 1: src = wn;  n = 38400;  off = WN1; break;
        case 2: src = ws;  n = 16384;  off = WS1; break;
        case 3: src = wf;  n = 16384;  off = WF1; break;
        case 4: src = wi2; n = 65536;  off = WI2; break;
        case 5: src = c1;  n = 393216; off = WC1; break;
        default: src = c2; n = 393216; off = WC2; break;
    }
    int stride = gridDim.x * blockDim.x;
    for (int i = blockIdx.x * blockDim.x + threadIdx.x; i < n; i += stride) {
        float x = src[i];
        __nv_bfloat16 h = __float2bfloat16_rn(x);
        wh[off + i] = h;
        wl[off + i] = __float2bfloat16_rn(x - __bfloat162float(h));
    }
}

__global__ void counti_kernel(const int* __restrict__ idx, int n, int* __restrict__ cnt) {
    int i = blockIdx.x * blockDim.x + threadIdx.x;
    int stride = gridDim.x * blockDim.x;
    for (; i < n; i += stride) atomicAdd(&cnt[idx[i]], 1);
}

__global__ void rsqrt_cnt_kernel(const int* __restrict__ cnt, float* __restrict__ deg, int n) {
    int i = blockIdx.x * blockDim.x + threadIdx.x;
    int stride = gridDim.x * blockDim.x;
    for (; i < n; i += stride) {
        int c = cnt[i];
        deg[i] = rsqrtf((float)(c < 1 ? 1 : c));
    }
}

__global__ __launch_bounds__(1024) void scan6_kernel(const int* __restrict__ cnt,
                                                     int* __restrict__ rp) {
    const int segs[6] = {DS_POSTS_N, DS_POSTS_U, DS_PUB_N, DS_PUB_S, DS_FOL_U, DS_FOL_F};
    const int ns[6]   = {N_NEWS, N_USER, N_NEWS, N_SOURCE, N_USER, N_FOLLOWER};
    const int rpo[6]  = {RP0, RP1, RP2, RP3, RP4, RP5};
    int r = blockIdx.x;
    const int* c = cnt + segs[r];
    int* out = rp + rpo[r];
    int n = ns[r];
    int tid = threadIdx.x;
    int lane = tid & 31;
    int wid = tid >> 5;
    __shared__ int wsum[32];
    __shared__ int carry;
    if (tid == 0) { carry = 0; out[0] = 0; }
    __syncthreads();
    for (int base = 0; base < n; base += 1024) {
        int v = (base + tid < n) ? c[base + tid] : 0;
        int x = v;
#pragma unroll
        for (int o = 1; o < 32; o <<= 1) {
            int y = __shfl_up_sync(0xffffffffu, x, o);
            if (lane >= o) x += y;
        }
        if (lane == 31) wsum[wid] = x;
        __syncthreads();
        if (wid == 0) {
            int s = wsum[lane];
#pragma unroll
            for (int o = 1; o < 32; o <<= 1) {
                int y = __shfl_up_sync(0xffffffffu, s, o);
                if (lane >= o) s += y;
            }
            wsum[lane] = s;
        }
        __syncthreads();
        int pre = (wid > 0) ? wsum[wid - 1] : 0;
        int incl = carry + pre + x;
        if (base + tid < n) out[base + tid + 1] = incl;
        __syncthreads();
        if (tid == 1023) carry = incl;
        __syncthreads();
    }
}

__global__ void fill_kernel(const int* __restrict__ src, const int* __restrict__ dst, int E,
                            const int* __restrict__ rp, int* __restrict__ cur,
                            int* __restrict__ el) {
    int i = blockIdx.x * blockDim.x + threadIdx.x;
    int stride = gridDim.x * blockDim.x;
    for (; i < E; i += stride) {
        int d = dst[i];
        int p = atomicAdd(&cur[d], 1);
        el[rp[d] + p] = src[i];
    }
}

// CSR gather over split planes: agg[row, colofs..+127] = rs_dst[row] * sum rs_src[s]*h[s]
__global__ void gather_kernel(const __nv_bfloat16* __restrict__ Hh,
                              const __nv_bfloat16* __restrict__ Hl,
                              const int* __restrict__ rp, const int* __restrict__ el,
                              const float* __restrict__ rs_src,
                              const float* __restrict__ rs_dst,
                              __nv_bfloat16* __restrict__ Ah, __nv_bfloat16* __restrict__ Al,
                              int colofs, int n_dst) {
    int warp = (blockIdx.x * blockDim.x + threadIdx.x) >> 5;
    int lane = threadIdx.x & 31;
    int nwarps = (gridDim.x * blockDim.x) >> 5;
    for (int row = warp; row < n_dst; row += nwarps) {
        int beg = rp[row], end = rp[row + 1];
        float a0 = 0.f, a1 = 0.f, a2 = 0.f, a3 = 0.f;
        for (int e = beg; e < end; e++) {
            int s = el[e];
            float sc = rs_src[s];
            const size_t base = (size_t)s * HDIM + lane * 4;
            uint2 vh = *reinterpret_cast<const uint2*>(Hh + base);
            uint2 vl = *reinterpret_cast<const uint2*>(Hl + base);
            a0 += sc * (bflo(vh.x) + bflo(vl.x));
            a1 += sc * (bfhi(vh.x) + bfhi(vl.x));
            a2 += sc * (bflo(vh.y) + bflo(vl.y));
            a3 += sc * (bfhi(vh.y) + bfhi(vl.y));
        }
        float ri = rs_dst[row];
        a0 *= ri; a1 *= ri; a2 *= ri; a3 *= ri;
        uint32_t lp0, lp1;
        uint32_t hp0 = pack_hi2(a0, a1, &lp0);
        uint32_t hp1 = pack_hi2(a2, a3, &lp1);
        size_t o = (size_t)row * 256 + colofs + lane * 4;
        *reinterpret_cast<uint2*>(Ah + o) = make_uint2(hp0, hp1);
        *reinterpret_cast<uint2*>(Al + o) = make_uint2(lp0, lp1);
    }
}

// ---------------------------------------------------------------------------
// bf16x3 HMMA GEMM, K-chunk 64, 70KB smem, 2 CTAs/SM (reg cap 128).
// A input: fp32 (Afp) with in-kernel split, OR pre-split planes (Ah/Al) via cp.async.
// W input: pre-split planes, two segments [0,K0) -> Wh0/Wl0, [K0,K) -> Wh1/Wl1.
// Output: fp32 (Cf) or split planes (Ch/Cl).
// ---------------------------------------------------------------------------
#define ASTR 72
#define BSTR 136
#define SM_BYTES (2 * 128 * ASTR * 2 + 2 * 64 * BSTR * 2)  // 71680 B

#define CP_ASYNC16(smem, gptr) \
    asm volatile("cp.async.cg.shared.global [%0], [%1], 16;" :: "r"(smem), "l"(gptr))
#define CP_COMMIT() asm volatile("cp.async.commit_group;")
#define CP_WAIT0()  asm volatile("cp.async.wait_group 0;" ::: "memory")

__device__ __forceinline__ void mma16816(float* c, const uint32_t* a, const uint32_t* b) {
    asm volatile(
        "mma.sync.aligned.m16n8k16.row.col.f32.bf16.bf16.f32 "
        "{%0,%1,%2,%3}, {%4,%5,%6,%7}, {%8,%9}, {%0,%1,%2,%3};\n"
        : "+f"(c[0]), "+f"(c[1]), "+f"(c[2]), "+f"(c[3])
        : "r"(a[0]), "r"(a[1]), "r"(a[2]), "r"(a[3]), "r"(b[0]), "r"(b[1]));
}
__device__ __forceinline__ void ldsm_x4(uint32_t* r, const void* p) {
    uint32_t addr = (uint32_t)__cvta_generic_to_shared(p);
    asm volatile("ldmatrix.sync.aligned.m8n8.x4.shared.b16 {%0,%1,%2,%3}, [%4];"
                 : "=r"(r[0]), "=r"(r[1]), "=r"(r[2]), "=r"(r[3]) : "r"(addr));
}
__device__ __forceinline__ void ldsm_x4_t(uint32_t* r, const void* p) {
    uint32_t addr = (uint32_t)__cvta_generic_to_shared(p);
    asm volatile("ldmatrix.sync.aligned.m8n8.x4.trans.shared.b16 {%0,%1,%2,%3}, [%4];"
                 : "=r"(r[0]), "=r"(r[1]), "=r"(r[2]), "=r"(r[3]) : "r"(addr));
}

__global__ __launch_bounds__(256, 2) void tgemm_kernel(
    const float* __restrict__ Afp,
    const __nv_bfloat16* __restrict__ Ah, const __nv_bfloat16* __restrict__ Al, int lda,
    const __nv_bfloat16* __restrict__ Wh0, const __nv_bfloat16* __restrict__ Wl0,
    const __nv_bfloat16* __restrict__ Wh1, const __nv_bfloat16* __restrict__ Wl1,
    int K0, int K,
    const float* __restrict__ b0, const float* __restrict__ b1,
    float* __restrict__ Cf, __nv_bfloat16* __restrict__ Ch, __nv_bfloat16* __restrict__ Cl,
    int M, float scale, int do_act) {
    extern __shared__ __align__(16) char smraw[];
    __nv_bfloat16* AH = reinterpret_cast<__nv_bfloat16*>(smraw);
    __nv_bfloat16* AL = AH + 128 * ASTR;
    __nv_bfloat16* BH = AL + 128 * ASTR;
    __nv_bfloat16* BL = BH + 64 * BSTR;

    int tid = threadIdx.x;
    int lane = tid & 31;
    int warp = tid >> 5;
    int wm = warp & 1;
    int wn = warp >> 1;
    int block_row = blockIdx.x * 128;
    const uint4 z4 = make_uint4(0, 0, 0, 0);

    float c[4][4][4];
#pragma unroll
    for (int mt = 0; mt < 4; mt++)
#pragma unroll
        for (int nt = 0; nt < 4; nt++)
#pragma unroll
            for (int j = 0; j < 4; j++) c[mt][nt][j] = 0.f;

    for (int kbase = 0; kbase < K; kbase += 64) {
        int kcount = K - kbase; if (kcount > 64) kcount = 64;
        // ---- stage A chunk: 128 rows x 64 k ----
        if (Afp == nullptr) {
            // pre-split planes: pure 16B async copies
            for (int idx = tid; idx < 1024; idx += 256) {
                int row = idx >> 3;
                int kl = (idx & 7) * 8;
                int grow = block_row + row;
                int gk = kbase + kl;
                if (grow < M && gk < K) {
                    size_t go = (size_t)grow * lda + gk;
                    CP_ASYNC16((uint32_t)__cvta_generic_to_shared(&AH[row * ASTR + kl]), Ah + go);
                    CP_ASYNC16((uint32_t)__cvta_generic_to_shared(&AL[row * ASTR + kl]), Al + go);
                } else {
                    *reinterpret_cast<uint4*>(&AH[row * ASTR + kl]) = z4;
                    *reinterpret_cast<uint4*>(&AL[row * ASTR + kl]) = z4;
                }
            }
        } else {
            // raw fp32: load + split in registers
            for (int idx = tid; idx < 1024; idx += 256) {
                int row = idx >> 3;
                int kl = (idx & 7) * 8;
                float v[8];
#pragma unroll
                for (int j = 0; j < 8; j++) v[j] = 0.f;
                int grow = block_row + row;
                int gk = kbase + kl;
                if (grow < M && gk < K) {
                    const float* ap = Afp + (size_t)grow * lda + gk;
                    if (gk + 7 < K) {
                        float4 v0 = *reinterpret_cast<const float4*>(ap);
                        float4 v1 = *reinterpret_cast<const float4*>(ap + 4);
                        v[0] = v0.x; v[1] = v0.y; v[2] = v0.z; v[3] = v0.w;
                        v[4] = v1.x; v[5] = v1.y; v[6] = v1.z; v[7] = v1.w;
                    } else {
#pragma unroll
                        for (int j = 0; j < 8; j++)
                            if (gk + j < K) v[j] = ap[j];
                    }
                }
                uint32_t hp[4], lp[4];
#pragma unroll
                for (int j = 0; j < 4; j++) hp[j] = pack_hi2(v[2 * j], v[2 * j + 1], &lp[j]);
                uint32_t off = (uint32_t)(row * ASTR + kl);
                *reinterpret_cast<uint4*>(&AH[off]) = make_uint4(hp[0], hp[1], hp[2], hp[3]);
                *reinterpret_cast<uint4*>(&AL[off]) = make_uint4(lp[0], lp[1], lp[2], lp[3]);
            }
        }
        // ---- stage W chunk: 64 k-rows x 128 n (pre-split planes) ----
        for (int idx = tid; idx < 1024; idx += 256) {
            int kr = idx >> 4;
            int nl = (idx & 15) * 8;
            int gk = kbase + kr;
            uint32_t off = (uint32_t)(kr * BSTR + nl);
            if (gk < K) {
                size_t go = (gk < K0) ? ((size_t)gk * HDIM + nl)
                                      : ((size_t)(gk - K0) * HDIM + nl);
                const __nv_bfloat16* sh = (gk < K0) ? Wh0 : Wh1;
                const __nv_bfloat16* sl = (gk < K0) ? Wl0 : Wl1;
                CP_ASYNC16((uint32_t)__cvta_generic_to_shared(&BH[off]), sh + go);
                CP_ASYNC16((uint32_t)__cvta_generic_to_shared(&BL[off]), sl + go);
            } else {
                *reinterpret_cast<uint4*>(&BH[off]) = z4;
                *reinterpret_cast<uint4*>(&BL[off]) = z4;
            }
        }
        CP_COMMIT();
        CP_WAIT0();
        __syncthreads();

        int nsteps = (kcount + 15) / 16;
        for (int s = 0; s < nsteps; s++) {
            uint32_t bh[4][2], bl[4][2];
#pragma unroll
            for (int half = 0; half < 2; half++) {
                uint32_t off = (uint32_t)((s * 16 + (lane & 15)) * BSTR + wn * 32 +
                                          half * 16 + (lane >> 4) * 8);
                uint32_t r[4];
                ldsm_x4_t(r, &BH[off]);
                bh[half * 2][0] = r[0]; bh[half * 2][1] = r[1];
                bh[half * 2 + 1][0] = r[2]; bh[half * 2 + 1][1] = r[3];
                ldsm_x4_t(r, &BL[off]);
                bl[half * 2][0] = r[0]; bl[half * 2][1] = r[1];
                bl[half * 2 + 1][0] = r[2]; bl[half * 2 + 1][1] = r[3];
            }
#pragma unroll
            for (int mt = 0; mt < 4; mt++) {
                uint32_t off = (uint32_t)((wm * 64 + mt * 16 + (lane & 15)) * ASTR +
                                          s * 16 + (lane >> 4) * 8);
                uint32_t ah[4], al[4];
                ldsm_x4(ah, &AH[off]);
                ldsm_x4(al, &AL[off]);
#pragma unroll
                for (int nt = 0; nt < 4; nt++) {
                    mma16816(c[mt][nt], ah, bh[nt]);
                    mma16816(c[mt][nt], ah, bl[nt]);
                    mma16816(c[mt][nt], al, bh[nt]);
                }
            }
        }
        __syncthreads();
    }

    // ---- epilogue ----
#pragma unroll
    for (int mt = 0; mt < 4; mt++) {
#pragma unroll
        for (int nt = 0; nt < 4; nt++) {
            int col = wn * 32 + nt * 8 + (lane & 3) * 2;
            float bb0 = (b0 ? b0[col] : 0.f) + (b1 ? b1[col] : 0.f);
            float bb1 = (b0 ? b0[col + 1] : 0.f) + (b1 ? b1[col + 1] : 0.f);
#pragma unroll
            for (int h = 0; h < 2; h++) {
                int row = block_row + wm * 64 + mt * 16 + (lane >> 2) + h * 8;
                if (row >= M) continue;
                float r0 = (c[mt][nt][2 * h] + bb0) * scale;
                float r1 = (c[mt][nt][2 * h + 1] + bb1) * scale;
                if (do_act) {
                    r0 = r0 > 0.f ? r0 : 0.01f * r0;
                    r1 = r1 > 0.f ? r1 : 0.01f * r1;
                }
                if (Cf) {
                    *reinterpret_cast<float2*>(Cf + (size_t)row * HDIM + col) =
                        make_float2(r0, r1);
                } else {
                    uint32_t lp;
                    uint32_t hp = pack_hi2(r0, r1, &lp);
                    *reinterpret_cast<uint32_t*>(Ch + (size_t)row * HDIM + col) = hp;
                    *reinterpret_cast<uint32_t*>(Cl + (size_t)row * HDIM + col) = lp;
                }
            }
        }
    }
}

// final head: out[r,0:2] = h1[r,:] @ Wl[128,2] + bl
__global__ void head_kernel(const float* __restrict__ h1, const float* __restrict__ Wl,
                            const float* __restrict__ bl, float* __restrict__ out, int Nrows) {
    int warp = (blockIdx.x * blockDim.x + threadIdx.x) >> 5;
    int lane = threadIdx.x & 31;
    int nwarps = (gridDim.x * blockDim.x) >> 5;
    int k = lane * 4;
    float w00 = Wl[(k + 0) * 2], w01 = Wl[(k + 0) * 2 + 1];
    float w10 = Wl[(k + 1) * 2], w11 = Wl[(k + 1) * 2 + 1];
    float w20 = Wl[(k + 2) * 2], w21 = Wl[(k + 2) * 2 + 1];
    float w30 = Wl[(k + 3) * 2], w31 = Wl[(k + 3) * 2 + 1];
    for (int r = warp; r < Nrows; r += nwarps) {
        float4 v = *reinterpret_cast<const float4*>(h1 + (size_t)r * HDIM + k);
        float p0 = v.x * w00 + v.y * w10 + v.z * w20 + v.w * w30;
        float p1 = v.x * w01 + v.y * w11 + v.z * w21 + v.w * w31;
#pragma unroll
        for (int off = 16; off; off >>= 1) {
            p0 += __shfl_xor_sync(0xffffffffu, p0, off);
            p1 += __shfl_xor_sync(0xffffffffu, p1, off);
        }
        if (lane == 0) {
            out[(size_t)r * 2 + 0] = p0 + bl[0];
            out[(size_t)r * 2 + 1] = p1 + bl[1];
        }
    }
}

// ---------------------------------------------------------------------------
extern "C" void kernel_launch(void* const* d_in, const int* in_sizes, int n_in,
                              void* d_out, int out_size) {
    const float* x_user = (const float*)d_in[0];
    const float* x_news = (const float*)d_in[1];
    const float* x_source = (const float*)d_in[2];
    const float* x_follower = (const float*)d_in[3];
    const float* Wi1_user = (const float*)d_in[4];
    const float* bi1_user = (const float*)d_in[5];
    const float* Wi1_news = (const float*)d_in[6];
    const float* bi1_news = (const float*)d_in[7];
    const float* Wi1_source = (const float*)d_in[8];
    const float* bi1_source = (const float*)d_in[9];
    const float* Wi1_follower = (const float*)d_in[10];
    const float* bi1_follower = (const float*)d_in[11];
    const float* Wi2 = (const float*)d_in[12];
    const float* bi2 = (const float*)d_in[13];
    const float* conv1_W = (const float*)d_in[14];
    const float* conv1_b = (const float*)d_in[15];
    const float* conv2_W = (const float*)d_in[16];
    const float* conv2_b = (const float*)d_in[17];
    const float* Wl_user = (const float*)d_in[18];
    const float* bl_user = (const float*)d_in[19];
    const float* Wl_news = (const float*)d_in[20];
    const float* bl_news = (const float*)d_in[21];
    const float* Wl_source = (const float*)d_in[22];
    const float* bl_source = (const float*)d_in[23];
    const float* Wl_follower = (const float*)d_in[24];
    const float* bl_follower = (const float*)d_in[25];
    const int* posts_u = (const int*)d_in[26];
    const int* posts_n = (const int*)d_in[27];
    const int* pub_s = (const int*)d_in[28];
    const int* pub_n = (const int*)d_in[29];
    const int* fol_f = (const int*)d_in[30];
    const int* fol_u = (const int*)d_in[31];
    float* out = (float*)d_out;

    __nv_bfloat16 *pAh, *pAl, *pBh, *pBl, *aggh, *aggl, *wh, *wl;
    float* deg;
    int *cnt, *cur, *rp, *el;
    cudaGetSymbolAddress((void**)&pAh, g_pAh);
    cudaGetSymbolAddress((void**)&pAl, g_pAl);
    cudaGetSymbolAddress((void**)&pBh, g_pBh);
    cudaGetSymbolAddress((void**)&pBl, g_pBl);
    cudaGetSymbolAddress((void**)&aggh, g_aggh);
    cudaGetSymbolAddress((void**)&aggl, g_aggl);
    cudaGetSymbolAddress((void**)&wh, g_wh);
    cudaGetSymbolAddress((void**)&wl, g_wl);
    cudaGetSymbolAddress((void**)&deg, g_deg);
    cudaGetSymbolAddress((void**)&cnt, g_cnt);
    cudaGetSymbolAddress((void**)&cur, g_cur);
    cudaGetSymbolAddress((void**)&rp, g_rp);
    cudaGetSymbolAddress((void**)&el, g_el);

    cudaFuncSetAttribute(tgemm_kernel, cudaFuncAttributeMaxDynamicSharedMemorySize, SM_BYTES);

    // fp32-A GEMM (dense1): A raw, W planes
    auto gemmF = [&](const float* A, int lda, int woff, int K, const float* b,
                     __nv_bfloat16* Choi, __nv_bfloat16* Clo, int M) {
        tgemm_kernel<<<(M + 127) / 128, 256, SM_BYTES>>>(
            A, nullptr, nullptr, lda, wh + woff, wl + woff, nullptr, nullptr, K, K,
            b, nullptr, nullptr, Choi, Clo, M, 1.f, 1);
    };
    // split-A GEMM, one or two weight segments
    auto gemmS = [&](const __nv_bfloat16* Ahp, const __nv_bfloat16* Alp, int lda,
                     int woff0, int woff1, int K0, int K,
                     const float* b0, const float* b1,
                     float* Cf, __nv_bfloat16* Choi, __nv_bfloat16* Clo,
                     int M, float scale) {
        tgemm_kernel<<<(M + 127) / 128, 256, SM_BYTES>>>(
            nullptr, Ahp, Alp, lda, wh + woff0, wl + woff0,
            woff1 >= 0 ? wh + woff1 : nullptr, woff1 >= 0 ? wl + woff1 : nullptr, K0, K,
            b0, b1, Cf, Choi, Clo, M, scale, 1);
    };

    // ---- weight split (launch idx 0) ----
    wsplit_kernel<<<dim3(256, 7), 256>>>(Wi1_user, Wi1_news, Wi1_source, Wi1_follower,
                                         Wi2, conv1_W, conv2_W, wh, wl);

    // ---- dense layer 1 (idx 1-4): x -> pA planes ----
    gemmF(x_user, 128, WU1, 128, bi1_user, pAh + OFF_U, pAl + OFF_U, N_USER);
    gemmF(x_source, 128, WS1, 128, bi1_source, pAh + OFF_S, pAl + OFF_S, N_SOURCE);
    gemmF(x_follower, 128, WF1, 128, bi1_follower, pAh + OFF_F, pAl + OFF_F, N_FOLLOWER);
    gemmF(x_news, 300, WN1, 300, bi1_news, pAh + OFF_N, pAl + OFF_N, N_NEWS);

    // ---- dense layer 2 (idx 5-8; idx 5 = user M=200k split path for ncu) ----
    gemmS(pAh + OFF_U, pAl + OFF_U, 128, WI2 + 0 * 16384, -1, 128, 128,
          bi2 + 0 * HDIM, nullptr, nullptr, pBh + OFF_U, pBl + OFF_U, N_USER, 1.f);
    gemmS(pAh + OFF_F, pAl + OFF_F, 128, WI2 + 3 * 16384, -1, 128, 128,
          bi2 + 3 * HDIM, nullptr, nullptr, pBh + OFF_F, pBl + OFF_F, N_FOLLOWER, 1.f);
    gemmS(pAh + OFF_N, pAl + OFF_N, 128, WI2 + 1 * 16384, -1, 128, 128,
          bi2 + 1 * HDIM, nullptr, nullptr, pBh + OFF_N, pBl + OFF_N, N_NEWS, 1.f);
    gemmS(pAh + OFF_S, pAl + OFF_S, 128, WI2 + 2 * 16384, -1, 128, 128,
          bi2 + 2 * HDIM, nullptr, nullptr, pBh + OFF_S, pBl + OFF_S, N_SOURCE, 1.f);

    // ---- CSR build ----
    zero4_kernel<<<2048, 256>>>((float4*)cnt, DEG_TOTAL / 4);
    zero4_kernel<<<2048, 256>>>((float4*)cur, DEG_TOTAL / 4);
    counti_kernel<<<2048, 256>>>(posts_u, E_POSTS, cnt + DS_POSTS_U);
    counti_kernel<<<2048, 256>>>(posts_n, E_POSTS, cnt + DS_POSTS_N);
    counti_kernel<<<512, 256>>>(pub_s, E_PUB, cnt + DS_PUB_S);
    counti_kernel<<<512, 256>>>(pub_n, E_PUB, cnt + DS_PUB_N);
    counti_kernel<<<4096, 256>>>(fol_f, E_FOL, cnt + DS_FOL_F);
    counti_kernel<<<4096, 256>>>(fol_u, E_FOL, cnt + DS_FOL_U);
    rsqrt_cnt_kernel<<<2048, 256>>>(cnt, deg, DEG_TOTAL);
    scan6_kernel<<<6, 1024>>>(cnt, rp);
    fill_kernel<<<2048, 256>>>(posts_u, posts_n, E_POSTS, rp + RP0, cur + DS_POSTS_N, el + EL0);
    fill_kernel<<<2048, 256>>>(posts_n, posts_u, E_POSTS, rp + RP1, cur + DS_POSTS_U, el + EL1);
    fill_kernel<<<512, 256>>>(pub_s, pub_n, E_PUB, rp + RP2, cur + DS_PUB_N, el + EL2);
    fill_kernel<<<512, 256>>>(pub_n, pub_s, E_PUB, rp + RP3, cur + DS_PUB_S, el + EL3);
    fill_kernel<<<4096, 256>>>(fol_f, fol_u, E_FOL, rp + RP4, cur + DS_FOL_U, el + EL4);
    fill_kernel<<<4096, 256>>>(fol_u, fol_f, E_FOL, rp + RP5, cur + DS_FOL_F, el + EL5);

    auto gath = [&](const __nv_bfloat16* Hh, const __nv_bfloat16* Hl, size_t hoff,
                    int rpo, int elo, int rs_src, int rs_dst, int colofs, int n_dst) {
        gather_kernel<<<(n_dst + 7) / 8, 256>>>(Hh + hoff, Hl + hoff, rp + rpo, el + elo,
                                                deg + rs_src, deg + rs_dst, aggh, aggl,
                                                colofs, n_dst);
    };

    // ---- conv layers ----
    const size_t H1_BASE = (size_t)TOT_NODES * 2;
    float* h1_u = out + H1_BASE + OFF_U;
    float* h1_n = out + H1_BASE + OFF_N;
    float* h1_s = out + H1_BASE + OFF_S;
    float* h1_f = out + H1_BASE + OFF_F;

    for (int layer = 0; layer < 2; layer++) {
        const __nv_bfloat16* Hh = (layer == 0) ? pBh : pAh;
        const __nv_bfloat16* Hl = (layer == 0) ? pBl : pAl;
        int WC = (layer == 0) ? WC1 : WC2;
        const float* bc = (layer == 0) ? conv1_b : conv2_b;

        // user: r1 cols 0-127, r4 cols 128-255
        gath(Hh, Hl, OFF_N, RP1, EL1, DS_POSTS_N, DS_POSTS_U, 0, N_USER);
        gath(Hh, Hl, OFF_F, RP4, EL4, DS_FOL_F, DS_FOL_U, 128, N_USER);
        gemmS(aggh, aggl, 256, WC + (0 * 6 + 1) * 16384, WC + (0 * 6 + 4) * 16384, 128, 256,
              bc + (0 * 6 + 1) * HDIM, bc + (0 * 6 + 4) * HDIM,
              (layer == 0) ? nullptr : h1_u,
              (layer == 0) ? pAh + OFF_U : nullptr, (layer == 0) ? pAl + OFF_U : nullptr,
              N_USER, 0.5f);
        // news: r0 cols 0-127, r2 cols 128-255
        gath(Hh, Hl, OFF_U, RP0, EL0, DS_POSTS_U, DS_POSTS_N, 0, N_NEWS);
        gath(Hh, Hl, OFF_S, RP2, EL2, DS_PUB_S, DS_PUB_N, 128, N_NEWS);
        gemmS(aggh, aggl, 256, WC + (1 * 6 + 0) * 16384, WC + (1 * 6 + 2) * 16384, 128, 256,
              bc + (1 * 6 + 0) * HDIM, bc + (1 * 6 + 2) * HDIM,
              (layer == 0) ? nullptr : h1_n,
              (layer == 0) ? pAh + OFF_N : nullptr, (layer == 0) ? pAl + OFF_N : nullptr,
              N_NEWS, 0.5f);
        // source: r3 single relation
        gath(Hh, Hl, OFF_N, RP3, EL3, DS_PUB_N, DS_PUB_S, 0, N_SOURCE);
        gemmS(aggh, aggl, 256, WC + (2 * 6 + 3) * 16384, -1, 128, 128,
              bc + (2 * 6 + 3) * HDIM, nullptr,
              (layer == 0) ? nullptr : h1_s,
              (layer == 0) ? pAh + OFF_S : nullptr, (layer == 0) ? pAl + OFF_S : nullptr,
              N_SOURCE, 1.f);
        // follower: r5 single relation
        gath(Hh, Hl, OFF_U, RP5, EL5, DS_FOL_U, DS_FOL_F, 0, N_FOLLOWER);
        gemmS(aggh, aggl, 256, WC + (3 * 6 + 5) * 16384, -1, 128, 128,
              bc + (3 * 6 + 5) * HDIM, nullptr,
              (layer == 0) ? nullptr : h1_f,
              (layer == 0) ? pAh + OFF_F : nullptr, (layer == 0) ? pAl + OFF_F : nullptr,
              N_FOLLOWER, 1.f);
    }

    // ---- head ----
    float* out_u = out + 0;
    float* out_n = out + (size_t)N_USER * 2;
    float* out_s = out + (size_t)(N_USER + N_NEWS) * 2;
    float* out_f = out + (size_t)(N_USER + N_NEWS + N_SOURCE) * 2;
    head_kernel<<<(N_USER * 32 + 255) / 256, 256>>>(h1_u, Wl_user, bl_user, out_u, N_USER);
    head_kernel<<<(N_NEWS * 32 + 255) / 256, 256>>>(h1_n, Wl_news, bl_news, out_n, N_NEWS);
    head_kernel<<<(N_SOURCE * 32 + 255) / 256, 256>>>(h1_s, Wl_source, bl_source, out_s, N_SOURCE);
    head_kernel<<<(N_FOLLOWER * 32 + 255) / 256, 256>>>(h1_f, Wl_follower, bl_follower, out_f, N_FOLLOWER);
}

// round 13
// speedup vs baseline: 1.5875x; 1.0567x over previous
#include <cuda_runtime.h>
#include <cuda_bf16.h>
#include <cstdint>
#include <cstddef>

#define N_USER 200000
#define N_NEWS 100000
#define N_SOURCE 5000
#define N_FOLLOWER 200000
#define HDIM 128
#define E_POSTS 500000
#define E_PUB 100000
#define E_FOL 1000000

#define TOT_NODES (N_USER + N_NEWS + N_SOURCE + N_FOLLOWER)

#define OFF_U ((size_t)0)
#define OFF_N ((size_t)N_USER * HDIM)
#define OFF_S ((size_t)(N_USER + N_NEWS) * HDIM)
#define OFF_F ((size_t)(N_USER + N_NEWS + N_SOURCE) * HDIM)

#define DS_POSTS_U 0
#define DS_POSTS_N 200000
#define DS_PUB_S   300000
#define DS_PUB_N   305000
#define DS_FOL_F   405000
#define DS_FOL_U   605000
#define DEG_TOTAL  805000

#define RP0 0
#define RP1 100001
#define RP2 300002
#define RP3 400003
#define RP4 405004
#define RP5 605005
#define RP_TOTAL 805006

#define EL0 0
#define EL1 500000
#define EL2 1000000
#define EL3 1100000
#define EL4 1200000
#define EL5 2200000
#define EL_TOTAL 3200000

// weight-plane segment offsets (elements)
#define WU1 0
#define WN1 16384
#define WS1 54784
#define WF1 71168
#define WI2 87552
#define WC1 153088
#define WC2 546304
#define WTOT 939520

// split feature planes (bf16 hi/lo) + scratch
__device__ __nv_bfloat16 g_pAh[(size_t)TOT_NODES * HDIM];
__device__ __nv_bfloat16 g_pAl[(size_t)TOT_NODES * HDIM];
__device__ __nv_bfloat16 g_pBh[(size_t)TOT_NODES * HDIM];
__device__ __nv_bfloat16 g_pBl[(size_t)TOT_NODES * HDIM];
__device__ __nv_bfloat16 g_aggh[(size_t)N_USER * 256];
__device__ __nv_bfloat16 g_aggl[(size_t)N_USER * 256];
__device__ __nv_bfloat16 g_wh[WTOT];
__device__ __nv_bfloat16 g_wl[WTOT];
__device__ float g_deg[DEG_TOTAL];
__device__ int   g_cnt[DEG_TOTAL];
__device__ int   g_cur[DEG_TOTAL];
__device__ int   g_rp[RP_TOTAL];
__device__ int   g_el[EL_TOTAL];

// ---------------------------------------------------------------------------
__device__ __forceinline__ uint32_t pack_hi2(float a, float b, uint32_t* lo) {
    __nv_bfloat16 h0 = __float2bfloat16_rn(a);
    __nv_bfloat16 h1 = __float2bfloat16_rn(b);
    __nv_bfloat16 l0 = __float2bfloat16_rn(a - __bfloat162float(h0));
    __nv_bfloat16 l1 = __float2bfloat16_rn(b - __bfloat162float(h1));
    *lo = (uint32_t)__bfloat16_as_ushort(l0) | ((uint32_t)__bfloat16_as_ushort(l1) << 16);
    return (uint32_t)__bfloat16_as_ushort(h0) | ((uint32_t)__bfloat16_as_ushort(h1) << 16);
}
__device__ __forceinline__ float bflo(uint32_t u) { return __uint_as_float(u << 16); }
__device__ __forceinline__ float bfhi(uint32_t u) { return __uint_as_float(u & 0xffff0000u); }

// ---------------------------------------------------------------------------
__global__ void zero4_kernel(float4* __restrict__ p, size_t n4) {
    size_t i = (size_t)blockIdx.x * blockDim.x + threadIdx.x;
    size_t stride = (size_t)gridDim.x * blockDim.x;
    float4 z = make_float4(0.f, 0.f, 0.f, 0.f);
    for (; i < n4; i += stride) p[i] = z;
}

__global__ void wsplit_kernel(const float* __restrict__ wu, const float* __restrict__ wn,
                              const float* __restrict__ ws, const float* __restrict__ wf,
                              const float* __restrict__ wi2, const float* __restrict__ c1,
                              const float* __restrict__ c2,
                              __nv_bfloat16* __restrict__ wh, __nv_bfloat16* __restrict__ wl) {
    const float* src; int n; int off;
    switch (blockIdx.y) {
        case 0: src = wu;  n = 16384;  off = WU1; break;
        case 1: src = wn;  n = 38400;  off = WN1; break;
        case 2: src = ws;  n = 16384;  off = WS1; break;
        case 3: src = wf;  n = 16384;  off = WF1; break;
        case 4: src = wi2; n = 65536;  off = WI2; break;
        case 5: src = c1;  n = 393216; off = WC1; break;
        default: src = c2; n = 393216; off = WC2; break;
    }
    int stride = gridDim.x * blockDim.x;
    for (int i = blockIdx.x * blockDim.x + threadIdx.x; i < n; i += stride) {
        float x = src[i];
        __nv_bfloat16 h = __float2bfloat16_rn(x);
        wh[off + i] = h;
        wl[off + i] = __float2bfloat16_rn(x - __bfloat162float(h));
    }
}

__global__ void counti_kernel(const int* __restrict__ idx, int n, int* __restrict__ cnt) {
    int i = blockIdx.x * blockDim.x + threadIdx.x;
    int stride = gridDim.x * blockDim.x;
    for (; i < n; i += stride) atomicAdd(&cnt[idx[i]], 1);
}

__global__ void rsqrt_cnt_kernel(const int* __restrict__ cnt, float* __restrict__ deg, int n) {
    int i = blockIdx.x * blockDim.x + threadIdx.x;
    int stride = gridDim.x * blockDim.x;
    for (; i < n; i += stride) {
        int c = cnt[i];
        deg[i] = rsqrtf((float)(c < 1 ? 1 : c));
    }
}

__global__ __launch_bounds__(1024) void scan6_kernel(const int* __restrict__ cnt,
                                                     int* __restrict__ rp) {
    const int segs[6] = {DS_POSTS_N, DS_POSTS_U, DS_PUB_N, DS_PUB_S, DS_FOL_U, DS_FOL_F};
    const int ns[6]   = {N_NEWS, N_USER, N_NEWS, N_SOURCE, N_USER, N_FOLLOWER};
    const int rpo[6]  = {RP0, RP1, RP2, RP3, RP4, RP5};
    int r = blockIdx.x;
    const int* c = cnt + segs[r];
    int* out = rp + rpo[r];
    int n = ns[r];
    int tid = threadIdx.x;
    int lane = tid & 31;
    int wid = tid >> 5;
    __shared__ int wsum[32];
    __shared__ int carry;
    if (tid == 0) { carry = 0; out[0] = 0; }
    __syncthreads();
    for (int base = 0; base < n; base += 1024) {
        int v = (base + tid < n) ? c[base + tid] : 0;
        int x = v;
#pragma unroll
        for (int o = 1; o < 32; o <<= 1) {
            int y = __shfl_up_sync(0xffffffffu, x, o);
            if (lane >= o) x += y;
        }
        if (lane == 31) wsum[wid] = x;
        __syncthreads();
        if (wid == 0) {
            int s = wsum[lane];
#pragma unroll
            for (int o = 1; o < 32; o <<= 1) {
                int y = __shfl_up_sync(0xffffffffu, s, o);
                if (lane >= o) s += y;
            }
            wsum[lane] = s;
        }
        __syncthreads();
        int pre = (wid > 0) ? wsum[wid - 1] : 0;
        int incl = carry + pre + x;
        if (base + tid < n) out[base + tid + 1] = incl;
        __syncthreads();
        if (tid == 1023) carry = incl;
        __syncthreads();
    }
}

__global__ void fill_kernel(const int* __restrict__ src, const int* __restrict__ dst, int E,
                            const int* __restrict__ rp, int* __restrict__ cur,
                            int* __restrict__ el) {
    int i = blockIdx.x * blockDim.x + threadIdx.x;
    int stride = gridDim.x * blockDim.x;
    for (; i < E; i += stride) {
        int d = dst[i];
        int p = atomicAdd(&cur[d], 1);
        el[rp[d] + p] = src[i];
    }
}

__global__ void gather_kernel(const __nv_bfloat16* __restrict__ Hh,
                              const __nv_bfloat16* __restrict__ Hl,
                              const int* __restrict__ rp, const int* __restrict__ el,
                              const float* __restrict__ rs_src,
                              const float* __restrict__ rs_dst,
                              __nv_bfloat16* __restrict__ Ah, __nv_bfloat16* __restrict__ Al,
                              int colofs, int n_dst) {
    int warp = (blockIdx.x * blockDim.x + threadIdx.x) >> 5;
    int lane = threadIdx.x & 31;
    int nwarps = (gridDim.x * blockDim.x) >> 5;
    for (int row = warp; row < n_dst; row += nwarps) {
        int beg = rp[row], end = rp[row + 1];
        float a0 = 0.f, a1 = 0.f, a2 = 0.f, a3 = 0.f;
        for (int e = beg; e < end; e++) {
            int s = el[e];
            float sc = rs_src[s];
            const size_t base = (size_t)s * HDIM + lane * 4;
            uint2 vh = *reinterpret_cast<const uint2*>(Hh + base);
            uint2 vl = *reinterpret_cast<const uint2*>(Hl + base);
            a0 += sc * (bflo(vh.x) + bflo(vl.x));
            a1 += sc * (bfhi(vh.x) + bfhi(vl.x));
            a2 += sc * (bflo(vh.y) + bflo(vl.y));
            a3 += sc * (bfhi(vh.y) + bfhi(vl.y));
        }
        float ri = rs_dst[row];
        a0 *= ri; a1 *= ri; a2 *= ri; a3 *= ri;
        uint32_t lp0, lp1;
        uint32_t hp0 = pack_hi2(a0, a1, &lp0);
        uint32_t hp1 = pack_hi2(a2, a3, &lp1);
        size_t o = (size_t)row * 256 + colofs + lane * 4;
        *reinterpret_cast<uint2*>(Ah + o) = make_uint2(hp0, hp1);
        *reinterpret_cast<uint2*>(Al + o) = make_uint2(lp0, lp1);
    }
}

// ---------------------------------------------------------------------------
// bf16x3 HMMA GEMM. CTA tile 64(M) x 128(N), K-chunk 64, 52KB smem, 3 CTAs/SM.
// ---------------------------------------------------------------------------
#define ASTR 72
#define BSTR 136
#define SM_BYTES (2 * 64 * ASTR * 2 + 2 * 64 * BSTR * 2)  // 18432 + 34816 = 53248 B

#define CP_ASYNC16(smem, gptr) \
    asm volatile("cp.async.cg.shared.global [%0], [%1], 16;" :: "r"(smem), "l"(gptr))
#define CP_COMMIT() asm volatile("cp.async.commit_group;")
#define CP_WAIT0()  asm volatile("cp.async.wait_group 0;" ::: "memory")

__device__ __forceinline__ void mma16816(float* c, const uint32_t* a, const uint32_t* b) {
    asm volatile(
        "mma.sync.aligned.m16n8k16.row.col.f32.bf16.bf16.f32 "
        "{%0,%1,%2,%3}, {%4,%5,%6,%7}, {%8,%9}, {%0,%1,%2,%3};\n"
        : "+f"(c[0]), "+f"(c[1]), "+f"(c[2]), "+f"(c[3])
        : "r"(a[0]), "r"(a[1]), "r"(a[2]), "r"(a[3]), "r"(b[0]), "r"(b[1]));
}
__device__ __forceinline__ void ldsm_x4(uint32_t* r, const void* p) {
    uint32_t addr = (uint32_t)__cvta_generic_to_shared(p);
    asm volatile("ldmatrix.sync.aligned.m8n8.x4.shared.b16 {%0,%1,%2,%3}, [%4];"
                 : "=r"(r[0]), "=r"(r[1]), "=r"(r[2]), "=r"(r[3]) : "r"(addr));
}
__device__ __forceinline__ void ldsm_x4_t(uint32_t* r, const void* p) {
    uint32_t addr = (uint32_t)__cvta_generic_to_shared(p);
    asm volatile("ldmatrix.sync.aligned.m8n8.x4.trans.shared.b16 {%0,%1,%2,%3}, [%4];"
                 : "=r"(r[0]), "=r"(r[1]), "=r"(r[2]), "=r"(r[3]) : "r"(addr));
}

__global__ __launch_bounds__(256, 3) void tgemm_kernel(
    const float* __restrict__ Afp,
    const __nv_bfloat16* __restrict__ Ah, const __nv_bfloat16* __restrict__ Al, int lda,
    const __nv_bfloat16* __restrict__ Wh0, const __nv_bfloat16* __restrict__ Wl0,
    const __nv_bfloat16* __restrict__ Wh1, const __nv_bfloat16* __restrict__ Wl1,
    int K0, int K,
    const float* __restrict__ b0, const float* __restrict__ b1,
    float* __restrict__ Cf, __nv_bfloat16* __restrict__ Ch, __nv_bfloat16* __restrict__ Cl,
    int M, float scale, int do_act) {
    extern __shared__ __align__(16) char smraw[];
    __nv_bfloat16* AH = reinterpret_cast<__nv_bfloat16*>(smraw);
    __nv_bfloat16* AL = AH + 64 * ASTR;
    __nv_bfloat16* BH = AL + 64 * ASTR;
    __nv_bfloat16* BL = BH + 64 * BSTR;

    int tid = threadIdx.x;
    int lane = tid & 31;
    int warp = tid >> 5;
    int wm = warp & 1;   // 0..1 -> 32-row band
    int wn = warp >> 1;  // 0..3 -> 32-col band
    int block_row = blockIdx.x * 64;
    const uint4 z4 = make_uint4(0, 0, 0, 0);

    float c[2][4][4];
#pragma unroll
    for (int mt = 0; mt < 2; mt++)
#pragma unroll
        for (int nt = 0; nt < 4; nt++)
#pragma unroll
            for (int j = 0; j < 4; j++) c[mt][nt][j] = 0.f;

    for (int kbase = 0; kbase < K; kbase += 64) {
        int kcount = K - kbase; if (kcount > 64) kcount = 64;
        // ---- stage A chunk: 64 rows x 64 k ----
        if (Afp == nullptr) {
#pragma unroll
            for (int it = 0; it < 2; it++) {
                int idx = tid + it * 256;
                int row = idx >> 3;
                int kl = (idx & 7) * 8;
                int grow = block_row + row;
                int gk = kbase + kl;
                if (grow < M && gk < K) {
                    size_t go = (size_t)grow * lda + gk;
                    CP_ASYNC16((uint32_t)__cvta_generic_to_shared(&AH[row * ASTR + kl]), Ah + go);
                    CP_ASYNC16((uint32_t)__cvta_generic_to_shared(&AL[row * ASTR + kl]), Al + go);
                } else {
                    *reinterpret_cast<uint4*>(&AH[row * ASTR + kl]) = z4;
                    *reinterpret_cast<uint4*>(&AL[row * ASTR + kl]) = z4;
                }
            }
        } else {
#pragma unroll
            for (int it = 0; it < 2; it++) {
                int idx = tid + it * 256;
                int row = idx >> 3;
                int kl = (idx & 7) * 8;
                float v[8];
#pragma unroll
                for (int j = 0; j < 8; j++) v[j] = 0.f;
                int grow = block_row + row;
                int gk = kbase + kl;
                if (grow < M && gk < K) {
                    const float* ap = Afp + (size_t)grow * lda + gk;
                    if (gk + 7 < K) {
                        float4 v0 = *reinterpret_cast<const float4*>(ap);
                        float4 v1 = *reinterpret_cast<const float4*>(ap + 4);
                        v[0] = v0.x; v[1] = v0.y; v[2] = v0.z; v[3] = v0.w;
                        v[4] = v1.x; v[5] = v1.y; v[6] = v1.z; v[7] = v1.w;
                    } else {
#pragma unroll
                        for (int j = 0; j < 8; j++)
                            if (gk + j < K) v[j] = ap[j];
                    }
                }
                uint32_t hp[4], lp[4];
#pragma unroll
                for (int j = 0; j < 4; j++) hp[j] = pack_hi2(v[2 * j], v[2 * j + 1], &lp[j]);
                uint32_t off = (uint32_t)(row * ASTR + kl);
                *reinterpret_cast<uint4*>(&AH[off]) = make_uint4(hp[0], hp[1], hp[2], hp[3]);
                *reinterpret_cast<uint4*>(&AL[off]) = make_uint4(lp[0], lp[1], lp[2], lp[3]);
            }
        }
        // ---- stage W chunk: 64 k-rows x 128 n ----
#pragma unroll
        for (int it = 0; it < 4; it++) {
            int idx = tid + it * 256;
            int kr = idx >> 4;
            int nl = (idx & 15) * 8;
            int gk = kbase + kr;
            uint32_t off = (uint32_t)(kr * BSTR + nl);
            if (gk < K) {
                size_t go = (gk < K0) ? ((size_t)gk * HDIM + nl)
                                      : ((size_t)(gk - K0) * HDIM + nl);
                const __nv_bfloat16* sh = (gk < K0) ? Wh0 : Wh1;
                const __nv_bfloat16* sl = (gk < K0) ? Wl0 : Wl1;
                CP_ASYNC16((uint32_t)__cvta_generic_to_shared(&BH[off]), sh + go);
                CP_ASYNC16((uint32_t)__cvta_generic_to_shared(&BL[off]), sl + go);
            } else {
                *reinterpret_cast<uint4*>(&BH[off]) = z4;
                *reinterpret_cast<uint4*>(&BL[off]) = z4;
            }
        }
        CP_COMMIT();
        CP_WAIT0();
        __syncthreads();

        int nsteps = (kcount + 15) / 16;
#pragma unroll 4
        for (int s = 0; s < nsteps; s++) {
            uint32_t bh[4][2], bl[4][2];
#pragma unroll
            for (int half = 0; half < 2; half++) {
                uint32_t off = (uint32_t)((s * 16 + (lane & 15)) * BSTR + wn * 32 +
                                          half * 16 + (lane >> 4) * 8);
                uint32_t r[4];
                ldsm_x4_t(r, &BH[off]);
                bh[half * 2][0] = r[0]; bh[half * 2][1] = r[1];
                bh[half * 2 + 1][0] = r[2]; bh[half * 2 + 1][1] = r[3];
                ldsm_x4_t(r, &BL[off]);
                bl[half * 2][0] = r[0]; bl[half * 2][1] = r[1];
                bl[half * 2 + 1][0] = r[2]; bl[half * 2 + 1][1] = r[3];
            }
#pragma unroll
            for (int mt = 0; mt < 2; mt++) {
                uint32_t off = (uint32_t)((wm * 32 + mt * 16 + (lane & 15)) * ASTR +
                                          s * 16 + (lane >> 4) * 8);
                uint32_t ah[4], al[4];
                ldsm_x4(ah, &AH[off]);
                ldsm_x4(al, &AL[off]);
#pragma unroll
                for (int nt = 0; nt < 4; nt++) {
                    mma16816(c[mt][nt], ah, bh[nt]);
                    mma16816(c[mt][nt], ah, bl[nt]);
                    mma16816(c[mt][nt], al, bh[nt]);
                }
            }
        }
        __syncthreads();
    }

    // ---- epilogue ----
#pragma unroll
    for (int mt = 0; mt < 2; mt++) {
#pragma unroll
        for (int nt = 0; nt < 4; nt++) {
            int col = wn * 32 + nt * 8 + (lane & 3) * 2;
            float bb0 = (b0 ? b0[col] : 0.f) + (b1 ? b1[col] : 0.f);
            float bb1 = (b0 ? b0[col + 1] : 0.f) + (b1 ? b1[col + 1] : 0.f);
#pragma unroll
            for (int h = 0; h < 2; h++) {
                int row = block_row + wm * 32 + mt * 16 + (lane >> 2) + h * 8;
                if (row >= M) continue;
                float r0 = (c[mt][nt][2 * h] + bb0) * scale;
                float r1 = (c[mt][nt][2 * h + 1] + bb1) * scale;
                if (do_act) {
                    r0 = r0 > 0.f ? r0 : 0.01f * r0;
                    r1 = r1 > 0.f ? r1 : 0.01f * r1;
                }
                if (Cf) {
                    *reinterpret_cast<float2*>(Cf + (size_t)row * HDIM + col) =
                        make_float2(r0, r1);
                } else {
                    uint32_t lp;
                    uint32_t hp = pack_hi2(r0, r1, &lp);
                    *reinterpret_cast<uint32_t*>(Ch + (size_t)row * HDIM + col) = hp;
                    *reinterpret_cast<uint32_t*>(Cl + (size_t)row * HDIM + col) = lp;
                }
            }
        }
    }
}

// final head: out[r,0:2] = h1[r,:] @ Wl[128,2] + bl
__global__ void head_kernel(const float* __restrict__ h1, const float* __restrict__ Wl,
                            const float* __restrict__ bl, float* __restrict__ out, int Nrows) {
    int warp = (blockIdx.x * blockDim.x + threadIdx.x) >> 5;
    int lane = threadIdx.x & 31;
    int nwarps = (gridDim.x * blockDim.x) >> 5;
    int k = lane * 4;
    float w00 = Wl[(k + 0) * 2], w01 = Wl[(k + 0) * 2 + 1];
    float w10 = Wl[(k + 1) * 2], w11 = Wl[(k + 1) * 2 + 1];
    float w20 = Wl[(k + 2) * 2], w21 = Wl[(k + 2) * 2 + 1];
    float w30 = Wl[(k + 3) * 2], w31 = Wl[(k + 3) * 2 + 1];
    for (int r = warp; r < Nrows; r += nwarps) {
        float4 v = *reinterpret_cast<const float4*>(h1 + (size_t)r * HDIM + k);
        float p0 = v.x * w00 + v.y * w10 + v.z * w20 + v.w * w30;
        float p1 = v.x * w01 + v.y * w11 + v.z * w21 + v.w * w31;
#pragma unroll
        for (int off = 16; off; off >>= 1) {
            p0 += __shfl_xor_sync(0xffffffffu, p0, off);
            p1 += __shfl_xor_sync(0xffffffffu, p1, off);
        }
        if (lane == 0) {
            out[(size_t)r * 2 + 0] = p0 + bl[0];
            out[(size_t)r * 2 + 1] = p1 + bl[1];
        }
    }
}

// ---------------------------------------------------------------------------
extern "C" void kernel_launch(void* const* d_in, const int* in_sizes, int n_in,
                              void* d_out, int out_size) {
    const float* x_user = (const float*)d_in[0];
    const float* x_news = (const float*)d_in[1];
    const float* x_source = (const float*)d_in[2];
    const float* x_follower = (const float*)d_in[3];
    const float* Wi1_user = (const float*)d_in[4];
    const float* bi1_user = (const float*)d_in[5];
    const float* Wi1_news = (const float*)d_in[6];
    const float* bi1_news = (const float*)d_in[7];
    const float* Wi1_source = (const float*)d_in[8];
    const float* bi1_source = (const float*)d_in[9];
    const float* Wi1_follower = (const float*)d_in[10];
    const float* bi1_follower = (const float*)d_in[11];
    const float* Wi2 = (const float*)d_in[12];
    const float* bi2 = (const float*)d_in[13];
    const float* conv1_W = (const float*)d_in[14];
    const float* conv1_b = (const float*)d_in[15];
    const float* conv2_W = (const float*)d_in[16];
    const float* conv2_b = (const float*)d_in[17];
    const float* Wl_user = (const float*)d_in[18];
    const float* bl_user = (const float*)d_in[19];
    const float* Wl_news = (const float*)d_in[20];
    const float* bl_news = (const float*)d_in[21];
    const float* Wl_source = (const float*)d_in[22];
    const float* bl_source = (const float*)d_in[23];
    const float* Wl_follower = (const float*)d_in[24];
    const float* bl_follower = (const float*)d_in[25];
    const int* posts_u = (const int*)d_in[26];
    const int* posts_n = (const int*)d_in[27];
    const int* pub_s = (const int*)d_in[28];
    const int* pub_n = (const int*)d_in[29];
    const int* fol_f = (const int*)d_in[30];
    const int* fol_u = (const int*)d_in[31];
    float* out = (float*)d_out;

    __nv_bfloat16 *pAh, *pAl, *pBh, *pBl, *aggh, *aggl, *wh, *wl;
    float* deg;
    int *cnt, *cur, *rp, *el;
    cudaGetSymbolAddress((void**)&pAh, g_pAh);
    cudaGetSymbolAddress((void**)&pAl, g_pAl);
    cudaGetSymbolAddress((void**)&pBh, g_pBh);
    cudaGetSymbolAddress((void**)&pBl, g_pBl);
    cudaGetSymbolAddress((void**)&aggh, g_aggh);
    cudaGetSymbolAddress((void**)&aggl, g_aggl);
    cudaGetSymbolAddress((void**)&wh, g_wh);
    cudaGetSymbolAddress((void**)&wl, g_wl);
    cudaGetSymbolAddress((void**)&deg, g_deg);
    cudaGetSymbolAddress((void**)&cnt, g_cnt);
    cudaGetSymbolAddress((void**)&cur, g_cur);
    cudaGetSymbolAddress((void**)&rp, g_rp);
    cudaGetSymbolAddress((void**)&el, g_el);

    cudaFuncSetAttribute(tgemm_kernel, cudaFuncAttributeMaxDynamicSharedMemorySize, SM_BYTES);

    auto gemmF = [&](const float* A, int lda, int woff, int K, const float* b,
                     __nv_bfloat16* Choi, __nv_bfloat16* Clo, int M) {
        tgemm_kernel<<<(M + 63) / 64, 256, SM_BYTES>>>(
            A, nullptr, nullptr, lda, wh + woff, wl + woff, nullptr, nullptr, K, K,
            b, nullptr, nullptr, Choi, Clo, M, 1.f, 1);
    };
    auto gemmS = [&](const __nv_bfloat16* Ahp, const __nv_bfloat16* Alp, int lda,
                     int woff0, int woff1, int K0, int K,
                     const float* b0, const float* b1,
                     float* Cf, __nv_bfloat16* Choi, __nv_bfloat16* Clo,
                     int M, float scale) {
        tgemm_kernel<<<(M + 63) / 64, 256, SM_BYTES>>>(
            nullptr, Ahp, Alp, lda, wh + woff0, wl + woff0,
            woff1 >= 0 ? wh + woff1 : nullptr, woff1 >= 0 ? wl + woff1 : nullptr, K0, K,
            b0, b1, Cf, Choi, Clo, M, scale, 1);
    };

    // ---- weight split (launch idx 0) ----
    wsplit_kernel<<<dim3(256, 7), 256>>>(Wi1_user, Wi1_news, Wi1_source, Wi1_follower,
                                         Wi2, conv1_W, conv2_W, wh, wl);

    // ---- dense layer 1 (idx 1-4): x -> pA planes ----
    gemmF(x_user, 128, WU1, 128, bi1_user, pAh + OFF_U, pAl + OFF_U, N_USER);
    gemmF(x_source, 128, WS1, 128, bi1_source, pAh + OFF_S, pAl + OFF_S, N_SOURCE);
    gemmF(x_follower, 128, WF1, 128, bi1_follower, pAh + OFF_F, pAl + OFF_F, N_FOLLOWER);
    gemmF(x_news, 300, WN1, 300, bi1_news, pAh + OFF_N, pAl + OFF_N, N_NEWS);

    // ---- dense layer 2 (idx 5-8; idx 5 = user M=200k split path for ncu) ----
    gemmS(pAh + OFF_U, pAl + OFF_U, 128, WI2 + 0 * 16384, -1, 128, 128,
          bi2 + 0 * HDIM, nullptr, nullptr, pBh + OFF_U, pBl + OFF_U, N_USER, 1.f);
    gemmS(pAh + OFF_F, pAl + OFF_F, 128, WI2 + 3 * 16384, -1, 128, 128,
          bi2 + 3 * HDIM, nullptr, nullptr, pBh + OFF_F, pBl + OFF_F, N_FOLLOWER, 1.f);
    gemmS(pAh + OFF_N, pAl + OFF_N, 128, WI2 + 1 * 16384, -1, 128, 128,
          bi2 + 1 * HDIM, nullptr, nullptr, pBh + OFF_N, pBl + OFF_N, N_NEWS, 1.f);
    gemmS(pAh + OFF_S, pAl + OFF_S, 128, WI2 + 2 * 16384, -1, 128, 128,
          bi2 + 2 * HDIM, nullptr, nullptr, pBh + OFF_S, pBl + OFF_S, N_SOURCE, 1.f);

    // ---- CSR build ----
    zero4_kernel<<<2048, 256>>>((float4*)cnt, DEG_TOTAL / 4);
    zero4_kernel<<<2048, 256>>>((float4*)cur, DEG_TOTAL / 4);
    counti_kernel<<<2048, 256>>>(posts_u, E_POSTS, cnt + DS_POSTS_U);
    counti_kernel<<<2048, 256>>>(posts_n, E_POSTS, cnt + DS_POSTS_N);
    counti_kernel<<<512, 256>>>(pub_s, E_PUB, cnt + DS_PUB_S);
    counti_kernel<<<512, 256>>>(pub_n, E_PUB, cnt + DS_PUB_N);
    counti_kernel<<<4096, 256>>>(fol_f, E_FOL, cnt + DS_FOL_F);
    counti_kernel<<<4096, 256>>>(fol_u, E_FOL, cnt + DS_FOL_U);
    rsqrt_cnt_kernel<<<2048, 256>>>(cnt, deg, DEG_TOTAL);
    scan6_kernel<<<6, 1024>>>(cnt, rp);
    fill_kernel<<<2048, 256>>>(posts_u, posts_n, E_POSTS, rp + RP0, cur + DS_POSTS_N, el + EL0);
    fill_kernel<<<2048, 256>>>(posts_n, posts_u, E_POSTS, rp + RP1, cur + DS_POSTS_U, el + EL1);
    fill_kernel<<<512, 256>>>(pub_s, pub_n, E_PUB, rp + RP2, cur + DS_PUB_N, el + EL2);
    fill_kernel<<<512, 256>>>(pub_n, pub_s, E_PUB, rp + RP3, cur + DS_PUB_S, el + EL3);
    fill_kernel<<<4096, 256>>>(fol_f, fol_u, E_FOL, rp + RP4, cur + DS_FOL_U, el + EL4);
    fill_kernel<<<4096, 256>>>(fol_u, fol_f, E_FOL, rp + RP5, cur + DS_FOL_F, el + EL5);

    auto gath = [&](const __nv_bfloat16* Hh, const __nv_bfloat16* Hl, size_t hoff,
                    int rpo, int elo, int rs_src, int rs_dst, int colofs, int n_dst) {
        gather_kernel<<<(n_dst + 7) / 8, 256>>>(Hh + hoff, Hl + hoff, rp + rpo, el + elo,
                                                deg + rs_src, deg + rs_dst, aggh, aggl,
                                                colofs, n_dst);
    };

    // ---- conv layers ----
    const size_t H1_BASE = (size_t)TOT_NODES * 2;
    float* h1_u = out + H1_BASE + OFF_U;
    float* h1_n = out + H1_BASE + OFF_N;
    float* h1_s = out + H1_BASE + OFF_S;
    float* h1_f = out + H1_BASE + OFF_F;

    for (int layer = 0; layer < 2; layer++) {
        const __nv_bfloat16* Hh = (layer == 0) ? pBh : pAh;
        const __nv_bfloat16* Hl = (layer == 0) ? pBl : pAl;
        int WC = (layer == 0) ? WC1 : WC2;
        const float* bc = (layer == 0) ? conv1_b : conv2_b;

        gath(Hh, Hl, OFF_N, RP1, EL1, DS_POSTS_N, DS_POSTS_U, 0, N_USER);
        gath(Hh, Hl, OFF_F, RP4, EL4, DS_FOL_F, DS_FOL_U, 128, N_USER);
        gemmS(aggh, aggl, 256, WC + (0 * 6 + 1) * 16384, WC + (0 * 6 + 4) * 16384, 128, 256,
              bc + (0 * 6 + 1) * HDIM, bc + (0 * 6 + 4) * HDIM,
              (layer == 0) ? nullptr : h1_u,
              (layer == 0) ? pAh + OFF_U : nullptr, (layer == 0) ? pAl + OFF_U : nullptr,
              N_USER, 0.5f);
        gath(Hh, Hl, OFF_U, RP0, EL0, DS_POSTS_U, DS_POSTS_N, 0, N_NEWS);
        gath(Hh, Hl, OFF_S, RP2, EL2, DS_PUB_S, DS_PUB_N, 128, N_NEWS);
        gemmS(aggh, aggl, 256, WC + (1 * 6 + 0) * 16384, WC + (1 * 6 + 2) * 16384, 128, 256,
              bc + (1 * 6 + 0) * HDIM, bc + (1 * 6 + 2) * HDIM,
              (layer == 0) ? nullptr : h1_n,
              (layer == 0) ? pAh + OFF_N : nullptr, (layer == 0) ? pAl + OFF_N : nullptr,
              N_NEWS, 0.5f);
        gath(Hh, Hl, OFF_N, RP3, EL3, DS_PUB_N, DS_PUB_S, 0, N_SOURCE);
        gemmS(aggh, aggl, 256, WC + (2 * 6 + 3) * 16384, -1, 128, 128,
              bc + (2 * 6 + 3) * HDIM, nullptr,
              (layer == 0) ? nullptr : h1_s,
              (layer == 0) ? pAh + OFF_S : nullptr, (layer == 0) ? pAl + OFF_S : nullptr,
              N_SOURCE, 1.f);
        gath(Hh, Hl, OFF_U, RP5, EL5, DS_FOL_U, DS_FOL_F, 0, N_FOLLOWER);
        gemmS(aggh, aggl, 256, WC + (3 * 6 + 5) * 16384, -1, 128, 128,
              bc + (3 * 6 + 5) * HDIM, nullptr,
              (layer == 0) ? nullptr : h1_f,
              (layer == 0) ? pAh + OFF_F : nullptr, (layer == 0) ? pAl + OFF_F : nullptr,
              N_FOLLOWER, 1.f);
    }

    // ---- head ----
    float* out_u = out + 0;
    float* out_n = out + (size_t)N_USER * 2;
    float* out_s = out + (size_t)(N_USER + N_NEWS) * 2;
    float* out_f = out + (size_t)(N_USER + N_NEWS + N_SOURCE) * 2;
    head_kernel<<<(N_USER * 32 + 255) / 256, 256>>>(h1_u, Wl_user, bl_user, out_u, N_USER);
    head_kernel<<<(N_NEWS * 32 + 255) / 256, 256>>>(h1_n, Wl_news, bl_news, out_n, N_NEWS);
    head_kernel<<<(N_SOURCE * 32 + 255) / 256, 256>>>(h1_s, Wl_source, bl_source, out_s, N_SOURCE);
    head_kernel<<<(N_FOLLOWER * 32 + 255) / 256, 256>>>(h1_f, Wl_follower, bl_follower, out_f, N_FOLLOWER);
}

// round 14
// speedup vs baseline: 1.6177x; 1.0191x over previous
#include <cuda_runtime.h>
#include <cuda_bf16.h>
#include <cstdint>
#include <cstddef>

#define N_USER 200000
#define N_NEWS 100000
#define N_SOURCE 5000
#define N_FOLLOWER 200000
#define HDIM 128
#define E_POSTS 500000
#define E_PUB 100000
#define E_FOL 1000000

#define TOT_NODES (N_USER + N_NEWS + N_SOURCE + N_FOLLOWER)

#define OFF_U ((size_t)0)
#define OFF_N ((size_t)N_USER * HDIM)
#define OFF_S ((size_t)(N_USER + N_NEWS) * HDIM)
#define OFF_F ((size_t)(N_USER + N_NEWS + N_SOURCE) * HDIM)

#define DS_POSTS_U 0
#define DS_POSTS_N 200000
#define DS_PUB_S   300000
#define DS_PUB_N   305000
#define DS_FOL_F   405000
#define DS_FOL_U   605000
#define DEG_TOTAL  805000

#define RP0 0
#define RP1 100001
#define RP2 300002
#define RP3 400003
#define RP4 405004
#define RP5 605005
#define RP_TOTAL 805006

#define EL0 0
#define EL1 500000
#define EL2 1000000
#define EL3 1100000
#define EL4 1200000
#define EL5 2200000
#define EL_TOTAL 3200000

// weight-plane segment offsets (elements)
#define WU1 0
#define WN1 16384
#define WS1 54784
#define WF1 71168
#define WI2 87552
#define WC1 153088
#define WC2 546304
#define WTOT 939520

// split feature planes (bf16 hi/lo) + scratch
__device__ __nv_bfloat16 g_pAh[(size_t)TOT_NODES * HDIM];
__device__ __nv_bfloat16 g_pAl[(size_t)TOT_NODES * HDIM];
__device__ __nv_bfloat16 g_pBh[(size_t)TOT_NODES * HDIM];
__device__ __nv_bfloat16 g_pBl[(size_t)TOT_NODES * HDIM];
__device__ __nv_bfloat16 g_aggh[(size_t)N_USER * 256];
__device__ __nv_bfloat16 g_aggl[(size_t)N_USER * 256];
__device__ __nv_bfloat16 g_wh[WTOT];
__device__ __nv_bfloat16 g_wl[WTOT];
__device__ float g_deg[DEG_TOTAL];
__device__ int   g_cnt[DEG_TOTAL];
__device__ int   g_cur[DEG_TOTAL];
__device__ int   g_rp[RP_TOTAL];
__device__ int   g_el[EL_TOTAL];

// ---------------------------------------------------------------------------
__device__ __forceinline__ uint32_t pack_hi2(float a, float b, uint32_t* lo) {
    __nv_bfloat16 h0 = __float2bfloat16_rn(a);
    __nv_bfloat16 h1 = __float2bfloat16_rn(b);
    __nv_bfloat16 l0 = __float2bfloat16_rn(a - __bfloat162float(h0));
    __nv_bfloat16 l1 = __float2bfloat16_rn(b - __bfloat162float(h1));
    *lo = (uint32_t)__bfloat16_as_ushort(l0) | ((uint32_t)__bfloat16_as_ushort(l1) << 16);
    return (uint32_t)__bfloat16_as_ushort(h0) | ((uint32_t)__bfloat16_as_ushort(h1) << 16);
}
__device__ __forceinline__ float bflo(uint32_t u) { return __uint_as_float(u << 16); }
__device__ __forceinline__ float bfhi(uint32_t u) { return __uint_as_float(u & 0xffff0000u); }

// ---------------------------------------------------------------------------
__global__ void zero4_kernel(float4* __restrict__ p, size_t n4) {
    size_t i = (size_t)blockIdx.x * blockDim.x + threadIdx.x;
    size_t stride = (size_t)gridDim.x * blockDim.x;
    float4 z = make_float4(0.f, 0.f, 0.f, 0.f);
    for (; i < n4; i += stride) p[i] = z;
}

__global__ void wsplit_kernel(const float* __restrict__ wu, const float* __restrict__ wn,
                              const float* __restrict__ ws, const float* __restrict__ wf,
                              const float* __restrict__ wi2, const float* __restrict__ c1,
                              const float* __restrict__ c2,
                              __nv_bfloat16* __restrict__ wh, __nv_bfloat16* __restrict__ wl) {
    const float* src; int n; int off;
    switch (blockIdx.y) {
        case 0: src = wu;  n = 16384;  off = WU1; break;
        case 1: src = wn;  n = 38400;  off = WN1; break;
        case 2: src = ws;  n = 16384;  off = WS1; break;
        case 3: src = wf;  n = 16384;  off = WF1; break;
        case 4: src = wi2; n = 65536;  off = WI2; break;
        case 5: src = c1;  n = 393216; off = WC1; break;
        default: src = c2; n = 393216; off = WC2; break;
    }
    int stride = gridDim.x * blockDim.x;
    for (int i = blockIdx.x * blockDim.x + threadIdx.x; i < n; i += stride) {
        float x = src[i];
        __nv_bfloat16 h = __float2bfloat16_rn(x);
        wh[off + i] = h;
        wl[off + i] = __float2bfloat16_rn(x - __bfloat162float(h));
    }
}

__global__ void counti_kernel(const int* __restrict__ idx, int n, int* __restrict__ cnt) {
    int i = blockIdx.x * blockDim.x + threadIdx.x;
    int stride = gridDim.x * blockDim.x;
    for (; i < n; i += stride) atomicAdd(&cnt[idx[i]], 1);
}

__global__ void rsqrt_cnt_kernel(const int* __restrict__ cnt, float* __restrict__ deg, int n) {
    int i = blockIdx.x * blockDim.x + threadIdx.x;
    int stride = gridDim.x * blockDim.x;
    for (; i < n; i += stride) {
        int c = cnt[i];
        deg[i] = rsqrtf((float)(c < 1 ? 1 : c));
    }
}

__global__ __launch_bounds__(1024) void scan6_kernel(const int* __restrict__ cnt,
                                                     int* __restrict__ rp) {
    const int segs[6] = {DS_POSTS_N, DS_POSTS_U, DS_PUB_N, DS_PUB_S, DS_FOL_U, DS_FOL_F};
    const int ns[6]   = {N_NEWS, N_USER, N_NEWS, N_SOURCE, N_USER, N_FOLLOWER};
    const int rpo[6]  = {RP0, RP1, RP2, RP3, RP4, RP5};
    int r = blockIdx.x;
    const int* c = cnt + segs[r];
    int* out = rp + rpo[r];
    int n = ns[r];
    int tid = threadIdx.x;
    int lane = tid & 31;
    int wid = tid >> 5;
    __shared__ int wsum[32];
    __shared__ int carry;
    if (tid == 0) { carry = 0; out[0] = 0; }
    __syncthreads();
    for (int base = 0; base < n; base += 1024) {
        int v = (base + tid < n) ? c[base + tid] : 0;
        int x = v;
#pragma unroll
        for (int o = 1; o < 32; o <<= 1) {
            int y = __shfl_up_sync(0xffffffffu, x, o);
            if (lane >= o) x += y;
        }
        if (lane == 31) wsum[wid] = x;
        __syncthreads();
        if (wid == 0) {
            int s = wsum[lane];
#pragma unroll
            for (int o = 1; o < 32; o <<= 1) {
                int y = __shfl_up_sync(0xffffffffu, s, o);
                if (lane >= o) s += y;
            }
            wsum[lane] = s;
        }
        __syncthreads();
        int pre = (wid > 0) ? wsum[wid - 1] : 0;
        int incl = carry + pre + x;
        if (base + tid < n) out[base + tid + 1] = incl;
        __syncthreads();
        if (tid == 1023) carry = incl;
        __syncthreads();
    }
}

__global__ void fill_kernel(const int* __restrict__ src, const int* __restrict__ dst, int E,
                            const int* __restrict__ rp, int* __restrict__ cur,
                            int* __restrict__ el) {
    int i = blockIdx.x * blockDim.x + threadIdx.x;
    int stride = gridDim.x * blockDim.x;
    for (; i < E; i += stride) {
        int d = dst[i];
        int p = atomicAdd(&cur[d], 1);
        el[rp[d] + p] = src[i];
    }
}

__global__ void gather_kernel(const __nv_bfloat16* __restrict__ Hh,
                              const __nv_bfloat16* __restrict__ Hl,
                              const int* __restrict__ rp, const int* __restrict__ el,
                              const float* __restrict__ rs_src,
                              const float* __restrict__ rs_dst,
                              __nv_bfloat16* __restrict__ Ah, __nv_bfloat16* __restrict__ Al,
                              int colofs, int n_dst) {
    int warp = (blockIdx.x * blockDim.x + threadIdx.x) >> 5;
    int lane = threadIdx.x & 31;
    int nwarps = (gridDim.x * blockDim.x) >> 5;
    for (int row = warp; row < n_dst; row += nwarps) {
        int beg = rp[row], end = rp[row + 1];
        float a0 = 0.f, a1 = 0.f, a2 = 0.f, a3 = 0.f;
        for (int e = beg; e < end; e++) {
            int s = el[e];
            float sc = rs_src[s];
            const size_t base = (size_t)s * HDIM + lane * 4;
            uint2 vh = *reinterpret_cast<const uint2*>(Hh + base);
            uint2 vl = *reinterpret_cast<const uint2*>(Hl + base);
            a0 += sc * (bflo(vh.x) + bflo(vl.x));
            a1 += sc * (bfhi(vh.x) + bfhi(vl.x));
            a2 += sc * (bflo(vh.y) + bflo(vl.y));
            a3 += sc * (bfhi(vh.y) + bfhi(vl.y));
        }
        float ri = rs_dst[row];
        a0 *= ri; a1 *= ri; a2 *= ri; a3 *= ri;
        uint32_t lp0, lp1;
        uint32_t hp0 = pack_hi2(a0, a1, &lp0);
        uint32_t hp1 = pack_hi2(a2, a3, &lp1);
        size_t o = (size_t)row * 256 + colofs + lane * 4;
        *reinterpret_cast<uint2*>(Ah + o) = make_uint2(hp0, hp1);
        *reinterpret_cast<uint2*>(Al + o) = make_uint2(lp0, lp1);
    }
}

// ---------------------------------------------------------------------------
// bf16x3 HMMA GEMM. CTA tile 64(M) x 128(N), K-chunk 64, 52KB smem, 4 CTAs/SM.
// ---------------------------------------------------------------------------
#define ASTR 72
#define BSTR 136
#define SM_BYTES (2 * 64 * ASTR * 2 + 2 * 64 * BSTR * 2)  // 53248 B

#define CP_ASYNC16(smem, gptr) \
    asm volatile("cp.async.cg.shared.global [%0], [%1], 16;" :: "r"(smem), "l"(gptr))
#define CP_COMMIT() asm volatile("cp.async.commit_group;")
#define CP_WAIT0()  asm volatile("cp.async.wait_group 0;" ::: "memory")

__device__ __forceinline__ void mma16816(float* c, const uint32_t* a, const uint32_t* b) {
    asm volatile(
        "mma.sync.aligned.m16n8k16.row.col.f32.bf16.bf16.f32 "
        "{%0,%1,%2,%3}, {%4,%5,%6,%7}, {%8,%9}, {%0,%1,%2,%3};\n"
        : "+f"(c[0]), "+f"(c[1]), "+f"(c[2]), "+f"(c[3])
        : "r"(a[0]), "r"(a[1]), "r"(a[2]), "r"(a[3]), "r"(b[0]), "r"(b[1]));
}
__device__ __forceinline__ void ldsm_x4(uint32_t* r, uint32_t addr) {
    asm volatile("ldmatrix.sync.aligned.m8n8.x4.shared.b16 {%0,%1,%2,%3}, [%4];"
                 : "=r"(r[0]), "=r"(r[1]), "=r"(r[2]), "=r"(r[3]) : "r"(addr));
}
__device__ __forceinline__ void ldsm_x4_t(uint32_t* r, uint32_t addr) {
    asm volatile("ldmatrix.sync.aligned.m8n8.x4.trans.shared.b16 {%0,%1,%2,%3}, [%4];"
                 : "=r"(r[0]), "=r"(r[1]), "=r"(r[2]), "=r"(r[3]) : "r"(addr));
}

__global__ __launch_bounds__(256, 4) void tgemm_kernel(
    const float* __restrict__ Afp,
    const __nv_bfloat16* __restrict__ Ah, const __nv_bfloat16* __restrict__ Al, int lda,
    const __nv_bfloat16* __restrict__ Wh0, const __nv_bfloat16* __restrict__ Wl0,
    const __nv_bfloat16* __restrict__ Wh1, const __nv_bfloat16* __restrict__ Wl1,
    int K0, int K,
    const float* __restrict__ b0, const float* __restrict__ b1,
    float* __restrict__ Cf, __nv_bfloat16* __restrict__ Ch, __nv_bfloat16* __restrict__ Cl,
    int M, float scale, int do_act) {
    extern __shared__ __align__(16) char smraw[];
    __nv_bfloat16* AH = reinterpret_cast<__nv_bfloat16*>(smraw);
    __nv_bfloat16* AL = AH + 64 * ASTR;
    __nv_bfloat16* BH = AL + 64 * ASTR;
    __nv_bfloat16* BL = BH + 64 * BSTR;

    int tid = threadIdx.x;
    int lane = tid & 31;
    int warp = tid >> 5;
    int wm = warp & 1;
    int wn = warp >> 1;
    int block_row = blockIdx.x * 64;
    const uint4 z4 = make_uint4(0, 0, 0, 0);

    // invariant ldsm base addresses (hoisted out of loops)
    uint32_t aBaseH = (uint32_t)__cvta_generic_to_shared(
        &AH[(wm * 32 + (lane & 15)) * ASTR + (lane >> 4) * 8]);
    uint32_t aBaseL = aBaseH + 64 * ASTR * 2;
    uint32_t bBaseH = (uint32_t)__cvta_generic_to_shared(
        &BH[(lane & 15) * BSTR + wn * 32 + (lane >> 4) * 8]);
    uint32_t bBaseL = bBaseH + 64 * BSTR * 2;

    float c[2][4][4];
#pragma unroll
    for (int mt = 0; mt < 2; mt++)
#pragma unroll
        for (int nt = 0; nt < 4; nt++)
#pragma unroll
            for (int j = 0; j < 4; j++) c[mt][nt][j] = 0.f;

    for (int kbase = 0; kbase < K; kbase += 64) {
        int kcount = K - kbase; if (kcount > 64) kcount = 64;
        // ---- stage A chunk: 64 rows x 64 k ----
        if (Afp == nullptr) {
#pragma unroll
            for (int it = 0; it < 2; it++) {
                int idx = tid + it * 256;
                int row = idx >> 3;
                int kl = (idx & 7) * 8;
                int grow = block_row + row;
                int gk = kbase + kl;
                if (grow < M && gk < K) {
                    size_t go = (size_t)grow * lda + gk;
                    CP_ASYNC16((uint32_t)__cvta_generic_to_shared(&AH[row * ASTR + kl]), Ah + go);
                    CP_ASYNC16((uint32_t)__cvta_generic_to_shared(&AL[row * ASTR + kl]), Al + go);
                } else {
                    *reinterpret_cast<uint4*>(&AH[row * ASTR + kl]) = z4;
                    *reinterpret_cast<uint4*>(&AL[row * ASTR + kl]) = z4;
                }
            }
        } else {
#pragma unroll
            for (int it = 0; it < 2; it++) {
                int idx = tid + it * 256;
                int row = idx >> 3;
                int kl = (idx & 7) * 8;
                float v[8];
#pragma unroll
                for (int j = 0; j < 8; j++) v[j] = 0.f;
                int grow = block_row + row;
                int gk = kbase + kl;
                if (grow < M && gk < K) {
                    const float* ap = Afp + (size_t)grow * lda + gk;
                    if (gk + 7 < K) {
                        float4 v0 = *reinterpret_cast<const float4*>(ap);
                        float4 v1 = *reinterpret_cast<const float4*>(ap + 4);
                        v[0] = v0.x; v[1] = v0.y; v[2] = v0.z; v[3] = v0.w;
                        v[4] = v1.x; v[5] = v1.y; v[6] = v1.z; v[7] = v1.w;
                    } else {
#pragma unroll
                        for (int j = 0; j < 8; j++)
                            if (gk + j < K) v[j] = ap[j];
                    }
                }
                uint32_t hp[4], lp[4];
#pragma unroll
                for (int j = 0; j < 4; j++) hp[j] = pack_hi2(v[2 * j], v[2 * j + 1], &lp[j]);
                uint32_t off = (uint32_t)(row * ASTR + kl);
                *reinterpret_cast<uint4*>(&AH[off]) = make_uint4(hp[0], hp[1], hp[2], hp[3]);
                *reinterpret_cast<uint4*>(&AL[off]) = make_uint4(lp[0], lp[1], lp[2], lp[3]);
            }
        }
        // ---- stage W chunk: 64 k-rows x 128 n ----
#pragma unroll
        for (int it = 0; it < 4; it++) {
            int idx = tid + it * 256;
            int kr = idx >> 4;
            int nl = (idx & 15) * 8;
            int gk = kbase + kr;
            uint32_t off = (uint32_t)(kr * BSTR + nl);
            if (gk < K) {
                size_t go = (gk < K0) ? ((size_t)gk * HDIM + nl)
                                      : ((size_t)(gk - K0) * HDIM + nl);
                const __nv_bfloat16* sh = (gk < K0) ? Wh0 : Wh1;
                const __nv_bfloat16* sl = (gk < K0) ? Wl0 : Wl1;
                CP_ASYNC16((uint32_t)__cvta_generic_to_shared(&BH[off]), sh + go);
                CP_ASYNC16((uint32_t)__cvta_generic_to_shared(&BL[off]), sl + go);
            } else {
                *reinterpret_cast<uint4*>(&BH[off]) = z4;
                *reinterpret_cast<uint4*>(&BL[off]) = z4;
            }
        }
        CP_COMMIT();
        CP_WAIT0();
        __syncthreads();

        int nsteps = (kcount + 15) / 16;
#pragma unroll 4
        for (int s = 0; s < nsteps; s++) {
            uint32_t bh[4][2], bl[4][2];
#pragma unroll
            for (int half = 0; half < 2; half++) {
                uint32_t off = (uint32_t)(s * 16 * BSTR + half * 16) * 2;
                uint32_t r[4];
                ldsm_x4_t(r, bBaseH + off);
                bh[half * 2][0] = r[0]; bh[half * 2][1] = r[1];
                bh[half * 2 + 1][0] = r[2]; bh[half * 2 + 1][1] = r[3];
                ldsm_x4_t(r, bBaseL + off);
                bl[half * 2][0] = r[0]; bl[half * 2][1] = r[1];
                bl[half * 2 + 1][0] = r[2]; bl[half * 2 + 1][1] = r[3];
            }
#pragma unroll
            for (int mt = 0; mt < 2; mt++) {
                uint32_t off = (uint32_t)(mt * 16 * ASTR + s * 16) * 2;
                uint32_t ah[4], al[4];
                ldsm_x4(ah, aBaseH + off);
                ldsm_x4(al, aBaseL + off);
#pragma unroll
                for (int nt = 0; nt < 4; nt++) {
                    mma16816(c[mt][nt], ah, bh[nt]);
                    mma16816(c[mt][nt], ah, bl[nt]);
                    mma16816(c[mt][nt], al, bh[nt]);
                }
            }
        }
        __syncthreads();
    }

    // ---- epilogue ----
#pragma unroll
    for (int mt = 0; mt < 2; mt++) {
#pragma unroll
        for (int nt = 0; nt < 4; nt++) {
            int col = wn * 32 + nt * 8 + (lane & 3) * 2;
            float bb0 = (b0 ? b0[col] : 0.f) + (b1 ? b1[col] : 0.f);
            float bb1 = (b0 ? b0[col + 1] : 0.f) + (b1 ? b1[col + 1] : 0.f);
#pragma unroll
            for (int h = 0; h < 2; h++) {
                int row = block_row + wm * 32 + mt * 16 + (lane >> 2) + h * 8;
                if (row >= M) continue;
                float r0 = (c[mt][nt][2 * h] + bb0) * scale;
                float r1 = (c[mt][nt][2 * h + 1] + bb1) * scale;
                if (do_act) {
                    r0 = r0 > 0.f ? r0 : 0.01f * r0;
                    r1 = r1 > 0.f ? r1 : 0.01f * r1;
                }
                if (Cf) {
                    *reinterpret_cast<float2*>(Cf + (size_t)row * HDIM + col) =
                        make_float2(r0, r1);
                } else {
                    uint32_t lp;
                    uint32_t hp = pack_hi2(r0, r1, &lp);
                    *reinterpret_cast<uint32_t*>(Ch + (size_t)row * HDIM + col) = hp;
                    *reinterpret_cast<uint32_t*>(Cl + (size_t)row * HDIM + col) = lp;
                }
            }
        }
    }
}

// final head: out[r,0:2] = h1[r,:] @ Wl[128,2] + bl
__global__ void head_kernel(const float* __restrict__ h1, const float* __restrict__ Wl,
                            const float* __restrict__ bl, float* __restrict__ out, int Nrows) {
    int warp = (blockIdx.x * blockDim.x + threadIdx.x) >> 5;
    int lane = threadIdx.x & 31;
    int nwarps = (gridDim.x * blockDim.x) >> 5;
    int k = lane * 4;
    float w00 = Wl[(k + 0) * 2], w01 = Wl[(k + 0) * 2 + 1];
    float w10 = Wl[(k + 1) * 2], w11 = Wl[(k + 1) * 2 + 1];
    float w20 = Wl[(k + 2) * 2], w21 = Wl[(k + 2) * 2 + 1];
    float w30 = Wl[(k + 3) * 2], w31 = Wl[(k + 3) * 2 + 1];
    for (int r = warp; r < Nrows; r += nwarps) {
        float4 v = *reinterpret_cast<const float4*>(h1 + (size_t)r * HDIM + k);
        float p0 = v.x * w00 + v.y * w10 + v.z * w20 + v.w * w30;
        float p1 = v.x * w01 + v.y * w11 + v.z * w21 + v.w * w31;
#pragma unroll
        for (int off = 16; off; off >>= 1) {
            p0 += __shfl_xor_sync(0xffffffffu, p0, off);
            p1 += __shfl_xor_sync(0xffffffffu, p1, off);
        }
        if (lane == 0) {
            out[(size_t)r * 2 + 0] = p0 + bl[0];
            out[(size_t)r * 2 + 1] = p1 + bl[1];
        }
    }
}

// ---------------------------------------------------------------------------
extern "C" void kernel_launch(void* const* d_in, const int* in_sizes, int n_in,
                              void* d_out, int out_size) {
    const float* x_user = (const float*)d_in[0];
    const float* x_news = (const float*)d_in[1];
    const float* x_source = (const float*)d_in[2];
    const float* x_follower = (const float*)d_in[3];
    const float* Wi1_user = (const float*)d_in[4];
    const float* bi1_user = (const float*)d_in[5];
    const float* Wi1_news = (const float*)d_in[6];
    const float* bi1_news = (const float*)d_in[7];
    const float* Wi1_source = (const float*)d_in[8];
    const float* bi1_source = (const float*)d_in[9];
    const float* Wi1_follower = (const float*)d_in[10];
    const float* bi1_follower = (const float*)d_in[11];
    const float* Wi2 = (const float*)d_in[12];
    const float* bi2 = (const float*)d_in[13];
    const float* conv1_W = (const float*)d_in[14];
    const float* conv1_b = (const float*)d_in[15];
    const float* conv2_W = (const float*)d_in[16];
    const float* conv2_b = (const float*)d_in[17];
    const float* Wl_user = (const float*)d_in[18];
    const float* bl_user = (const float*)d_in[19];
    const float* Wl_news = (const float*)d_in[20];
    const float* bl_news = (const float*)d_in[21];
    const float* Wl_source = (const float*)d_in[22];
    const float* bl_source = (const float*)d_in[23];
    const float* Wl_follower = (const float*)d_in[24];
    const float* bl_follower = (const float*)d_in[25];
    const int* posts_u = (const int*)d_in[26];
    const int* posts_n = (const int*)d_in[27];
    const int* pub_s = (const int*)d_in[28];
    const int* pub_n = (const int*)d_in[29];
    const int* fol_f = (const int*)d_in[30];
    const int* fol_u = (const int*)d_in[31];
    float* out = (float*)d_out;

    __nv_bfloat16 *pAh, *pAl, *pBh, *pBl, *aggh, *aggl, *wh, *wl;
    float* deg;
    int *cnt, *cur, *rp, *el;
    cudaGetSymbolAddress((void**)&pAh, g_pAh);
    cudaGetSymbolAddress((void**)&pAl, g_pAl);
    cudaGetSymbolAddress((void**)&pBh, g_pBh);
    cudaGetSymbolAddress((void**)&pBl, g_pBl);
    cudaGetSymbolAddress((void**)&aggh, g_aggh);
    cudaGetSymbolAddress((void**)&aggl, g_aggl);
    cudaGetSymbolAddress((void**)&wh, g_wh);
    cudaGetSymbolAddress((void**)&wl, g_wl);
    cudaGetSymbolAddress((void**)&deg, g_deg);
    cudaGetSymbolAddress((void**)&cnt, g_cnt);
    cudaGetSymbolAddress((void**)&cur, g_cur);
    cudaGetSymbolAddress((void**)&rp, g_rp);
    cudaGetSymbolAddress((void**)&el, g_el);

    cudaFuncSetAttribute(tgemm_kernel, cudaFuncAttributeMaxDynamicSharedMemorySize, SM_BYTES);

    auto gemmF = [&](const float* A, int lda, int woff, int K, const float* b,
                     __nv_bfloat16* Choi, __nv_bfloat16* Clo, int M) {
        tgemm_kernel<<<(M + 63) / 64, 256, SM_BYTES>>>(
            A, nullptr, nullptr, lda, wh + woff, wl + woff, nullptr, nullptr, K, K,
            b, nullptr, nullptr, Choi, Clo, M, 1.f, 1);
    };
    auto gemmS = [&](const __nv_bfloat16* Ahp, const __nv_bfloat16* Alp, int lda,
                     int woff0, int woff1, int K0, int K,
                     const float* b0, const float* b1,
                     float* Cf, __nv_bfloat16* Choi, __nv_bfloat16* Clo,
                     int M, float scale) {
        tgemm_kernel<<<(M + 63) / 64, 256, SM_BYTES>>>(
            nullptr, Ahp, Alp, lda, wh + woff0, wl + woff0,
            woff1 >= 0 ? wh + woff1 : nullptr, woff1 >= 0 ? wl + woff1 : nullptr, K0, K,
            b0, b1, Cf, Choi, Clo, M, scale, 1);
    };

    // ---- weight split (launch idx 0) ----
    wsplit_kernel<<<dim3(256, 7), 256>>>(Wi1_user, Wi1_news, Wi1_source, Wi1_follower,
                                         Wi2, conv1_W, conv2_W, wh, wl);

    // ---- dense layer 1 (idx 1-4): x -> pA planes ----
    gemmF(x_user, 128, WU1, 128, bi1_user, pAh + OFF_U, pAl + OFF_U, N_USER);
    gemmF(x_source, 128, WS1, 128, bi1_source, pAh + OFF_S, pAl + OFF_S, N_SOURCE);
    gemmF(x_follower, 128, WF1, 128, bi1_follower, pAh + OFF_F, pAl + OFF_F, N_FOLLOWER);
    gemmF(x_news, 300, WN1, 300, bi1_news, pAh + OFF_N, pAl + OFF_N, N_NEWS);

    // ---- dense layer 2 (idx 5-8; idx 5 = user M=200k split path for ncu) ----
    gemmS(pAh + OFF_U, pAl + OFF_U, 128, WI2 + 0 * 16384, -1, 128, 128,
          bi2 + 0 * HDIM, nullptr, nullptr, pBh + OFF_U, pBl + OFF_U, N_USER, 1.f);
    gemmS(pAh + OFF_F, pAl + OFF_F, 128, WI2 + 3 * 16384, -1, 128, 128,
          bi2 + 3 * HDIM, nullptr, nullptr, pBh + OFF_F, pBl + OFF_F, N_FOLLOWER, 1.f);
    gemmS(pAh + OFF_N, pAl + OFF_N, 128, WI2 + 1 * 16384, -1, 128, 128,
          bi2 + 1 * HDIM, nullptr, nullptr, pBh + OFF_N, pBl + OFF_N, N_NEWS, 1.f);
    gemmS(pAh + OFF_S, pAl + OFF_S, 128, WI2 + 2 * 16384, -1, 128, 128,
          bi2 + 2 * HDIM, nullptr, nullptr, pBh + OFF_S, pBl + OFF_S, N_SOURCE, 1.f);

    // ---- CSR build ----
    zero4_kernel<<<2048, 256>>>((float4*)cnt, DEG_TOTAL / 4);
    zero4_kernel<<<2048, 256>>>((float4*)cur, DEG_TOTAL / 4);
    counti_kernel<<<2048, 256>>>(posts_u, E_POSTS, cnt + DS_POSTS_U);
    counti_kernel<<<2048, 256>>>(posts_n, E_POSTS, cnt + DS_POSTS_N);
    counti_kernel<<<512, 256>>>(pub_s, E_PUB, cnt + DS_PUB_S);
    counti_kernel<<<512, 256>>>(pub_n, E_PUB, cnt + DS_PUB_N);
    counti_kernel<<<4096, 256>>>(fol_f, E_FOL, cnt + DS_FOL_F);
    counti_kernel<<<4096, 256>>>(fol_u, E_FOL, cnt + DS_FOL_U);
    rsqrt_cnt_kernel<<<2048, 256>>>(cnt, deg, DEG_TOTAL);
    scan6_kernel<<<6, 1024>>>(cnt, rp);
    fill_kernel<<<2048, 256>>>(posts_u, posts_n, E_POSTS, rp + RP0, cur + DS_POSTS_N, el + EL0);
    fill_kernel<<<2048, 256>>>(posts_n, posts_u, E_POSTS, rp + RP1, cur + DS_POSTS_U, el + EL1);
    fill_kernel<<<512, 256>>>(pub_s, pub_n, E_PUB, rp + RP2, cur + DS_PUB_N, el + EL2);
    fill_kernel<<<512, 256>>>(pub_n, pub_s, E_PUB, rp + RP3, cur + DS_PUB_S, el + EL3);
    fill_kernel<<<4096, 256>>>(fol_f, fol_u, E_FOL, rp + RP4, cur + DS_FOL_U, el + EL4);
    fill_kernel<<<4096, 256>>>(fol_u, fol_f, E_FOL, rp + RP5, cur + DS_FOL_F, el + EL5);

    auto gath = [&](const __nv_bfloat16* Hh, const __nv_bfloat16* Hl, size_t hoff,
                    int rpo, int elo, int rs_src, int rs_dst, int colofs, int n_dst) {
        gather_kernel<<<(n_dst + 7) / 8, 256>>>(Hh + hoff, Hl + hoff, rp + rpo, el + elo,
                                                deg + rs_src, deg + rs_dst, aggh, aggl,
                                                colofs, n_dst);
    };

    // ---- conv layers ----
    const size_t H1_BASE = (size_t)TOT_NODES * 2;
    float* h1_u = out + H1_BASE + OFF_U;
    float* h1_n = out + H1_BASE + OFF_N;
    float* h1_s = out + H1_BASE + OFF_S;
    float* h1_f = out + H1_BASE + OFF_F;

    for (int layer = 0; layer < 2; layer++) {
        const __nv_bfloat16* Hh = (layer == 0) ? pBh : pAh;
        const __nv_bfloat16* Hl = (layer == 0) ? pBl : pAl;
        int WC = (layer == 0) ? WC1 : WC2;
        const float* bc = (layer == 0) ? conv1_b : conv2_b;

        gath(Hh, Hl, OFF_N, RP1, EL1, DS_POSTS_N, DS_POSTS_U, 0, N_USER);
        gath(Hh, Hl, OFF_F, RP4, EL4, DS_FOL_F, DS_FOL_U, 128, N_USER);
        gemmS(aggh, aggl, 256, WC + (0 * 6 + 1) * 16384, WC + (0 * 6 + 4) * 16384, 128, 256,
              bc + (0 * 6 + 1) * HDIM, bc + (0 * 6 + 4) * HDIM,
              (layer == 0) ? nullptr : h1_u,
              (layer == 0) ? pAh + OFF_U : nullptr, (layer == 0) ? pAl + OFF_U : nullptr,
              N_USER, 0.5f);
        gath(Hh, Hl, OFF_U, RP0, EL0, DS_POSTS_U, DS_POSTS_N, 0, N_NEWS);
        gath(Hh, Hl, OFF_S, RP2, EL2, DS_PUB_S, DS_PUB_N, 128, N_NEWS);
        gemmS(aggh, aggl, 256, WC + (1 * 6 + 0) * 16384, WC + (1 * 6 + 2) * 16384, 128, 256,
              bc + (1 * 6 + 0) * HDIM, bc + (1 * 6 + 2) * HDIM,
              (layer == 0) ? nullptr : h1_n,
              (layer == 0) ? pAh + OFF_N : nullptr, (layer == 0) ? pAl + OFF_N : nullptr,
              N_NEWS, 0.5f);
        gath(Hh, Hl, OFF_N, RP3, EL3, DS_PUB_N, DS_PUB_S, 0, N_SOURCE);
        gemmS(aggh, aggl, 256, WC + (2 * 6 + 3) * 16384, -1, 128, 128,
              bc + (2 * 6 + 3) * HDIM, nullptr,
              (layer == 0) ? nullptr : h1_s,
              (layer == 0) ? pAh + OFF_S : nullptr, (layer == 0) ? pAl + OFF_S : nullptr,
              N_SOURCE, 1.f);
        gath(Hh, Hl, OFF_U, RP5, EL5, DS_FOL_U, DS_FOL_F, 0, N_FOLLOWER);
        gemmS(aggh, aggl, 256, WC + (3 * 6 + 5) * 16384, -1, 128, 128,
              bc + (3 * 6 + 5) * HDIM, nullptr,
              (layer == 0) ? nullptr : h1_f,
              (layer == 0) ? pAh + OFF_F : nullptr, (layer == 0) ? pAl + OFF_F : nullptr,
              N_FOLLOWER, 1.f);
    }

    // ---- head ----
    float* out_u = out + 0;
    float* out_n = out + (size_t)N_USER * 2;
    float* out_s = out + (size_t)(N_USER + N_NEWS) * 2;
    float* out_f = out + (size_t)(N_USER + N_NEWS + N_SOURCE) * 2;
    head_kernel<<<(N_USER * 32 + 255) / 256, 256>>>(h1_u, Wl_user, bl_user, out_u, N_USER);
    head_kernel<<<(N_NEWS * 32 + 255) / 256, 256>>>(h1_n, Wl_news, bl_news, out_n, N_NEWS);
    head_kernel<<<(N_SOURCE * 32 + 255) / 256, 256>>>(h1_s, Wl_source, bl_source, out_s, N_SOURCE);
    head_kernel<<<(N_FOLLOWER * 32 + 255) / 256, 256>>>(h1_f, Wl_follower, bl_follower, out_f, N_FOLLOWER);
}

// round 15
// speedup vs baseline: 1.6278x; 1.0062x over previous
#include <cuda_runtime.h>
#include <cuda_bf16.h>
#include <cstdint>
#include <cstddef>

#define N_USER 200000
#define N_NEWS 100000
#define N_SOURCE 5000
#define N_FOLLOWER 200000
#define HDIM 128
#define E_POSTS 500000
#define E_PUB 100000
#define E_FOL 1000000

#define TOT_NODES (N_USER + N_NEWS + N_SOURCE + N_FOLLOWER)

#define OFF_U ((size_t)0)
#define OFF_N ((size_t)N_USER * HDIM)
#define OFF_S ((size_t)(N_USER + N_NEWS) * HDIM)
#define OFF_F ((size_t)(N_USER + N_NEWS + N_SOURCE) * HDIM)

#define DS_POSTS_U 0
#define DS_POSTS_N 200000
#define DS_PUB_S   300000
#define DS_PUB_N   305000
#define DS_FOL_F   405000
#define DS_FOL_U   605000
#define DEG_TOTAL  805000

#define RP0 0
#define RP1 100001
#define RP2 300002
#define RP3 400003
#define RP4 405004
#define RP5 605005
#define RP_TOTAL 805006

#define EL0 0
#define EL1 500000
#define EL2 1000000
#define EL3 1100000
#define EL4 1200000
#define EL5 2200000
#define EL_TOTAL 3200000

// weight-plane segment offsets (elements)
#define WU1 0
#define WN1 16384
#define WS1 54784
#define WF1 71168
#define WI2 87552
#define WC1 153088
#define WC2 546304
#define WTOT 939520

// agg row offsets (row stride 256 for all types)
#define AGG_U 0
#define AGG_N 200000
#define AGG_S 300000
#define AGG_F 305000
#define AGG_ROWS 505000

__device__ __nv_bfloat16 g_pAh[(size_t)TOT_NODES * HDIM];
__device__ __nv_bfloat16 g_pAl[(size_t)TOT_NODES * HDIM];
__device__ __nv_bfloat16 g_pBh[(size_t)TOT_NODES * HDIM];
__device__ __nv_bfloat16 g_pBl[(size_t)TOT_NODES * HDIM];
__device__ __nv_bfloat16 g_aggh[(size_t)AGG_ROWS * 256];
__device__ __nv_bfloat16 g_aggl[(size_t)AGG_ROWS * 256];
__device__ __nv_bfloat16 g_wh[WTOT];
__device__ __nv_bfloat16 g_wl[WTOT];
__device__ float g_deg[DEG_TOTAL];
__device__ int   g_cnt[DEG_TOTAL];
__device__ int   g_cur[DEG_TOTAL];
__device__ int   g_rp[RP_TOTAL];
__device__ int   g_el[EL_TOTAL];

// ---------------------------------------------------------------------------
__device__ __forceinline__ uint32_t pack_hi2(float a, float b, uint32_t* lo) {
    __nv_bfloat16 h0 = __float2bfloat16_rn(a);
    __nv_bfloat16 h1 = __float2bfloat16_rn(b);
    __nv_bfloat16 l0 = __float2bfloat16_rn(a - __bfloat162float(h0));
    __nv_bfloat16 l1 = __float2bfloat16_rn(b - __bfloat162float(h1));
    *lo = (uint32_t)__bfloat16_as_ushort(l0) | ((uint32_t)__bfloat16_as_ushort(l1) << 16);
    return (uint32_t)__bfloat16_as_ushort(h0) | ((uint32_t)__bfloat16_as_ushort(h1) << 16);
}
__device__ __forceinline__ float bflo(uint32_t u) { return __uint_as_float(u << 16); }
__device__ __forceinline__ float bfhi(uint32_t u) { return __uint_as_float(u & 0xffff0000u); }

// ---------------------------------------------------------------------------
__global__ void zero4_kernel(float4* __restrict__ p, size_t n4) {
    size_t i = (size_t)blockIdx.x * blockDim.x + threadIdx.x;
    size_t stride = (size_t)gridDim.x * blockDim.x;
    float4 z = make_float4(0.f, 0.f, 0.f, 0.f);
    for (; i < n4; i += stride) p[i] = z;
}

__global__ void wsplit_kernel(const float* __restrict__ wu, const float* __restrict__ wn,
                              const float* __restrict__ ws, const float* __restrict__ wf,
                              const float* __restrict__ wi2, const float* __restrict__ c1,
                              const float* __restrict__ c2,
                              __nv_bfloat16* __restrict__ wh, __nv_bfloat16* __restrict__ wl) {
    const float* src; int n; int off;
    switch (blockIdx.y) {
        case 0: src = wu;  n = 16384;  off = WU1; break;
        case 1: src = wn;  n = 38400;  off = WN1; break;
        case 2: src = ws;  n = 16384;  off = WS1; break;
        case 3: src = wf;  n = 16384;  off = WF1; break;
        case 4: src = wi2; n = 65536;  off = WI2; break;
        case 5: src = c1;  n = 393216; off = WC1; break;
        default: src = c2; n = 393216; off = WC2; break;
    }
    int stride = gridDim.x * blockDim.x;
    for (int i = blockIdx.x * blockDim.x + threadIdx.x; i < n; i += stride) {
        float x = src[i];
        __nv_bfloat16 h = __float2bfloat16_rn(x);
        wh[off + i] = h;
        wl[off + i] = __float2bfloat16_rn(x - __bfloat162float(h));
    }
}

__global__ void rsqrt_cnt_kernel(const int* __restrict__ cnt, float* __restrict__ deg, int n) {
    int i = blockIdx.x * blockDim.x + threadIdx.x;
    int stride = gridDim.x * blockDim.x;
    for (; i < n; i += stride) {
        int c = cnt[i];
        deg[i] = rsqrtf((float)(c < 1 ? 1 : c));
    }
}

__global__ __launch_bounds__(1024) void scan6_kernel(const int* __restrict__ cnt,
                                                     int* __restrict__ rp) {
    const int segs[6] = {DS_POSTS_N, DS_POSTS_U, DS_PUB_N, DS_PUB_S, DS_FOL_U, DS_FOL_F};
    const int ns[6]   = {N_NEWS, N_USER, N_NEWS, N_SOURCE, N_USER, N_FOLLOWER};
    const int rpo[6]  = {RP0, RP1, RP2, RP3, RP4, RP5};
    int r = blockIdx.x;
    const int* c = cnt + segs[r];
    int* out = rp + rpo[r];
    int n = ns[r];
    int tid = threadIdx.x;
    int lane = tid & 31;
    int wid = tid >> 5;
    __shared__ int wsum[32];
    __shared__ int carry;
    if (tid == 0) { carry = 0; out[0] = 0; }
    __syncthreads();
    for (int base = 0; base < n; base += 1024) {
        int v = (base + tid < n) ? c[base + tid] : 0;
        int x = v;
#pragma unroll
        for (int o = 1; o < 32; o <<= 1) {
            int y = __shfl_up_sync(0xffffffffu, x, o);
            if (lane >= o) x += y;
        }
        if (lane == 31) wsum[wid] = x;
        __syncthreads();
        if (wid == 0) {
            int s = wsum[lane];
#pragma unroll
            for (int o = 1; o < 32; o <<= 1) {
                int y = __shfl_up_sync(0xffffffffu, s, o);
                if (lane >= o) s += y;
            }
            wsum[lane] = s;
        }
        __syncthreads();
        int pre = (wid > 0) ? wsum[wid - 1] : 0;
        int incl = carry + pre + x;
        if (base + tid < n) out[base + tid + 1] = incl;
        __syncthreads();
        if (tid == 1023) carry = incl;
        __syncthreads();
    }
}

// ---- batched count ----
struct CntSeg { const int* idx; int* cnt; int n; int bstart; int nthreads; };
struct CntBatch { int nseg; CntSeg s[6]; };
__global__ void count_batch_kernel(CntBatch B) {
    int bid = blockIdx.x;
    int si = 0;
#pragma unroll
    for (int i = 1; i < 6; i++)
        if (i < B.nseg && bid >= B.s[i].bstart) si = i;
    const CntSeg& g = B.s[si];
    int t = (bid - g.bstart) * 256 + threadIdx.x;
    for (; t < g.n; t += g.nthreads) atomicAdd(&g.cnt[g.idx[t]], 1);
}

// ---- batched fill ----
struct FillSeg { const int* src; const int* dst; const int* rp; int* cur; int* el;
                 int E; int bstart; int nthreads; };
struct FillBatch { int nseg; FillSeg s[6]; };
__global__ void fill_batch_kernel(FillBatch B) {
    int bid = blockIdx.x;
    int si = 0;
#pragma unroll
    for (int i = 1; i < 6; i++)
        if (i < B.nseg && bid >= B.s[i].bstart) si = i;
    const FillSeg& g = B.s[si];
    int t = (bid - g.bstart) * 256 + threadIdx.x;
    for (; t < g.E; t += g.nthreads) {
        int d = g.dst[t];
        int p = atomicAdd(&g.cur[d], 1);
        g.el[g.rp[d] + p] = g.src[t];
    }
}

// ---- batched gather ----
struct GathSeg { const __nv_bfloat16* Hh; const __nv_bfloat16* Hl;
                 const int* rp; const int* el;
                 const float* rs_src; const float* rs_dst;
                 __nv_bfloat16* Ah; __nv_bfloat16* Al;
                 int colofs; int n_dst; int bstart; int nwarps; };
struct GathBatch { int nseg; GathSeg s[6]; };
__global__ void gather_batch_kernel(GathBatch B) {
    int bid = blockIdx.x;
    int si = 0;
#pragma unroll
    for (int i = 1; i < 6; i++)
        if (i < B.nseg && bid >= B.s[i].bstart) si = i;
    const GathSeg& g = B.s[si];
    int lane = threadIdx.x & 31;
    int lwarp = (bid - g.bstart) * 8 + (threadIdx.x >> 5);
    for (int row = lwarp; row < g.n_dst; row += g.nwarps) {
        int beg = g.rp[row], end = g.rp[row + 1];
        float a0 = 0.f, a1 = 0.f, a2 = 0.f, a3 = 0.f;
        for (int e = beg; e < end; e++) {
            int s = g.el[e];
            float sc = g.rs_src[s];
            const size_t base = (size_t)s * HDIM + lane * 4;
            uint2 vh = *reinterpret_cast<const uint2*>(g.Hh + base);
            uint2 vl = *reinterpret_cast<const uint2*>(g.Hl + base);
            a0 += sc * (bflo(vh.x) + bflo(vl.x));
            a1 += sc * (bfhi(vh.x) + bfhi(vl.x));
            a2 += sc * (bflo(vh.y) + bflo(vl.y));
            a3 += sc * (bfhi(vh.y) + bfhi(vl.y));
        }
        float ri = g.rs_dst[row];
        a0 *= ri; a1 *= ri; a2 *= ri; a3 *= ri;
        uint32_t lp0, lp1;
        uint32_t hp0 = pack_hi2(a0, a1, &lp0);
        uint32_t hp1 = pack_hi2(a2, a3, &lp1);
        size_t o = (size_t)row * 256 + g.colofs + lane * 4;
        *reinterpret_cast<uint2*>(g.Ah + o) = make_uint2(hp0, hp1);
        *reinterpret_cast<uint2*>(g.Al + o) = make_uint2(lp0, lp1);
    }
}

// ---------------------------------------------------------------------------
// bf16x3 HMMA GEMM, batched segments. CTA tile 64x128, K-chunk 64, 4 CTAs/SM.
// ---------------------------------------------------------------------------
#define ASTR 72
#define BSTR 136
#define SM_BYTES (2 * 64 * ASTR * 2 + 2 * 64 * BSTR * 2)  // 53248 B

#define CP_ASYNC16(smem, gptr) \
    asm volatile("cp.async.cg.shared.global [%0], [%1], 16;" :: "r"(smem), "l"(gptr))
#define CP_COMMIT() asm volatile("cp.async.commit_group;")
#define CP_WAIT0()  asm volatile("cp.async.wait_group 0;" ::: "memory")

__device__ __forceinline__ void mma16816(float* c, const uint32_t* a, const uint32_t* b) {
    asm volatile(
        "mma.sync.aligned.m16n8k16.row.col.f32.bf16.bf16.f32 "
        "{%0,%1,%2,%3}, {%4,%5,%6,%7}, {%8,%9}, {%0,%1,%2,%3};\n"
        : "+f"(c[0]), "+f"(c[1]), "+f"(c[2]), "+f"(c[3])
        : "r"(a[0]), "r"(a[1]), "r"(a[2]), "r"(a[3]), "r"(b[0]), "r"(b[1]));
}
__device__ __forceinline__ void ldsm_x4(uint32_t* r, uint32_t addr) {
    asm volatile("ldmatrix.sync.aligned.m8n8.x4.shared.b16 {%0,%1,%2,%3}, [%4];"
                 : "=r"(r[0]), "=r"(r[1]), "=r"(r[2]), "=r"(r[3]) : "r"(addr));
}
__device__ __forceinline__ void ldsm_x4_t(uint32_t* r, uint32_t addr) {
    asm volatile("ldmatrix.sync.aligned.m8n8.x4.trans.shared.b16 {%0,%1,%2,%3}, [%4];"
                 : "=r"(r[0]), "=r"(r[1]), "=r"(r[2]), "=r"(r[3]) : "r"(addr));
}

struct GemmSeg {
    const float* Afp;
    const __nv_bfloat16* Ah; const __nv_bfloat16* Al; int lda;
    const __nv_bfloat16* Wh0; const __nv_bfloat16* Wl0;
    const __nv_bfloat16* Wh1; const __nv_bfloat16* Wl1;
    int K0; int K;
    const float* b0; const float* b1;
    float* Cf; __nv_bfloat16* Ch; __nv_bfloat16* Cl;
    int M; float scale; int bstart;
};
struct GemmBatch { int nseg; GemmSeg s[4]; };

__global__ __launch_bounds__(256, 4) void tgemm_batch_kernel(GemmBatch B) {
    int bid = blockIdx.x;
    int si = 0;
#pragma unroll
    for (int i = 1; i < 4; i++)
        if (i < B.nseg && bid >= B.s[i].bstart) si = i;
    const GemmSeg& g = B.s[si];

    extern __shared__ __align__(16) char smraw[];
    __nv_bfloat16* AH = reinterpret_cast<__nv_bfloat16*>(smraw);
    __nv_bfloat16* AL = AH + 64 * ASTR;
    __nv_bfloat16* BH = AL + 64 * ASTR;
    __nv_bfloat16* BL = BH + 64 * BSTR;

    int tid = threadIdx.x;
    int lane = tid & 31;
    int warp = tid >> 5;
    int wm = warp & 1;
    int wn = warp >> 1;
    int block_row = (bid - g.bstart) * 64;
    const int lda = g.lda;
    const int K = g.K;
    const int K0 = g.K0;
    const int M = g.M;
    const uint4 z4 = make_uint4(0, 0, 0, 0);

    uint32_t aBaseH = (uint32_t)__cvta_generic_to_shared(
        &AH[(wm * 32 + (lane & 15)) * ASTR + (lane >> 4) * 8]);
    uint32_t aBaseL = aBaseH + 64 * ASTR * 2;
    uint32_t bBaseH = (uint32_t)__cvta_generic_to_shared(
        &BH[(lane & 15) * BSTR + wn * 32 + (lane >> 4) * 8]);
    uint32_t bBaseL = bBaseH + 64 * BSTR * 2;

    float c[2][4][4];
#pragma unroll
    for (int mt = 0; mt < 2; mt++)
#pragma unroll
        for (int nt = 0; nt < 4; nt++)
#pragma unroll
            for (int j = 0; j < 4; j++) c[mt][nt][j] = 0.f;

    for (int kbase = 0; kbase < K; kbase += 64) {
        int kcount = K - kbase; if (kcount > 64) kcount = 64;
        // ---- stage A chunk: 64 rows x 64 k ----
        if (g.Afp == nullptr) {
#pragma unroll
            for (int it = 0; it < 2; it++) {
                int idx = tid + it * 256;
                int row = idx >> 3;
                int kl = (idx & 7) * 8;
                int grow = block_row + row;
                int gk = kbase + kl;
                if (grow < M && gk < K) {
                    size_t go = (size_t)grow * lda + gk;
                    CP_ASYNC16((uint32_t)__cvta_generic_to_shared(&AH[row * ASTR + kl]), g.Ah + go);
                    CP_ASYNC16((uint32_t)__cvta_generic_to_shared(&AL[row * ASTR + kl]), g.Al + go);
                } else {
                    *reinterpret_cast<uint4*>(&AH[row * ASTR + kl]) = z4;
                    *reinterpret_cast<uint4*>(&AL[row * ASTR + kl]) = z4;
                }
            }
        } else {
#pragma unroll
            for (int it = 0; it < 2; it++) {
                int idx = tid + it * 256;
                int row = idx >> 3;
                int kl = (idx & 7) * 8;
                float v[8];
#pragma unroll
                for (int j = 0; j < 8; j++) v[j] = 0.f;
                int grow = block_row + row;
                int gk = kbase + kl;
                if (grow < M && gk < K) {
                    const float* ap = g.Afp + (size_t)grow * lda + gk;
                    if (gk + 7 < K) {
                        float4 v0 = *reinterpret_cast<const float4*>(ap);
                        float4 v1 = *reinterpret_cast<const float4*>(ap + 4);
                        v[0] = v0.x; v[1] = v0.y; v[2] = v0.z; v[3] = v0.w;
                        v[4] = v1.x; v[5] = v1.y; v[6] = v1.z; v[7] = v1.w;
                    } else {
#pragma unroll
                        for (int j = 0; j < 8; j++)
                            if (gk + j < K) v[j] = ap[j];
                    }
                }
                uint32_t hp[4], lp[4];
#pragma unroll
                for (int j = 0; j < 4; j++) hp[j] = pack_hi2(v[2 * j], v[2 * j + 1], &lp[j]);
                uint32_t off = (uint32_t)(row * ASTR + kl);
                *reinterpret_cast<uint4*>(&AH[off]) = make_uint4(hp[0], hp[1], hp[2], hp[3]);
                *reinterpret_cast<uint4*>(&AL[off]) = make_uint4(lp[0], lp[1], lp[2], lp[3]);
            }
        }
        // ---- stage W chunk: 64 k-rows x 128 n ----
#pragma unroll
        for (int it = 0; it < 4; it++) {
            int idx = tid + it * 256;
            int kr = idx >> 4;
            int nl = (idx & 15) * 8;
            int gk = kbase + kr;
            uint32_t off = (uint32_t)(kr * BSTR + nl);
            if (gk < K) {
                size_t go = (gk < K0) ? ((size_t)gk * HDIM + nl)
                                      : ((size_t)(gk - K0) * HDIM + nl);
                const __nv_bfloat16* sh = (gk < K0) ? g.Wh0 : g.Wh1;
                const __nv_bfloat16* sl = (gk < K0) ? g.Wl0 : g.Wl1;
                CP_ASYNC16((uint32_t)__cvta_generic_to_shared(&BH[off]), sh + go);
                CP_ASYNC16((uint32_t)__cvta_generic_to_shared(&BL[off]), sl + go);
            } else {
                *reinterpret_cast<uint4*>(&BH[off]) = z4;
                *reinterpret_cast<uint4*>(&BL[off]) = z4;
            }
        }
        CP_COMMIT();
        CP_WAIT0();
        __syncthreads();

        int nsteps = (kcount + 15) / 16;
#pragma unroll 4
        for (int s = 0; s < nsteps; s++) {
            uint32_t bh[4][2], bl[4][2];
#pragma unroll
            for (int half = 0; half < 2; half++) {
                uint32_t off = (uint32_t)(s * 16 * BSTR + half * 16) * 2;
                uint32_t r[4];
                ldsm_x4_t(r, bBaseH + off);
                bh[half * 2][0] = r[0]; bh[half * 2][1] = r[1];
                bh[half * 2 + 1][0] = r[2]; bh[half * 2 + 1][1] = r[3];
                ldsm_x4_t(r, bBaseL + off);
                bl[half * 2][0] = r[0]; bl[half * 2][1] = r[1];
                bl[half * 2 + 1][0] = r[2]; bl[half * 2 + 1][1] = r[3];
            }
#pragma unroll
            for (int mt = 0; mt < 2; mt++) {
                uint32_t off = (uint32_t)(mt * 16 * ASTR + s * 16) * 2;
                uint32_t ah[4], al[4];
                ldsm_x4(ah, aBaseH + off);
                ldsm_x4(al, aBaseL + off);
#pragma unroll
                for (int nt = 0; nt < 4; nt++) {
                    mma16816(c[mt][nt], ah, bh[nt]);
                    mma16816(c[mt][nt], ah, bl[nt]);
                    mma16816(c[mt][nt], al, bh[nt]);
                }
            }
        }
        __syncthreads();
    }

    // ---- epilogue ----
    float scale = g.scale;
#pragma unroll
    for (int mt = 0; mt < 2; mt++) {
#pragma unroll
        for (int nt = 0; nt < 4; nt++) {
            int col = wn * 32 + nt * 8 + (lane & 3) * 2;
            float bb0 = (g.b0 ? g.b0[col] : 0.f) + (g.b1 ? g.b1[col] : 0.f);
            float bb1 = (g.b0 ? g.b0[col + 1] : 0.f) + (g.b1 ? g.b1[col + 1] : 0.f);
#pragma unroll
            for (int h = 0; h < 2; h++) {
                int row = block_row + wm * 32 + mt * 16 + (lane >> 2) + h * 8;
                if (row >= M) continue;
                float r0 = (c[mt][nt][2 * h] + bb0) * scale;
                float r1 = (c[mt][nt][2 * h + 1] + bb1) * scale;
                r0 = r0 > 0.f ? r0 : 0.01f * r0;
                r1 = r1 > 0.f ? r1 : 0.01f * r1;
                if (g.Cf) {
                    *reinterpret_cast<float2*>(g.Cf + (size_t)row * HDIM + col) =
                        make_float2(r0, r1);
                } else {
                    uint32_t lp;
                    uint32_t hp = pack_hi2(r0, r1, &lp);
                    *reinterpret_cast<uint32_t*>(g.Ch + (size_t)row * HDIM + col) = hp;
                    *reinterpret_cast<uint32_t*>(g.Cl + (size_t)row * HDIM + col) = lp;
                }
            }
        }
    }
}

// ---- batched head ----
struct HeadSeg { const float* h1; const float* Wl; const float* bl; float* out;
                 int N; int bstart; int nwarps; };
struct HeadBatch { int nseg; HeadSeg s[4]; };
__global__ void head_batch_kernel(HeadBatch B) {
    int bid = blockIdx.x;
    int si = 0;
#pragma unroll
    for (int i = 1; i < 4; i++)
        if (i < B.nseg && bid >= B.s[i].bstart) si = i;
    const HeadSeg& g = B.s[si];
    int lane = threadIdx.x & 31;
    int lwarp = (bid - g.bstart) * 8 + (threadIdx.x >> 5);
    int k = lane * 4;
    float w00 = g.Wl[(k + 0) * 2], w01 = g.Wl[(k + 0) * 2 + 1];
    float w10 = g.Wl[(k + 1) * 2], w11 = g.Wl[(k + 1) * 2 + 1];
    float w20 = g.Wl[(k + 2) * 2], w21 = g.Wl[(k + 2) * 2 + 1];
    float w30 = g.Wl[(k + 3) * 2], w31 = g.Wl[(k + 3) * 2 + 1];
    for (int r = lwarp; r < g.N; r += g.nwarps) {
        float4 v = *reinterpret_cast<const float4*>(g.h1 + (size_t)r * HDIM + k);
        float p0 = v.x * w00 + v.y * w10 + v.z * w20 + v.w * w30;
        float p1 = v.x * w01 + v.y * w11 + v.z * w21 + v.w * w31;
#pragma unroll
        for (int off = 16; off; off >>= 1) {
            p0 += __shfl_xor_sync(0xffffffffu, p0, off);
            p1 += __shfl_xor_sync(0xffffffffu, p1, off);
        }
        if (lane == 0) {
            g.out[(size_t)r * 2 + 0] = p0 + g.bl[0];
            g.out[(size_t)r * 2 + 1] = p1 + g.bl[1];
        }
    }
}

// ---------------------------------------------------------------------------
extern "C" void kernel_launch(void* const* d_in, const int* in_sizes, int n_in,
                              void* d_out, int out_size) {
    const float* x_user = (const float*)d_in[0];
    const float* x_news = (const float*)d_in[1];
    const float* x_source = (const float*)d_in[2];
    const float* x_follower = (const float*)d_in[3];
    const float* Wi1_user = (const float*)d_in[4];
    const float* bi1_user = (const float*)d_in[5];
    const float* Wi1_news = (const float*)d_in[6];
    const float* bi1_news = (const float*)d_in[7];
    const float* Wi1_source = (const float*)d_in[8];
    const float* bi1_source = (const float*)d_in[9];
    const float* Wi1_follower = (const float*)d_in[10];
    const float* bi1_follower = (const float*)d_in[11];
    const float* Wi2 = (const float*)d_in[12];
    const float* bi2 = (const float*)d_in[13];
    const float* conv1_W = (const float*)d_in[14];
    const float* conv1_b = (const float*)d_in[15];
    const float* conv2_W = (const float*)d_in[16];
    const float* conv2_b = (const float*)d_in[17];
    const float* Wl_user = (const float*)d_in[18];
    const float* bl_user = (const float*)d_in[19];
    const float* Wl_news = (const float*)d_in[20];
    const float* bl_news = (const float*)d_in[21];
    const float* Wl_source = (const float*)d_in[22];
    const float* bl_source = (const float*)d_in[23];
    const float* Wl_follower = (const float*)d_in[24];
    const float* bl_follower = (const float*)d_in[25];
    const int* posts_u = (const int*)d_in[26];
    const int* posts_n = (const int*)d_in[27];
    const int* pub_s = (const int*)d_in[28];
    const int* pub_n = (const int*)d_in[29];
    const int* fol_f = (const int*)d_in[30];
    const int* fol_u = (const int*)d_in[31];
    float* out = (float*)d_out;

    __nv_bfloat16 *pAh, *pAl, *pBh, *pBl, *aggh, *aggl, *wh, *wl;
    float* deg;
    int *cnt, *cur, *rp, *el;
    cudaGetSymbolAddress((void**)&pAh, g_pAh);
    cudaGetSymbolAddress((void**)&pAl, g_pAl);
    cudaGetSymbolAddress((void**)&pBh, g_pBh);
    cudaGetSymbolAddress((void**)&pBl, g_pBl);
    cudaGetSymbolAddress((void**)&aggh, g_aggh);
    cudaGetSymbolAddress((void**)&aggl, g_aggl);
    cudaGetSymbolAddress((void**)&wh, g_wh);
    cudaGetSymbolAddress((void**)&wl, g_wl);
    cudaGetSymbolAddress((void**)&deg, g_deg);
    cudaGetSymbolAddress((void**)&cnt, g_cnt);
    cudaGetSymbolAddress((void**)&cur, g_cur);
    cudaGetSymbolAddress((void**)&rp, g_rp);
    cudaGetSymbolAddress((void**)&el, g_el);

    cudaFuncSetAttribute(tgemm_batch_kernel, cudaFuncAttributeMaxDynamicSharedMemorySize,
                         SM_BYTES);

    auto mkseg = [&](const float* Afp, const __nv_bfloat16* Ahp, const __nv_bfloat16* Alp,
                     int lda, int woff0, int woff1, int K0, int K,
                     const float* b0, const float* b1,
                     float* Cf, __nv_bfloat16* Ch, __nv_bfloat16* Cl,
                     int M, float scale, int bstart) {
        GemmSeg s;
        s.Afp = Afp; s.Ah = Ahp; s.Al = Alp; s.lda = lda;
        s.Wh0 = wh + woff0; s.Wl0 = wl + woff0;
        s.Wh1 = (woff1 >= 0) ? wh + woff1 : nullptr;
        s.Wl1 = (woff1 >= 0) ? wl + woff1 : nullptr;
        s.K0 = K0; s.K = K; s.b0 = b0; s.b1 = b1;
        s.Cf = Cf; s.Ch = Ch; s.Cl = Cl; s.M = M; s.scale = scale; s.bstart = bstart;
        return s;
    };
    auto nb = [](int M) { return (M + 63) / 64; };

    // ---- launch 0-1: zero cnt/cur ----
    zero4_kernel<<<2048, 256>>>((float4*)cnt, DEG_TOTAL / 4);
    zero4_kernel<<<2048, 256>>>((float4*)cur, DEG_TOTAL / 4);

    // ---- launch 2: batched degree count ----
    {
        CntBatch B; B.nseg = 6;
        int bs = 0;
        auto add = [&](int i, const int* idx, int n, int coff, int blocks) {
            B.s[i] = {idx, cnt + coff, n, bs, blocks * 256};
            bs += blocks;
        };
        add(0, posts_u, E_POSTS, DS_POSTS_U, 2048);
        add(1, posts_n, E_POSTS, DS_POSTS_N, 2048);
        add(2, pub_s, E_PUB, DS_PUB_S, 512);
        add(3, pub_n, E_PUB, DS_PUB_N, 512);
        add(4, fol_f, E_FOL, DS_FOL_F, 4096);
        add(5, fol_u, E_FOL, DS_FOL_U, 4096);
        count_batch_kernel<<<bs, 256>>>(B);
    }

    // ---- launch 3: weight split ----
    wsplit_kernel<<<dim3(256, 7), 256>>>(Wi1_user, Wi1_news, Wi1_source, Wi1_follower,
                                         Wi2, conv1_W, conv2_W, wh, wl);

    // ---- launch 4: rsqrt ----
    rsqrt_cnt_kernel<<<2048, 256>>>(cnt, deg, DEG_TOTAL);

    // ---- launch 5: dense1 batched (ncu capture target) ----
    {
        GemmBatch B; B.nseg = 4;
        int bs = 0;
        B.s[0] = mkseg(x_user, nullptr, nullptr, 128, WU1, -1, 128, 128, bi1_user, nullptr,
                       nullptr, pAh + OFF_U, pAl + OFF_U, N_USER, 1.f, bs);
        bs += nb(N_USER);
        B.s[1] = mkseg(x_follower, nullptr, nullptr, 128, WF1, -1, 128, 128, bi1_follower,
                       nullptr, nullptr, pAh + OFF_F, pAl + OFF_F, N_FOLLOWER, 1.f, bs);
        bs += nb(N_FOLLOWER);
        B.s[2] = mkseg(x_news, nullptr, nullptr, 300, WN1, -1, 300, 300, bi1_news, nullptr,
                       nullptr, pAh + OFF_N, pAl + OFF_N, N_NEWS, 1.f, bs);
        bs += nb(N_NEWS);
        B.s[3] = mkseg(x_source, nullptr, nullptr, 128, WS1, -1, 128, 128, bi1_source,
                       nullptr, nullptr, pAh + OFF_S, pAl + OFF_S, N_SOURCE, 1.f, bs);
        bs += nb(N_SOURCE);
        tgemm_batch_kernel<<<bs, 256, SM_BYTES>>>(B);
    }

    // ---- launch 6: dense2 batched ----
    {
        GemmBatch B; B.nseg = 4;
        int bs = 0;
        B.s[0] = mkseg(nullptr, pAh + OFF_U, pAl + OFF_U, 128, WI2 + 0 * 16384, -1, 128, 128,
                       bi2 + 0 * HDIM, nullptr, nullptr, pBh + OFF_U, pBl + OFF_U,
                       N_USER, 1.f, bs);
        bs += nb(N_USER);
        B.s[1] = mkseg(nullptr, pAh + OFF_F, pAl + OFF_F, 128, WI2 + 3 * 16384, -1, 128, 128,
                       bi2 + 3 * HDIM, nullptr, nullptr, pBh + OFF_F, pBl + OFF_F,
                       N_FOLLOWER, 1.f, bs);
        bs += nb(N_FOLLOWER);
        B.s[2] = mkseg(nullptr, pAh + OFF_N, pAl + OFF_N, 128, WI2 + 1 * 16384, -1, 128, 128,
                       bi2 + 1 * HDIM, nullptr, nullptr, pBh + OFF_N, pBl + OFF_N,
                       N_NEWS, 1.f, bs);
        bs += nb(N_NEWS);
        B.s[3] = mkseg(nullptr, pAh + OFF_S, pAl + OFF_S, 128, WI2 + 2 * 16384, -1, 128, 128,
                       bi2 + 2 * HDIM, nullptr, nullptr, pBh + OFF_S, pBl + OFF_S,
                       N_SOURCE, 1.f, bs);
        bs += nb(N_SOURCE);
        tgemm_batch_kernel<<<bs, 256, SM_BYTES>>>(B);
    }

    // ---- launch 7: scan ----
    scan6_kernel<<<6, 1024>>>(cnt, rp);

    // ---- launch 8: batched CSR fill ----
    {
        FillBatch B; B.nseg = 6;
        int bs = 0;
        auto add = [&](int i, const int* s, const int* d, int E, int rpo, int coff, int elo,
                       int blocks) {
            B.s[i] = {s, d, rp + rpo, cur + coff, el + elo, E, bs, blocks * 256};
            bs += blocks;
        };
        add(0, posts_u, posts_n, E_POSTS, RP0, DS_POSTS_N, EL0, 2048);
        add(1, posts_n, posts_u, E_POSTS, RP1, DS_POSTS_U, EL1, 2048);
        add(2, pub_s, pub_n, E_PUB, RP2, DS_PUB_N, EL2, 512);
        add(3, pub_n, pub_s, E_PUB, RP3, DS_PUB_S, EL3, 512);
        add(4, fol_f, fol_u, E_FOL, RP4, DS_FOL_U, EL4, 4096);
        add(5, fol_u, fol_f, E_FOL, RP5, DS_FOL_F, EL5, 4096);
        fill_batch_kernel<<<bs, 256>>>(B);
    }

    // ---- conv layers: per layer 1 batched gather + 1 batched GEMM ----
    const size_t H1_BASE = (size_t)TOT_NODES * 2;
    float* h1_u = out + H1_BASE + OFF_U;
    float* h1_n = out + H1_BASE + OFF_N;
    float* h1_s = out + H1_BASE + OFF_S;
    float* h1_f = out + H1_BASE + OFF_F;

    for (int layer = 0; layer < 2; layer++) {
        const __nv_bfloat16* Hh = (layer == 0) ? pBh : pAh;
        const __nv_bfloat16* Hl = (layer == 0) ? pBl : pAl;
        int WC = (layer == 0) ? WC1 : WC2;
        const float* bc = (layer == 0) ? conv1_b : conv2_b;

        // batched gather: 6 relations into per-type agg regions
        {
            GathBatch B; B.nseg = 6;
            int bs = 0;
            auto add = [&](int i, size_t hoff, int rpo, int elo, int rs_s, int rs_d,
                           size_t aggrow, int colofs, int n_dst) {
                int blocks = (n_dst + 7) / 8;
                B.s[i] = {Hh + hoff, Hl + hoff, rp + rpo, el + elo,
                          deg + rs_s, deg + rs_d,
                          aggh + aggrow * 256, aggl + aggrow * 256,
                          colofs, n_dst, bs, blocks * 8};
                bs += blocks;
            };
            add(0, OFF_N, RP1, EL1, DS_POSTS_N, DS_POSTS_U, AGG_U, 0, N_USER);
            add(1, OFF_F, RP4, EL4, DS_FOL_F, DS_FOL_U, AGG_U, 128, N_USER);
            add(2, OFF_U, RP0, EL0, DS_POSTS_U, DS_POSTS_N, AGG_N, 0, N_NEWS);
            add(3, OFF_S, RP2, EL2, DS_PUB_S, DS_PUB_N, AGG_N, 128, N_NEWS);
            add(4, OFF_N, RP3, EL3, DS_PUB_N, DS_PUB_S, AGG_S, 0, N_SOURCE);
            add(5, OFF_U, RP5, EL5, DS_FOL_U, DS_FOL_F, AGG_F, 0, N_FOLLOWER);
            gather_batch_kernel<<<bs, 256>>>(B);
        }
        // batched GEMM: 4 dst types
        {
            GemmBatch B; B.nseg = 4;
            int bs = 0;
            B.s[0] = mkseg(nullptr, aggh + (size_t)AGG_U * 256, aggl + (size_t)AGG_U * 256,
                           256, WC + (0 * 6 + 1) * 16384, WC + (0 * 6 + 4) * 16384, 128, 256,
                           bc + (0 * 6 + 1) * HDIM, bc + (0 * 6 + 4) * HDIM,
                           (layer == 0) ? nullptr : h1_u,
                           (layer == 0) ? pAh + OFF_U : nullptr,
                           (layer == 0) ? pAl + OFF_U : nullptr,
                           N_USER, 0.5f, bs);
            bs += nb(N_USER);
            B.s[1] = mkseg(nullptr, aggh + (size_t)AGG_F * 256, aggl + (size_t)AGG_F * 256,
                           256, WC + (3 * 6 + 5) * 16384, -1, 128, 128,
                           bc + (3 * 6 + 5) * HDIM, nullptr,
                           (layer == 0) ? nullptr : h1_f,
                           (layer == 0) ? pAh + OFF_F : nullptr,
                           (layer == 0) ? pAl + OFF_F : nullptr,
                           N_FOLLOWER, 1.f, bs);
            bs += nb(N_FOLLOWER);
            B.s[2] = mkseg(nullptr, aggh + (size_t)AGG_N * 256, aggl + (size_t)AGG_N * 256,
                           256, WC + (1 * 6 + 0) * 16384, WC + (1 * 6 + 2) * 16384, 128, 256,
                           bc + (1 * 6 + 0) * HDIM, bc + (1 * 6 + 2) * HDIM,
                           (layer == 0) ? nullptr : h1_n,
                           (layer == 0) ? pAh + OFF_N : nullptr,
                           (layer == 0) ? pAl + OFF_N : nullptr,
                           N_NEWS, 0.5f, bs);
            bs += nb(N_NEWS);
            B.s[3] = mkseg(nullptr, aggh + (size_t)AGG_S * 256, aggl + (size_t)AGG_S * 256,
                           256, WC + (2 * 6 + 3) * 16384, -1, 128, 128,
                           bc + (2 * 6 + 3) * HDIM, nullptr,
                           (layer == 0) ? nullptr : h1_s,
                           (layer == 0) ? pAh + OFF_S : nullptr,
                           (layer == 0) ? pAl + OFF_S : nullptr,
                           N_SOURCE, 1.f, bs);
            bs += nb(N_SOURCE);
            tgemm_batch_kernel<<<bs, 256, SM_BYTES>>>(B);
        }
    }

    // ---- batched head ----
    {
        float* out_u = out + 0;
        float* out_n = out + (size_t)N_USER * 2;
        float* out_s = out + (size_t)(N_USER + N_NEWS) * 2;
        float* out_f = out + (size_t)(N_USER + N_NEWS + N_SOURCE) * 2;
        HeadBatch B; B.nseg = 4;
        int bs = 0;
        auto add = [&](int i, const float* h1, const float* Wl, const float* bl, float* o,
                       int N) {
            int blocks = (N * 32 + 255) / 256;
            B.s[i] = {h1, Wl, bl, o, N, bs, blocks * 8};
            bs += blocks;
        };
        add(0, h1_u, Wl_user, bl_user, out_u, N_USER);
        add(1, h1_n, Wl_news, bl_news, out_n, N_NEWS);
        add(2, h1_s, Wl_source, bl_source, out_s, N_SOURCE);
        add(3, h1_f, Wl_follower, bl_follower, out_f, N_FOLLOWER);
        head_batch_kernel<<<bs, 256>>>(B);
    }
}

// round 16
// speedup vs baseline: 1.7391x; 1.0684x over previous
#include <cuda_runtime.h>
#include <cuda_bf16.h>
#include <cstdint>
#include <cstddef>

#define N_USER 200000
#define N_NEWS 100000
#define N_SOURCE 5000
#define N_FOLLOWER 200000
#define HDIM 128
#define E_POSTS 500000
#define E_PUB 100000
#define E_FOL 1000000

#define TOT_NODES (N_USER + N_NEWS + N_SOURCE + N_FOLLOWER)

#define OFF_U ((size_t)0)
#define OFF_N ((size_t)N_USER * HDIM)
#define OFF_S ((size_t)(N_USER + N_NEWS) * HDIM)
#define OFF_F ((size_t)(N_USER + N_NEWS + N_SOURCE) * HDIM)

#define DS_POSTS_U 0
#define DS_POSTS_N 200000
#define DS_PUB_S   300000
#define DS_PUB_N   305000
#define DS_FOL_F   405000
#define DS_FOL_U   605000
#define DEG_TOTAL  805000

#define RP0 0
#define RP1 100001
#define RP2 300002
#define RP3 400003
#define RP4 405004
#define RP5 605005
#define RP_TOTAL 805006

#define EL0 0
#define EL1 500000
#define EL2 1000000
#define EL3 1100000
#define EL4 1200000
#define EL5 2200000
#define EL_TOTAL 3200000

// weight-plane segment offsets (elements)
#define WU1 0
#define WN1 16384
#define WS1 54784
#define WF1 71168
#define WI2 87552
#define WC1 153088
#define WC2 546304
#define WTOT 939520

// agg row offsets (row stride 256 for all types)
#define AGG_U 0
#define AGG_N 200000
#define AGG_S 300000
#define AGG_F 305000
#define AGG_ROWS 505000

__device__ __nv_bfloat16 g_pAh[(size_t)TOT_NODES * HDIM];
__device__ __nv_bfloat16 g_pAl[(size_t)TOT_NODES * HDIM];
__device__ __nv_bfloat16 g_pBh[(size_t)TOT_NODES * HDIM];
__device__ __nv_bfloat16 g_pBl[(size_t)TOT_NODES * HDIM];
__device__ __nv_bfloat16 g_aggh[(size_t)AGG_ROWS * 256];
__device__ __nv_bfloat16 g_aggl[(size_t)AGG_ROWS * 256];
__device__ __nv_bfloat16 g_wh[WTOT];
__device__ __nv_bfloat16 g_wl[WTOT];
__device__ float g_deg[DEG_TOTAL];
__device__ int   g_cnt[DEG_TOTAL];
__device__ int   g_cur[DEG_TOTAL];
__device__ int   g_rp[RP_TOTAL];
__device__ int   g_el[EL_TOTAL];

// ---------------------------------------------------------------------------
__device__ __forceinline__ uint32_t pack_hi2(float a, float b, uint32_t* lo) {
    __nv_bfloat16 h0 = __float2bfloat16_rn(a);
    __nv_bfloat16 h1 = __float2bfloat16_rn(b);
    __nv_bfloat16 l0 = __float2bfloat16_rn(a - __bfloat162float(h0));
    __nv_bfloat16 l1 = __float2bfloat16_rn(b - __bfloat162float(h1));
    *lo = (uint32_t)__bfloat16_as_ushort(l0) | ((uint32_t)__bfloat16_as_ushort(l1) << 16);
    return (uint32_t)__bfloat16_as_ushort(h0) | ((uint32_t)__bfloat16_as_ushort(h1) << 16);
}
__device__ __forceinline__ float bflo(uint32_t u) { return __uint_as_float(u << 16); }
__device__ __forceinline__ float bfhi(uint32_t u) { return __uint_as_float(u & 0xffff0000u); }

// ---------------------------------------------------------------------------
__global__ void zero4_kernel(float4* __restrict__ p, size_t n4) {
    size_t i = (size_t)blockIdx.x * blockDim.x + threadIdx.x;
    size_t stride = (size_t)gridDim.x * blockDim.x;
    float4 z = make_float4(0.f, 0.f, 0.f, 0.f);
    for (; i < n4; i += stride) p[i] = z;
}

__global__ void wsplit_kernel(const float* __restrict__ wu, const float* __restrict__ wn,
                              const float* __restrict__ ws, const float* __restrict__ wf,
                              const float* __restrict__ wi2, const float* __restrict__ c1,
                              const float* __restrict__ c2,
                              __nv_bfloat16* __restrict__ wh, __nv_bfloat16* __restrict__ wl) {
    const float* src; int n; int off;
    switch (blockIdx.y) {
        case 0: src = wu;  n = 16384;  off = WU1; break;
        case 1: src = wn;  n = 38400;  off = WN1; break;
        case 2: src = ws;  n = 16384;  off = WS1; break;
        case 3: src = wf;  n = 16384;  off = WF1; break;
        case 4: src = wi2; n = 65536;  off = WI2; break;
        case 5: src = c1;  n = 393216; off = WC1; break;
        default: src = c2; n = 393216; off = WC2; break;
    }
    int stride = gridDim.x * blockDim.x;
    for (int i = blockIdx.x * blockDim.x + threadIdx.x; i < n; i += stride) {
        float x = src[i];
        __nv_bfloat16 h = __float2bfloat16_rn(x);
        wh[off + i] = h;
        wl[off + i] = __float2bfloat16_rn(x - __bfloat162float(h));
    }
}

__global__ void rsqrt_cnt_kernel(const int* __restrict__ cnt, float* __restrict__ deg, int n) {
    int i = blockIdx.x * blockDim.x + threadIdx.x;
    int stride = gridDim.x * blockDim.x;
    for (; i < n; i += stride) {
        int c = cnt[i];
        deg[i] = rsqrtf((float)(c < 1 ? 1 : c));
    }
}

__global__ __launch_bounds__(1024) void scan6_kernel(const int* __restrict__ cnt,
                                                     int* __restrict__ rp) {
    const int segs[6] = {DS_POSTS_N, DS_POSTS_U, DS_PUB_N, DS_PUB_S, DS_FOL_U, DS_FOL_F};
    const int ns[6]   = {N_NEWS, N_USER, N_NEWS, N_SOURCE, N_USER, N_FOLLOWER};
    const int rpo[6]  = {RP0, RP1, RP2, RP3, RP4, RP5};
    int r = blockIdx.x;
    const int* c = cnt + segs[r];
    int* out = rp + rpo[r];
    int n = ns[r];
    int tid = threadIdx.x;
    int lane = tid & 31;
    int wid = tid >> 5;
    __shared__ int wsum[32];
    __shared__ int carry;
    if (tid == 0) { carry = 0; out[0] = 0; }
    __syncthreads();
    for (int base = 0; base < n; base += 1024) {
        int v = (base + tid < n) ? c[base + tid] : 0;
        int x = v;
#pragma unroll
        for (int o = 1; o < 32; o <<= 1) {
            int y = __shfl_up_sync(0xffffffffu, x, o);
            if (lane >= o) x += y;
        }
        if (lane == 31) wsum[wid] = x;
        __syncthreads();
        if (wid == 0) {
            int s = wsum[lane];
#pragma unroll
            for (int o = 1; o < 32; o <<= 1) {
                int y = __shfl_up_sync(0xffffffffu, s, o);
                if (lane >= o) s += y;
            }
            wsum[lane] = s;
        }
        __syncthreads();
        int pre = (wid > 0) ? wsum[wid - 1] : 0;
        int incl = carry + pre + x;
        if (base + tid < n) out[base + tid + 1] = incl;
        __syncthreads();
        if (tid == 1023) carry = incl;
        __syncthreads();
    }
}

// ---- batched count ----
struct CntSeg { const int* idx; int* cnt; int n; int bstart; int nthreads; };
struct CntBatch { int nseg; CntSeg s[6]; };
__global__ void count_batch_kernel(CntBatch B) {
    int bid = blockIdx.x;
    int si = 0;
#pragma unroll
    for (int i = 1; i < 6; i++)
        if (i < B.nseg && bid >= B.s[i].bstart) si = i;
    const CntSeg& g = B.s[si];
    int t = (bid - g.bstart) * 256 + threadIdx.x;
    for (; t < g.n; t += g.nthreads) atomicAdd(&g.cnt[g.idx[t]], 1);
}

// ---- batched fill ----
struct FillSeg { const int* src; const int* dst; const int* rp; int* cur; int* el;
                 int E; int bstart; int nthreads; };
struct FillBatch { int nseg; FillSeg s[6]; };
__global__ void fill_batch_kernel(FillBatch B) {
    int bid = blockIdx.x;
    int si = 0;
#pragma unroll
    for (int i = 1; i < 6; i++)
        if (i < B.nseg && bid >= B.s[i].bstart) si = i;
    const FillSeg& g = B.s[si];
    int t = (bid - g.bstart) * 256 + threadIdx.x;
    for (; t < g.E; t += g.nthreads) {
        int d = g.dst[t];
        int p = atomicAdd(&g.cur[d], 1);
        g.el[g.rp[d] + p] = g.src[t];
    }
}

// ---- batched gather (edge loop unrolled x2 for MLP) ----
struct GathSeg { const __nv_bfloat16* Hh; const __nv_bfloat16* Hl;
                 const int* rp; const int* el;
                 const float* rs_src; const float* rs_dst;
                 __nv_bfloat16* Ah; __nv_bfloat16* Al;
                 int colofs; int n_dst; int bstart; int nwarps; };
struct GathBatch { int nseg; GathSeg s[6]; };
__global__ void gather_batch_kernel(GathBatch B) {
    int bid = blockIdx.x;
    int si = 0;
#pragma unroll
    for (int i = 1; i < 6; i++)
        if (i < B.nseg && bid >= B.s[i].bstart) si = i;
    const GathSeg& g = B.s[si];
    int lane = threadIdx.x & 31;
    int lwarp = (bid - g.bstart) * 8 + (threadIdx.x >> 5);
    for (int row = lwarp; row < g.n_dst; row += g.nwarps) {
        int beg = g.rp[row], end = g.rp[row + 1];
        float a0 = 0.f, a1 = 0.f, a2 = 0.f, a3 = 0.f;
        int e = beg;
        for (; e + 1 < end; e += 2) {
            int s0 = g.el[e];
            int s1 = g.el[e + 1];
            float sc0 = g.rs_src[s0];
            float sc1 = g.rs_src[s1];
            const size_t b0 = (size_t)s0 * HDIM + lane * 4;
            const size_t b1 = (size_t)s1 * HDIM + lane * 4;
            uint2 vh0 = *reinterpret_cast<const uint2*>(g.Hh + b0);
            uint2 vl0 = *reinterpret_cast<const uint2*>(g.Hl + b0);
            uint2 vh1 = *reinterpret_cast<const uint2*>(g.Hh + b1);
            uint2 vl1 = *reinterpret_cast<const uint2*>(g.Hl + b1);
            a0 += sc0 * (bflo(vh0.x) + bflo(vl0.x)) + sc1 * (bflo(vh1.x) + bflo(vl1.x));
            a1 += sc0 * (bfhi(vh0.x) + bfhi(vl0.x)) + sc1 * (bfhi(vh1.x) + bfhi(vl1.x));
            a2 += sc0 * (bflo(vh0.y) + bflo(vl0.y)) + sc1 * (bflo(vh1.y) + bflo(vl1.y));
            a3 += sc0 * (bfhi(vh0.y) + bfhi(vl0.y)) + sc1 * (bfhi(vh1.y) + bfhi(vl1.y));
        }
        if (e < end) {
            int s = g.el[e];
            float sc = g.rs_src[s];
            const size_t base = (size_t)s * HDIM + lane * 4;
            uint2 vh = *reinterpret_cast<const uint2*>(g.Hh + base);
            uint2 vl = *reinterpret_cast<const uint2*>(g.Hl + base);
            a0 += sc * (bflo(vh.x) + bflo(vl.x));
            a1 += sc * (bfhi(vh.x) + bfhi(vl.x));
            a2 += sc * (bflo(vh.y) + bflo(vl.y));
            a3 += sc * (bfhi(vh.y) + bfhi(vl.y));
        }
        float ri = g.rs_dst[row];
        a0 *= ri; a1 *= ri; a2 *= ri; a3 *= ri;
        uint32_t lp0, lp1;
        uint32_t hp0 = pack_hi2(a0, a1, &lp0);
        uint32_t hp1 = pack_hi2(a2, a3, &lp1);
        size_t o = (size_t)row * 256 + g.colofs + lane * 4;
        *reinterpret_cast<uint2*>(g.Ah + o) = make_uint2(hp0, hp1);
        *reinterpret_cast<uint2*>(g.Al + o) = make_uint2(lp0, lp1);
    }
}

// ---------------------------------------------------------------------------
// bf16x3 HMMA GEMM, batched segments. CTA tile 64x128, K-chunk 64, 4 CTAs/SM.
// ---------------------------------------------------------------------------
#define ASTR 72
#define BSTR 136
#define SM_BYTES (2 * 64 * ASTR * 2 + 2 * 64 * BSTR * 2)  // 53248 B

#define CP_ASYNC16(smem, gptr) \
    asm volatile("cp.async.cg.shared.global [%0], [%1], 16;" :: "r"(smem), "l"(gptr))
#define CP_COMMIT() asm volatile("cp.async.commit_group;")
#define CP_WAIT0()  asm volatile("cp.async.wait_group 0;" ::: "memory")

__device__ __forceinline__ void mma16816(float* c, const uint32_t* a, const uint32_t* b) {
    asm volatile(
        "mma.sync.aligned.m16n8k16.row.col.f32.bf16.bf16.f32 "
        "{%0,%1,%2,%3}, {%4,%5,%6,%7}, {%8,%9}, {%0,%1,%2,%3};\n"
        : "+f"(c[0]), "+f"(c[1]), "+f"(c[2]), "+f"(c[3])
        : "r"(a[0]), "r"(a[1]), "r"(a[2]), "r"(a[3]), "r"(b[0]), "r"(b[1]));
}
__device__ __forceinline__ void ldsm_x4(uint32_t* r, uint32_t addr) {
    asm volatile("ldmatrix.sync.aligned.m8n8.x4.shared.b16 {%0,%1,%2,%3}, [%4];"
                 : "=r"(r[0]), "=r"(r[1]), "=r"(r[2]), "=r"(r[3]) : "r"(addr));
}
__device__ __forceinline__ void ldsm_x4_t(uint32_t* r, uint32_t addr) {
    asm volatile("ldmatrix.sync.aligned.m8n8.x4.trans.shared.b16 {%0,%1,%2,%3}, [%4];"
                 : "=r"(r[0]), "=r"(r[1]), "=r"(r[2]), "=r"(r[3]) : "r"(addr));
}

struct GemmSeg {
    const float* Afp;
    const __nv_bfloat16* Ah; const __nv_bfloat16* Al; int lda;
    const __nv_bfloat16* Wh0; const __nv_bfloat16* Wl0;
    const __nv_bfloat16* Wh1; const __nv_bfloat16* Wl1;
    int K0; int K;
    const float* b0; const float* b1;
    float* Cf; __nv_bfloat16* Ch; __nv_bfloat16* Cl;
    int M; float scale; int bstart;
};
struct GemmBatch { int nseg; GemmSeg s[4]; };

__global__ __launch_bounds__(256, 4) void tgemm_batch_kernel(GemmBatch B) {
    int bid = blockIdx.x;
    int si = 0;
#pragma unroll
    for (int i = 1; i < 4; i++)
        if (i < B.nseg && bid >= B.s[i].bstart) si = i;
    const GemmSeg& g = B.s[si];

    extern __shared__ __align__(16) char smraw[];
    __nv_bfloat16* AH = reinterpret_cast<__nv_bfloat16*>(smraw);
    __nv_bfloat16* AL = AH + 64 * ASTR;
    __nv_bfloat16* BH = AL + 64 * ASTR;
    __nv_bfloat16* BL = BH + 64 * BSTR;

    int tid = threadIdx.x;
    int lane = tid & 31;
    int warp = tid >> 5;
    int wm = warp & 1;
    int wn = warp >> 1;
    int block_row = (bid - g.bstart) * 64;
    const int lda = g.lda;
    const int K = g.K;
    const int K0 = g.K0;
    const int M = g.M;
    const uint4 z4 = make_uint4(0, 0, 0, 0);

    uint32_t aBaseH = (uint32_t)__cvta_generic_to_shared(
        &AH[(wm * 32 + (lane & 15)) * ASTR + (lane >> 4) * 8]);
    uint32_t aBaseL = aBaseH + 64 * ASTR * 2;
    uint32_t bBaseH = (uint32_t)__cvta_generic_to_shared(
        &BH[(lane & 15) * BSTR + wn * 32 + (lane >> 4) * 8]);
    uint32_t bBaseL = bBaseH + 64 * BSTR * 2;

    float c[2][4][4];
#pragma unroll
    for (int mt = 0; mt < 2; mt++)
#pragma unroll
        for (int nt = 0; nt < 4; nt++)
#pragma unroll
            for (int j = 0; j < 4; j++) c[mt][nt][j] = 0.f;

    for (int kbase = 0; kbase < K; kbase += 64) {
        int kcount = K - kbase; if (kcount > 64) kcount = 64;
        // ---- stage A chunk: 64 rows x 64 k ----
        if (g.Afp == nullptr) {
#pragma unroll
            for (int it = 0; it < 2; it++) {
                int idx = tid + it * 256;
                int row = idx >> 3;
                int kl = (idx & 7) * 8;
                int grow = block_row + row;
                int gk = kbase + kl;
                if (grow < M && gk < K) {
                    size_t go = (size_t)grow * lda + gk;
                    CP_ASYNC16((uint32_t)__cvta_generic_to_shared(&AH[row * ASTR + kl]), g.Ah + go);
                    CP_ASYNC16((uint32_t)__cvta_generic_to_shared(&AL[row * ASTR + kl]), g.Al + go);
                } else {
                    *reinterpret_cast<uint4*>(&AH[row * ASTR + kl]) = z4;
                    *reinterpret_cast<uint4*>(&AL[row * ASTR + kl]) = z4;
                }
            }
        } else {
#pragma unroll
            for (int it = 0; it < 2; it++) {
                int idx = tid + it * 256;
                int row = idx >> 3;
                int kl = (idx & 7) * 8;
                float v[8];
#pragma unroll
                for (int j = 0; j < 8; j++) v[j] = 0.f;
                int grow = block_row + row;
                int gk = kbase + kl;
                if (grow < M && gk < K) {
                    const float* ap = g.Afp + (size_t)grow * lda + gk;
                    if (gk + 7 < K) {
                        float4 v0 = *reinterpret_cast<const float4*>(ap);
                        float4 v1 = *reinterpret_cast<const float4*>(ap + 4);
                        v[0] = v0.x; v[1] = v0.y; v[2] = v0.z; v[3] = v0.w;
                        v[4] = v1.x; v[5] = v1.y; v[6] = v1.z; v[7] = v1.w;
                    } else {
#pragma unroll
                        for (int j = 0; j < 8; j++)
                            if (gk + j < K) v[j] = ap[j];
                    }
                }
                uint32_t hp[4], lp[4];
#pragma unroll
                for (int j = 0; j < 4; j++) hp[j] = pack_hi2(v[2 * j], v[2 * j + 1], &lp[j]);
                uint32_t off = (uint32_t)(row * ASTR + kl);
                *reinterpret_cast<uint4*>(&AH[off]) = make_uint4(hp[0], hp[1], hp[2], hp[3]);
                *reinterpret_cast<uint4*>(&AL[off]) = make_uint4(lp[0], lp[1], lp[2], lp[3]);
            }
        }
        // ---- stage W chunk: 64 k-rows x 128 n ----
#pragma unroll
        for (int it = 0; it < 4; it++) {
            int idx = tid + it * 256;
            int kr = idx >> 4;
            int nl = (idx & 15) * 8;
            int gk = kbase + kr;
            uint32_t off = (uint32_t)(kr * BSTR + nl);
            if (gk < K) {
                size_t go = (gk < K0) ? ((size_t)gk * HDIM + nl)
                                      : ((size_t)(gk - K0) * HDIM + nl);
                const __nv_bfloat16* sh = (gk < K0) ? g.Wh0 : g.Wh1;
                const __nv_bfloat16* sl = (gk < K0) ? g.Wl0 : g.Wl1;
                CP_ASYNC16((uint32_t)__cvta_generic_to_shared(&BH[off]), sh + go);
                CP_ASYNC16((uint32_t)__cvta_generic_to_shared(&BL[off]), sl + go);
            } else {
                *reinterpret_cast<uint4*>(&BH[off]) = z4;
                *reinterpret_cast<uint4*>(&BL[off]) = z4;
            }
        }
        CP_COMMIT();
        CP_WAIT0();
        __syncthreads();

        int nsteps = (kcount + 15) / 16;
#pragma unroll 4
        for (int s = 0; s < nsteps; s++) {
            uint32_t bh[4][2], bl[4][2];
#pragma unroll
            for (int half = 0; half < 2; half++) {
                uint32_t off = (uint32_t)(s * 16 * BSTR + half * 16) * 2;
                uint32_t r[4];
                ldsm_x4_t(r, bBaseH + off);
                bh[half * 2][0] = r[0]; bh[half * 2][1] = r[1];
                bh[half * 2 + 1][0] = r[2]; bh[half * 2 + 1][1] = r[3];
                ldsm_x4_t(r, bBaseL + off);
                bl[half * 2][0] = r[0]; bl[half * 2][1] = r[1];
                bl[half * 2 + 1][0] = r[2]; bl[half * 2 + 1][1] = r[3];
            }
#pragma unroll
            for (int mt = 0; mt < 2; mt++) {
                uint32_t off = (uint32_t)(mt * 16 * ASTR + s * 16) * 2;
                uint32_t ah[4], al[4];
                ldsm_x4(ah, aBaseH + off);
                ldsm_x4(al, aBaseL + off);
#pragma unroll
                for (int nt = 0; nt < 4; nt++) {
                    mma16816(c[mt][nt], ah, bh[nt]);
                    mma16816(c[mt][nt], ah, bl[nt]);
                    mma16816(c[mt][nt], al, bh[nt]);
                }
            }
        }
        __syncthreads();
    }

    // ---- epilogue ----
    float scale = g.scale;
#pragma unroll
    for (int mt = 0; mt < 2; mt++) {
#pragma unroll
        for (int nt = 0; nt < 4; nt++) {
            int col = wn * 32 + nt * 8 + (lane & 3) * 2;
            float bb0 = (g.b0 ? g.b0[col] : 0.f) + (g.b1 ? g.b1[col] : 0.f);
            float bb1 = (g.b0 ? g.b0[col + 1] : 0.f) + (g.b1 ? g.b1[col + 1] : 0.f);
#pragma unroll
            for (int h = 0; h < 2; h++) {
                int row = block_row + wm * 32 + mt * 16 + (lane >> 2) + h * 8;
                if (row >= M) continue;
                float r0 = (c[mt][nt][2 * h] + bb0) * scale;
                float r1 = (c[mt][nt][2 * h + 1] + bb1) * scale;
                r0 = r0 > 0.f ? r0 : 0.01f * r0;
                r1 = r1 > 0.f ? r1 : 0.01f * r1;
                if (g.Cf) {
                    *reinterpret_cast<float2*>(g.Cf + (size_t)row * HDIM + col) =
                        make_float2(r0, r1);
                } else {
                    uint32_t lp;
                    uint32_t hp = pack_hi2(r0, r1, &lp);
                    *reinterpret_cast<uint32_t*>(g.Ch + (size_t)row * HDIM + col) = hp;
                    *reinterpret_cast<uint32_t*>(g.Cl + (size_t)row * HDIM + col) = lp;
                }
            }
        }
    }
}

// ---- batched head ----
struct HeadSeg { const float* h1; const float* Wl; const float* bl; float* out;
                 int N; int bstart; int nwarps; };
struct HeadBatch { int nseg; HeadSeg s[4]; };
__global__ void head_batch_kernel(HeadBatch B) {
    int bid = blockIdx.x;
    int si = 0;
#pragma unroll
    for (int i = 1; i < 4; i++)
        if (i < B.nseg && bid >= B.s[i].bstart) si = i;
    const HeadSeg& g = B.s[si];
    int lane = threadIdx.x & 31;
    int lwarp = (bid - g.bstart) * 8 + (threadIdx.x >> 5);
    int k = lane * 4;
    float w00 = g.Wl[(k + 0) * 2], w01 = g.Wl[(k + 0) * 2 + 1];
    float w10 = g.Wl[(k + 1) * 2], w11 = g.Wl[(k + 1) * 2 + 1];
    float w20 = g.Wl[(k + 2) * 2], w21 = g.Wl[(k + 2) * 2 + 1];
    float w30 = g.Wl[(k + 3) * 2], w31 = g.Wl[(k + 3) * 2 + 1];
    for (int r = lwarp; r < g.N; r += g.nwarps) {
        float4 v = *reinterpret_cast<const float4*>(g.h1 + (size_t)r * HDIM + k);
        float p0 = v.x * w00 + v.y * w10 + v.z * w20 + v.w * w30;
        float p1 = v.x * w01 + v.y * w11 + v.z * w21 + v.w * w31;
#pragma unroll
        for (int off = 16; off; off >>= 1) {
            p0 += __shfl_xor_sync(0xffffffffu, p0, off);
            p1 += __shfl_xor_sync(0xffffffffu, p1, off);
        }
        if (lane == 0) {
            g.out[(size_t)r * 2 + 0] = p0 + g.bl[0];
            g.out[(size_t)r * 2 + 1] = p1 + g.bl[1];
        }
    }
}

// ---------------------------------------------------------------------------
extern "C" void kernel_launch(void* const* d_in, const int* in_sizes, int n_in,
                              void* d_out, int out_size) {
    const float* x_user = (const float*)d_in[0];
    const float* x_news = (const float*)d_in[1];
    const float* x_source = (const float*)d_in[2];
    const float* x_follower = (const float*)d_in[3];
    const float* Wi1_user = (const float*)d_in[4];
    const float* bi1_user = (const float*)d_in[5];
    const float* Wi1_news = (const float*)d_in[6];
    const float* bi1_news = (const float*)d_in[7];
    const float* Wi1_source = (const float*)d_in[8];
    const float* bi1_source = (const float*)d_in[9];
    const float* Wi1_follower = (const float*)d_in[10];
    const float* bi1_follower = (const float*)d_in[11];
    const float* Wi2 = (const float*)d_in[12];
    const float* bi2 = (const float*)d_in[13];
    const float* conv1_W = (const float*)d_in[14];
    const float* conv1_b = (const float*)d_in[15];
    const float* conv2_W = (const float*)d_in[16];
    const float* conv2_b = (const float*)d_in[17];
    const float* Wl_user = (const float*)d_in[18];
    const float* bl_user = (const float*)d_in[19];
    const float* Wl_news = (const float*)d_in[20];
    const float* bl_news = (const float*)d_in[21];
    const float* Wl_source = (const float*)d_in[22];
    const float* bl_source = (const float*)d_in[23];
    const float* Wl_follower = (const float*)d_in[24];
    const float* bl_follower = (const float*)d_in[25];
    const int* posts_u = (const int*)d_in[26];
    const int* posts_n = (const int*)d_in[27];
    const int* pub_s = (const int*)d_in[28];
    const int* pub_n = (const int*)d_in[29];
    const int* fol_f = (const int*)d_in[30];
    const int* fol_u = (const int*)d_in[31];
    float* out = (float*)d_out;

    __nv_bfloat16 *pAh, *pAl, *pBh, *pBl, *aggh, *aggl, *wh, *wl;
    float* deg;
    int *cnt, *cur, *rp, *el;
    cudaGetSymbolAddress((void**)&pAh, g_pAh);
    cudaGetSymbolAddress((void**)&pAl, g_pAl);
    cudaGetSymbolAddress((void**)&pBh, g_pBh);
    cudaGetSymbolAddress((void**)&pBl, g_pBl);
    cudaGetSymbolAddress((void**)&aggh, g_aggh);
    cudaGetSymbolAddress((void**)&aggl, g_aggl);
    cudaGetSymbolAddress((void**)&wh, g_wh);
    cudaGetSymbolAddress((void**)&wl, g_wl);
    cudaGetSymbolAddress((void**)&deg, g_deg);
    cudaGetSymbolAddress((void**)&cnt, g_cnt);
    cudaGetSymbolAddress((void**)&cur, g_cur);
    cudaGetSymbolAddress((void**)&rp, g_rp);
    cudaGetSymbolAddress((void**)&el, g_el);

    cudaFuncSetAttribute(tgemm_batch_kernel, cudaFuncAttributeMaxDynamicSharedMemorySize,
                         SM_BYTES);

    // persistent side stream + fork/join events (created once; reused across calls)
    static cudaStream_t s1 = nullptr;
    static cudaEvent_t evFork = nullptr, evJoin = nullptr;
    if (s1 == nullptr) {
        cudaStreamCreateWithFlags(&s1, cudaStreamNonBlocking);
        cudaEventCreateWithFlags(&evFork, cudaEventDisableTiming);
        cudaEventCreateWithFlags(&evJoin, cudaEventDisableTiming);
    }

    auto mkseg = [&](const float* Afp, const __nv_bfloat16* Ahp, const __nv_bfloat16* Alp,
                     int lda, int woff0, int woff1, int K0, int K,
                     const float* b0, const float* b1,
                     float* Cf, __nv_bfloat16* Ch, __nv_bfloat16* Cl,
                     int M, float scale, int bstart) {
        GemmSeg s;
        s.Afp = Afp; s.Ah = Ahp; s.Al = Alp; s.lda = lda;
        s.Wh0 = wh + woff0; s.Wl0 = wl + woff0;
        s.Wh1 = (woff1 >= 0) ? wh + woff1 : nullptr;
        s.Wl1 = (woff1 >= 0) ? wl + woff1 : nullptr;
        s.K0 = K0; s.K = K; s.b0 = b0; s.b1 = b1;
        s.Cf = Cf; s.Ch = Ch; s.Cl = Cl; s.M = M; s.scale = scale; s.bstart = bstart;
        return s;
    };
    auto nb = [](int M) { return (M + 63) / 64; };

    // ==== fork: CSR build on side stream s1 ====
    cudaEventRecord(evFork, 0);
    cudaStreamWaitEvent(s1, evFork, 0);

    zero4_kernel<<<2048, 256, 0, s1>>>((float4*)cnt, DEG_TOTAL / 4);
    zero4_kernel<<<2048, 256, 0, s1>>>((float4*)cur, DEG_TOTAL / 4);
    {
        CntBatch B; B.nseg = 6;
        int bs = 0;
        auto add = [&](int i, const int* idx, int n, int coff, int blocks) {
            B.s[i] = {idx, cnt + coff, n, bs, blocks * 256};
            bs += blocks;
        };
        add(0, posts_u, E_POSTS, DS_POSTS_U, 2048);
        add(1, posts_n, E_POSTS, DS_POSTS_N, 2048);
        add(2, pub_s, E_PUB, DS_PUB_S, 512);
        add(3, pub_n, E_PUB, DS_PUB_N, 512);
        add(4, fol_f, E_FOL, DS_FOL_F, 4096);
        add(5, fol_u, E_FOL, DS_FOL_U, 4096);
        count_batch_kernel<<<bs, 256, 0, s1>>>(B);
    }
    rsqrt_cnt_kernel<<<2048, 256, 0, s1>>>(cnt, deg, DEG_TOTAL);
    scan6_kernel<<<6, 1024, 0, s1>>>(cnt, rp);
    {
        FillBatch B; B.nseg = 6;
        int bs = 0;
        auto add = [&](int i, const int* s, const int* d, int E, int rpo, int coff, int elo,
                       int blocks) {
            B.s[i] = {s, d, rp + rpo, cur + coff, el + elo, E, bs, blocks * 256};
            bs += blocks;
        };
        add(0, posts_u, posts_n, E_POSTS, RP0, DS_POSTS_N, EL0, 2048);
        add(1, posts_n, posts_u, E_POSTS, RP1, DS_POSTS_U, EL1, 2048);
        add(2, pub_s, pub_n, E_PUB, RP2, DS_PUB_N, EL2, 512);
        add(3, pub_n, pub_s, E_PUB, RP3, DS_PUB_S, EL3, 512);
        add(4, fol_f, fol_u, E_FOL, RP4, DS_FOL_U, EL4, 4096);
        add(5, fol_u, fol_f, E_FOL, RP5, DS_FOL_F, EL5, 4096);
        fill_batch_kernel<<<bs, 256, 0, s1>>>(B);
    }
    cudaEventRecord(evJoin, s1);

    // ==== main stream: wsplit -> dense1 -> dense2 ====
    wsplit_kernel<<<dim3(256, 7), 256>>>(Wi1_user, Wi1_news, Wi1_source, Wi1_follower,
                                         Wi2, conv1_W, conv2_W, wh, wl);
    {
        GemmBatch B; B.nseg = 4;
        int bs = 0;
        B.s[0] = mkseg(x_user, nullptr, nullptr, 128, WU1, -1, 128, 128, bi1_user, nullptr,
                       nullptr, pAh + OFF_U, pAl + OFF_U, N_USER, 1.f, bs);
        bs += nb(N_USER);
        B.s[1] = mkseg(x_follower, nullptr, nullptr, 128, WF1, -1, 128, 128, bi1_follower,
                       nullptr, nullptr, pAh + OFF_F, pAl + OFF_F, N_FOLLOWER, 1.f, bs);
        bs += nb(N_FOLLOWER);
        B.s[2] = mkseg(x_news, nullptr, nullptr, 300, WN1, -1, 300, 300, bi1_news, nullptr,
                       nullptr, pAh + OFF_N, pAl + OFF_N, N_NEWS, 1.f, bs);
        bs += nb(N_NEWS);
        B.s[3] = mkseg(x_source, nullptr, nullptr, 128, WS1, -1, 128, 128, bi1_source,
                       nullptr, nullptr, pAh + OFF_S, pAl + OFF_S, N_SOURCE, 1.f, bs);
        bs += nb(N_SOURCE);
        tgemm_batch_kernel<<<bs, 256, SM_BYTES>>>(B);
    }
    {
        GemmBatch B; B.nseg = 4;
        int bs = 0;
        B.s[0] = mkseg(nullptr, pAh + OFF_U, pAl + OFF_U, 128, WI2 + 0 * 16384, -1, 128, 128,
                       bi2 + 0 * HDIM, nullptr, nullptr, pBh + OFF_U, pBl + OFF_U,
                       N_USER, 1.f, bs);
        bs += nb(N_USER);
        B.s[1] = mkseg(nullptr, pAh + OFF_F, pAl + OFF_F, 128, WI2 + 3 * 16384, -1, 128, 128,
                       bi2 + 3 * HDIM, nullptr, nullptr, pBh + OFF_F, pBl + OFF_F,
                       N_FOLLOWER, 1.f, bs);
        bs += nb(N_FOLLOWER);
        B.s[2] = mkseg(nullptr, pAh + OFF_N, pAl + OFF_N, 128, WI2 + 1 * 16384, -1, 128, 128,
                       bi2 + 1 * HDIM, nullptr, nullptr, pBh + OFF_N, pBl + OFF_N,
                       N_NEWS, 1.f, bs);
        bs += nb(N_NEWS);
        B.s[3] = mkseg(nullptr, pAh + OFF_S, pAl + OFF_S, 128, WI2 + 2 * 16384, -1, 128, 128,
                       bi2 + 2 * HDIM, nullptr, nullptr, pBh + OFF_S, pBl + OFF_S,
                       N_SOURCE, 1.f, bs);
        bs += nb(N_SOURCE);
        tgemm_batch_kernel<<<bs, 256, SM_BYTES>>>(B);
    }

    // ==== join: conv layers need CSR + dense2 ====
    cudaStreamWaitEvent(0, evJoin, 0);

    const size_t H1_BASE = (size_t)TOT_NODES * 2;
    float* h1_u = out + H1_BASE + OFF_U;
    float* h1_n = out + H1_BASE + OFF_N;
    float* h1_s = out + H1_BASE + OFF_S;
    float* h1_f = out + H1_BASE + OFF_F;

    for (int layer = 0; layer < 2; layer++) {
        const __nv_bfloat16* Hh = (layer == 0) ? pBh : pAh;
        const __nv_bfloat16* Hl = (layer == 0) ? pBl : pAl;
        int WC = (layer == 0) ? WC1 : WC2;
        const float* bc = (layer == 0) ? conv1_b : conv2_b;

        {
            GathBatch B; B.nseg = 6;
            int bs = 0;
            auto add = [&](int i, size_t hoff, int rpo, int elo, int rs_s, int rs_d,
                           size_t aggrow, int colofs, int n_dst) {
                int blocks = (n_dst + 7) / 8;
                B.s[i] = {Hh + hoff, Hl + hoff, rp + rpo, el + elo,
                          deg + rs_s, deg + rs_d,
                          aggh + aggrow * 256, aggl + aggrow * 256,
                          colofs, n_dst, bs, blocks * 8};
                bs += blocks;
            };
            add(0, OFF_N, RP1, EL1, DS_POSTS_N, DS_POSTS_U, AGG_U, 0, N_USER);
            add(1, OFF_F, RP4, EL4, DS_FOL_F, DS_FOL_U, AGG_U, 128, N_USER);
            add(2, OFF_U, RP0, EL0, DS_POSTS_U, DS_POSTS_N, AGG_N, 0, N_NEWS);
            add(3, OFF_S, RP2, EL2, DS_PUB_S, DS_PUB_N, AGG_N, 128, N_NEWS);
            add(4, OFF_N, RP3, EL3, DS_PUB_N, DS_PUB_S, AGG_S, 0, N_SOURCE);
            add(5, OFF_U, RP5, EL5, DS_FOL_U, DS_FOL_F, AGG_F, 0, N_FOLLOWER);
            gather_batch_kernel<<<bs, 256>>>(B);
        }
        {
            GemmBatch B; B.nseg = 4;
            int bs = 0;
            B.s[0] = mkseg(nullptr, aggh + (size_t)AGG_U * 256, aggl + (size_t)AGG_U * 256,
                           256, WC + (0 * 6 + 1) * 16384, WC + (0 * 6 + 4) * 16384, 128, 256,
                           bc + (0 * 6 + 1) * HDIM, bc + (0 * 6 + 4) * HDIM,
                           (layer == 0) ? nullptr : h1_u,
                           (layer == 0) ? pAh + OFF_U : nullptr,
                           (layer == 0) ? pAl + OFF_U : nullptr,
                           N_USER, 0.5f, bs);
            bs += nb(N_USER);
            B.s[1] = mkseg(nullptr, aggh + (size_t)AGG_F * 256, aggl + (size_t)AGG_F * 256,
                           256, WC + (3 * 6 + 5) * 16384, -1, 128, 128,
                           bc + (3 * 6 + 5) * HDIM, nullptr,
                           (layer == 0) ? nullptr : h1_f,
                           (layer == 0) ? pAh + OFF_F : nullptr,
                           (layer == 0) ? pAl + OFF_F : nullptr,
                           N_FOLLOWER, 1.f, bs);
            bs += nb(N_FOLLOWER);
            B.s[2] = mkseg(nullptr, aggh + (size_t)AGG_N * 256, aggl + (size_t)AGG_N * 256,
                           256, WC + (1 * 6 + 0) * 16384, WC + (1 * 6 + 2) * 16384, 128, 256,
                           bc + (1 * 6 + 0) * HDIM, bc + (1 * 6 + 2) * HDIM,
                           (layer == 0) ? nullptr : h1_n,
                           (layer == 0) ? pAh + OFF_N : nullptr,
                           (layer == 0) ? pAl + OFF_N : nullptr,
                           N_NEWS, 0.5f, bs);
            bs += nb(N_NEWS);
            B.s[3] = mkseg(nullptr, aggh + (size_t)AGG_S * 256, aggl + (size_t)AGG_S * 256,
                           256, WC + (2 * 6 + 3) * 16384, -1, 128, 128,
                           bc + (2 * 6 + 3) * HDIM, nullptr,
                           (layer == 0) ? nullptr : h1_s,
                           (layer == 0) ? pAh + OFF_S : nullptr,
                           (layer == 0) ? pAl + OFF_S : nullptr,
                           N_SOURCE, 1.f, bs);
            bs += nb(N_SOURCE);
            tgemm_batch_kernel<<<bs, 256, SM_BYTES>>>(B);
        }
    }

    // ---- batched head ----
    {
        float* out_u = out + 0;
        float* out_n = out + (size_t)N_USER * 2;
        float* out_s = out + (size_t)(N_USER + N_NEWS) * 2;
        float* out_f = out + (size_t)(N_USER + N_NEWS + N_SOURCE) * 2;
        HeadBatch B; B.nseg = 4;
        int bs = 0;
        auto add = [&](int i, const float* h1, const float* Wl, const float* bl, float* o,
                       int N) {
            int blocks = (N * 32 + 255) / 256;
            B.s[i] = {h1, Wl, bl, o, N, bs, blocks * 8};
            bs += blocks;
        };
        add(0, h1_u, Wl_user, bl_user, out_u, N_USER);
        add(1, h1_n, Wl_news, bl_news, out_n, N_NEWS);
        add(2, h1_s, Wl_source, bl_source, out_s, N_SOURCE);
        add(3, h1_f, Wl_follower, bl_follower, out_f, N_FOLLOWER);
        head_batch_kernel<<<bs, 256>>>(B);
    }
}